// round 7
// baseline (speedup 1.0000x reference)
#include <cuda_runtime.h>
#include <math.h>

#define Nn    20000
#define HIDF  256
#define ZF    64
#define EP    120000
#define E2    240000
#define ENEG  600000
#define ETOT  720000

typedef unsigned long long ull;

// ---------------- scratch (static device globals; no allocation) ----------------
__device__ __align__(16) float g_m[Nn * HIDF];        // x@W1
__device__ __align__(16) float g_h1[Nn * HIDF];       // post LN+relu
__device__ __align__(16) float g_tmulv[Nn * 128];     // [h1@Wmu | h1@Wlv]
__device__ __align__(16) float g_z[Nn * ZF];
__device__ __align__(16) float g_md[Nn * ZF];         // decoder gemm out (scaled in place)
__device__ __align__(16) float g_hd[Nn * ZF];         // decoder layer1 out
__device__ __align__(16) float g_hd2[Nn * ZF];        // decoder layer2 out
__device__ __align__(16) float g_A12[Nn * 128];       // [h@Wa1 | h@Wa2]
__device__ __align__(16) float g_Wcat[256 * 128];     // packed weight concat
__device__ float g_dis[Nn];
__device__ __align__(16) int g_degE[Nn];              // encoder in-degree
__device__ __align__(16) int g_degD[Nn];              // decoder in-degree
__device__ int g_startE[Nn + 1];
__device__ int g_startD[Nn + 1];
__device__ int g_curE[Nn];
__device__ int g_curD[Nn];
__device__ int g_permE[E2];                           // src sorted by dst
__device__ int g_permD[EP];                           // ps sorted by pd
__device__ double g_acc[2];                           // [recon_sum, unused]
__device__ double g_accp[64];                         // kl partial slots

#define FMA2(c, a, b) asm("fma.rn.f32x2 %0, %1, %2, %0;" : "+l"(c) : "l"(a), "l"(b))

// ---------------- zero: degree counters + accumulators ----------------
__global__ __launch_bounds__(256) void zero_kernel(int* degE, int* degD,
                                                   double* acc, double* accp)
{
    int idx = blockIdx.x * blockDim.x + threadIdx.x;
    if (idx < Nn) { degE[idx] = 0; degD[idx] = 0; }
    if (idx < 64) accp[idx] = 0.0;
    if (idx < 2) acc[idx] = 0.0;
}

// ---------------- degree count (both graphs fused) ----------------
__global__ __launch_bounds__(256) void count_kernel(
    const int* __restrict__ dst, const int* __restrict__ pd,
    int* __restrict__ degE, int* __restrict__ degD)
{
    int idx = blockIdx.x * blockDim.x + threadIdx.x;
    if (idx < E2) atomicAdd(&degE[dst[idx]], 1);
    if (idx < EP) atomicAdd(&degD[pd[idx]], 1);
}

// ---------------- exclusive scan of degrees (block 0: enc, block 1: dec) --------
__global__ __launch_bounds__(1024) void scan_kernel(
    const int* __restrict__ degE, int* startE, int* curE,
    const int* __restrict__ degD, int* startD, int* curD, float* dis)
{
    const int* deg = (blockIdx.x == 0) ? degE : degD;
    int* start     = (blockIdx.x == 0) ? startE : startD;
    int* cur       = (blockIdx.x == 0) ? curE : curD;
    int t = threadIdx.x;
    int base = t * 20;
    int local[20];
    int sum = 0;
#pragma unroll
    for (int i = 0; i < 20; i++) {
        int idx = base + i;
        int v = (idx < Nn) ? deg[idx] : 0;
        local[i] = sum;
        sum += v;
    }
    __shared__ int ps[1024];
    ps[t] = sum;
    __syncthreads();
    for (int off = 1; off < 1024; off <<= 1) {
        int v = (t >= off) ? ps[t - off] : 0;
        __syncthreads();
        ps[t] += v;
        __syncthreads();
    }
    int offset = (t > 0) ? ps[t - 1] : 0;
#pragma unroll
    for (int i = 0; i < 20; i++) {
        int idx = base + i;
        if (idx < Nn) {
            int s = offset + local[i];
            start[idx] = s;
            cur[idx] = s;
            if (blockIdx.x == 1) dis[idx] = rsqrtf((float)deg[idx] + 1.0f);
        }
    }
    if (t == 1023) start[Nn] = ps[1023];
}

// ---------------- CSR fill (both graphs fused) ----------------
__global__ __launch_bounds__(256) void fill_kernel(
    const int* __restrict__ src, const int* __restrict__ dst,
    const int* __restrict__ ps, const int* __restrict__ pd,
    int* __restrict__ curE, int* __restrict__ curD,
    int* __restrict__ permE, int* __restrict__ permD)
{
    int idx = blockIdx.x * blockDim.x + threadIdx.x;
    if (idx < E2) {
        int slot = atomicAdd(&curE[dst[idx]], 1);
        permE[slot] = src[idx];
    }
    if (idx < EP) {
        int slot = atomicAdd(&curD[pd[idx]], 1);
        permD[slot] = ps[idx];
    }
}

// ---------------- SGEMM BM=64 ----------------
__global__ __launch_bounds__(256) void sgemm_kernel(
    const float* __restrict__ A, const float* __restrict__ B, float* __restrict__ C,
    int M, int Ncols, int K, int ldc, int coff)
{
    __shared__ float As2[16][128];
    __shared__ float Bs[16][64];
    int tid = threadIdx.x;
    int m0 = blockIdx.y * 64;
    int n0 = blockIdx.x * 64;
    int ty = tid >> 4, tx = tid & 15;
    int am = tid >> 2, ak = (tid & 3) * 4;
    int bk = tid >> 4, bn = (tid & 15) * 4;

    ull acc[4][2];
#pragma unroll
    for (int i = 0; i < 4; i++) { acc[i][0] = 0ull; acc[i][1] = 0ull; }

    for (int k0 = 0; k0 < K; k0 += 16) {
        float4 va = make_float4(0.f, 0.f, 0.f, 0.f);
        int gm = m0 + am;
        if (gm < M) va = *(const float4*)(A + (size_t)gm * K + k0 + ak);
        As2[ak + 0][2 * am] = va.x; As2[ak + 0][2 * am + 1] = va.x;
        As2[ak + 1][2 * am] = va.y; As2[ak + 1][2 * am + 1] = va.y;
        As2[ak + 2][2 * am] = va.z; As2[ak + 2][2 * am + 1] = va.z;
        As2[ak + 3][2 * am] = va.w; As2[ak + 3][2 * am + 1] = va.w;
        *(float4*)&Bs[bk][bn] = *(const float4*)(B + (size_t)(k0 + bk) * Ncols + n0 + bn);
        __syncthreads();
#pragma unroll
        for (int kk = 0; kk < 16; kk++) {
            ull a0 = *(const ull*)&As2[kk][(ty * 4 + 0) * 2];
            ull a1 = *(const ull*)&As2[kk][(ty * 4 + 1) * 2];
            ull a2 = *(const ull*)&As2[kk][(ty * 4 + 2) * 2];
            ull a3 = *(const ull*)&As2[kk][(ty * 4 + 3) * 2];
            union { float4 f4; ull u[2]; } bu;
            bu.f4 = *(const float4*)&Bs[kk][tx * 4];
            FMA2(acc[0][0], a0, bu.u[0]); FMA2(acc[0][1], a0, bu.u[1]);
            FMA2(acc[1][0], a1, bu.u[0]); FMA2(acc[1][1], a1, bu.u[1]);
            FMA2(acc[2][0], a2, bu.u[0]); FMA2(acc[2][1], a2, bu.u[1]);
            FMA2(acc[3][0], a3, bu.u[0]); FMA2(acc[3][1], a3, bu.u[1]);
        }
        __syncthreads();
    }
#pragma unroll
    for (int i = 0; i < 4; i++) {
        int gm = m0 + ty * 4 + i;
        if (gm < M) {
            union { ull u[2]; float f[4]; } r;
            r.u[0] = acc[i][0]; r.u[1] = acc[i][1];
            *(float4*)(C + (size_t)gm * ldc + coff + n0 + tx * 4) =
                make_float4(r.f[0], r.f[1], r.f[2], r.f[3]);
        }
    }
}

// ---------------- SGEMM BM=32 (128 threads) ----------------
__global__ __launch_bounds__(128) void sgemm32_kernel(
    const float* __restrict__ A, const float* __restrict__ B, float* __restrict__ C,
    int M, int Ncols, int K, int ldc, int coff)
{
    __shared__ float As2[16][64];
    __shared__ float Bs[16][64];
    int tid = threadIdx.x;
    int m0 = blockIdx.y * 32;
    int n0 = blockIdx.x * 64;
    int ty = tid >> 4, tx = tid & 15;
    int am = tid >> 2, ak = (tid & 3) * 4;
    int bk = tid >> 4, bn = (tid & 15) * 4;

    ull acc[4][2];
#pragma unroll
    for (int i = 0; i < 4; i++) { acc[i][0] = 0ull; acc[i][1] = 0ull; }

    for (int k0 = 0; k0 < K; k0 += 16) {
        float4 va = make_float4(0.f, 0.f, 0.f, 0.f);
        int gm = m0 + am;
        if (gm < M) va = *(const float4*)(A + (size_t)gm * K + k0 + ak);
        As2[ak + 0][2 * am] = va.x; As2[ak + 0][2 * am + 1] = va.x;
        As2[ak + 1][2 * am] = va.y; As2[ak + 1][2 * am + 1] = va.y;
        As2[ak + 2][2 * am] = va.z; As2[ak + 2][2 * am + 1] = va.z;
        As2[ak + 3][2 * am] = va.w; As2[ak + 3][2 * am + 1] = va.w;
        *(float4*)&Bs[bk][bn]     = *(const float4*)(B + (size_t)(k0 + bk) * Ncols + n0 + bn);
        *(float4*)&Bs[bk + 8][bn] = *(const float4*)(B + (size_t)(k0 + bk + 8) * Ncols + n0 + bn);
        __syncthreads();
#pragma unroll
        for (int kk = 0; kk < 16; kk++) {
            ull a0 = *(const ull*)&As2[kk][(ty * 4 + 0) * 2];
            ull a1 = *(const ull*)&As2[kk][(ty * 4 + 1) * 2];
            ull a2 = *(const ull*)&As2[kk][(ty * 4 + 2) * 2];
            ull a3 = *(const ull*)&As2[kk][(ty * 4 + 3) * 2];
            union { float4 f4; ull u[2]; } bu;
            bu.f4 = *(const float4*)&Bs[kk][tx * 4];
            FMA2(acc[0][0], a0, bu.u[0]); FMA2(acc[0][1], a0, bu.u[1]);
            FMA2(acc[1][0], a1, bu.u[0]); FMA2(acc[1][1], a1, bu.u[1]);
            FMA2(acc[2][0], a2, bu.u[0]); FMA2(acc[2][1], a2, bu.u[1]);
            FMA2(acc[3][0], a3, bu.u[0]); FMA2(acc[3][1], a3, bu.u[1]);
        }
        __syncthreads();
    }
#pragma unroll
    for (int i = 0; i < 4; i++) {
        int gm = m0 + ty * 4 + i;
        if (gm < M) {
            union { ull u[2]; float f[4]; } r;
            r.u[0] = acc[i][0]; r.u[1] = acc[i][1];
            *(float4*)(C + (size_t)gm * ldc + coff + n0 + tx * 4) =
                make_float4(r.f[0], r.f[1], r.f[2], r.f[3]);
        }
    }
}

// ---------------- weight pack ----------------
__global__ __launch_bounds__(256) void pack2_kernel(
    const float* __restrict__ A, const float* __restrict__ B,
    float* __restrict__ out, int K)
{
    int idx = blockIdx.x * blockDim.x + threadIdx.x;
    if (idx >= K * 64) return;
    int k = idx >> 6, j = idx & 63;
    out[k * 128 + j]      = A[k * 64 + j];
    out[k * 128 + 64 + j] = B[k * 64 + j];
}

// ---------------- fused gather + bias + LayerNorm + relu (node-centric, W=256) ----
__global__ __launch_bounds__(256) void gather_ln_kernel(
    const float* __restrict__ m, const int* __restrict__ perm,
    const int* __restrict__ start, const float* __restrict__ b1,
    const float* __restrict__ g1, const float* __restrict__ bt1,
    float* __restrict__ h1)
{
    __shared__ int sidx[256];
    __shared__ float red[8];
    int n = blockIdx.x;
    int j = threadIdx.x;
    int lane = j & 31, w = j >> 5;
    int s0 = start[n], s1 = start[n + 1];
    int deg = s1 - s0;
    int cnt = deg < 256 ? deg : 256;
    if (j < cnt) sidx[j] = perm[s0 + j];
    __syncthreads();
    float a0 = 0.f, a1 = 0.f, a2 = 0.f, a3 = 0.f;
    int k = 0;
    for (; k + 4 <= cnt; k += 4) {
        a0 += m[(size_t)sidx[k + 0] * 256 + j];
        a1 += m[(size_t)sidx[k + 1] * 256 + j];
        a2 += m[(size_t)sidx[k + 2] * 256 + j];
        a3 += m[(size_t)sidx[k + 3] * 256 + j];
    }
    for (; k < cnt; k++) a0 += m[(size_t)sidx[k] * 256 + j];
    for (int k2 = 256; k2 < deg; k2++) a0 += m[(size_t)perm[s0 + k2] * 256 + j];
    float v = (a0 + a1) + (a2 + a3) + b1[j];
    // LayerNorm over 256
    float s = v;
#pragma unroll
    for (int o = 16; o; o >>= 1) s += __shfl_xor_sync(0xffffffffu, s, o);
    if (lane == 0) red[w] = s;
    __syncthreads();
    float tot = 0.f;
#pragma unroll
    for (int i = 0; i < 8; i++) tot += red[i];
    float mu = tot * (1.f / 256.f);
    __syncthreads();
    float d = v - mu;
    float q = d * d;
#pragma unroll
    for (int o = 16; o; o >>= 1) q += __shfl_xor_sync(0xffffffffu, q, o);
    if (lane == 0) red[w] = q;
    __syncthreads();
    float tq = 0.f;
#pragma unroll
    for (int i = 0; i < 8; i++) tq += red[i];
    float var = tq * (1.f / 256.f);
    float o = d * rsqrtf(var + 1e-5f) * g1[j] + bt1[j];
    h1[(size_t)n * 256 + j] = fmaxf(o, 0.f);
}

// ---------------- fused gather + z-reparam + KL (node-centric, W=128) -----------
__global__ __launch_bounds__(128) void gather_zkl_kernel(
    const float* __restrict__ t, const int* __restrict__ perm,
    const int* __restrict__ start, const float* __restrict__ bmu,
    const float* __restrict__ blv, const float* __restrict__ eps,
    float* __restrict__ z, double* __restrict__ accp)
{
    __shared__ int sidx[128];
    __shared__ float row[128];
    __shared__ double sred[4];
    int n = blockIdx.x;
    int j = threadIdx.x;
    int lane = j & 31, w = j >> 5;
    int s0 = start[n], s1 = start[n + 1];
    int deg = s1 - s0;
    int cnt = deg < 128 ? deg : 128;
    if (j < cnt) sidx[j] = perm[s0 + j];
    __syncthreads();
    float a0 = 0.f, a1 = 0.f, a2 = 0.f, a3 = 0.f;
    int k = 0;
    for (; k + 4 <= cnt; k += 4) {
        a0 += t[(size_t)sidx[k + 0] * 128 + j];
        a1 += t[(size_t)sidx[k + 1] * 128 + j];
        a2 += t[(size_t)sidx[k + 2] * 128 + j];
        a3 += t[(size_t)sidx[k + 3] * 128 + j];
    }
    for (; k < cnt; k++) a0 += t[(size_t)sidx[k] * 128 + j];
    for (int k2 = 128; k2 < deg; k2++) a0 += t[(size_t)perm[s0 + k2] * 128 + j];
    row[j] = (a0 + a1) + (a2 + a3);
    __syncthreads();
    double local = 0.0;
    if (j < 64) {
        float mu = row[j] + bmu[j];
        float lv = row[j + 64] + blv[j];
        z[(size_t)n * 64 + j] = mu + eps[(size_t)n * 64 + j] * expf(0.5f * lv);
        local = (double)(1.f + lv - mu * mu - expf(lv));
    }
#pragma unroll
    for (int o = 16; o; o >>= 1) local += __shfl_xor_sync(0xffffffffu, local, o);
    if (lane == 0) sred[w] = local;
    __syncthreads();
    if (j == 0) {
        double tt = sred[0] + sred[1] + sred[2] + sred[3];
        atomicAdd(&accp[n & 63], tt);
    }
}

// ---------------- row scale: md[n][:] *= dis[n] ----------------
__global__ __launch_bounds__(256) void scale_v4_kernel(
    float4* __restrict__ md, const float* __restrict__ dis)
{
    int idx = blockIdx.x * blockDim.x + threadIdx.x;
    if (idx >= Nn * 16) return;
    int n = idx >> 4;
    float d = dis[n];
    float4 v = md[idx];
    v.x *= d; v.y *= d; v.z *= d; v.w *= d;
    md[idx] = v;
}

// ---------------- fused decoder gather + selfloop + bias + relu (W=64, 4 nodes/blk)
__global__ __launch_bounds__(256) void gather_dec_kernel(
    const float* __restrict__ msc, const int* __restrict__ perm,
    const int* __restrict__ start, const float* __restrict__ dis,
    const float* __restrict__ bd, float* __restrict__ outp)
{
    __shared__ int sidx[4][64];
    int tid = threadIdx.x;
    int g = tid >> 6, j = tid & 63;
    int n = blockIdx.x * 4 + g;
    int s0 = start[n], s1 = start[n + 1];
    int deg = s1 - s0;
    int cnt = deg < 64 ? deg : 64;
    if (j < cnt) sidx[g][j] = perm[s0 + j];
    __syncthreads();
    float a0 = 0.f, a1 = 0.f, a2 = 0.f, a3 = 0.f;
    int k = 0;
    for (; k + 4 <= cnt; k += 4) {
        a0 += msc[(size_t)sidx[g][k + 0] * 64 + j];
        a1 += msc[(size_t)sidx[g][k + 1] * 64 + j];
        a2 += msc[(size_t)sidx[g][k + 2] * 64 + j];
        a3 += msc[(size_t)sidx[g][k + 3] * 64 + j];
    }
    for (; k < cnt; k++) a0 += msc[(size_t)sidx[g][k] * 64 + j];
    for (int k2 = 64; k2 < deg; k2++) a0 += msc[(size_t)perm[s0 + k2] * 64 + j];
    float v = (a0 + a1) + (a2 + a3) + msc[(size_t)n * 64 + j];   // selfloop (scaled)
    v = v * dis[n] + bd[j];
    outp[(size_t)n * 64 + j] = fmaxf(v, 0.f);
}

// ---------------- fused edge decoder + BCE loss (64-edge tiles) ----------------
__global__ __launch_bounds__(256) void edge_loss_kernel(
    const float* __restrict__ h, const float* __restrict__ A12,
    const float* __restrict__ Wa, const float* __restrict__ ba,
    const float* __restrict__ Wb, const float* __restrict__ bb,
    const float* __restrict__ tau,
    const int* __restrict__ pu, const int* __restrict__ pv,
    const int* __restrict__ nu, const int* __restrict__ nv,
    double* __restrict__ acc)
{
    extern __shared__ float sm[];
    float* sW = sm;                   // [128][64]  = 8192 floats
    float* sF = sW + 8192;            // [128][64]  = 8192 (k-major, edge-fast)
    float* sHU = sF + 8192;           // [64][65]   = 4160
    float* sHV = sHU + 4160;          // 4160
    int* sU = (int*)(sHV + 4160);     // 64
    int* sV = sU + 64;                // 64

    int tid = threadIdx.x;
    int lane = tid & 31, wid = tid >> 5;

    const float* W34 = Wa + 128 * 64;
    for (int i = tid; i < 8192; i += 256) sW[i] = W34[i];

    float tc = fmaxf(tau[0], 1e-4f);
    float invt = 1.0f / tc;
    float bbv = bb[0];
    float2 ba2 = ((const float2*)ba)[lane];
    float2 wb2 = ((const float2*)Wb)[lane];
    const float pw = (float)ENEG / (float)EP;
    double dsum = 0.0;

    int nTiles = ETOT / 64;  // 11250
    for (int tile = blockIdx.x; tile < nTiles; tile += gridDim.x) {
        __syncthreads();
        if (tid < 64) {
            int ge = tile * 64 + tid;
            int u, v;
            if (ge < EP) { u = pu[ge]; v = pv[ge]; }
            else         { u = nu[ge - EP]; v = nv[ge - EP]; }
            sU[tid] = u; sV[tid] = v;
        }
        __syncthreads();
#pragma unroll
        for (int ee = 0; ee < 8; ee++) {
            int e = wid * 8 + ee;
            int u = sU[e], v = sV[e];
            sHU[e * 65 + lane]      = h[(size_t)u * 64 + lane];
            sHU[e * 65 + 32 + lane] = h[(size_t)u * 64 + 32 + lane];
            sHV[e * 65 + lane]      = h[(size_t)v * 64 + lane];
            sHV[e * 65 + 32 + lane] = h[(size_t)v * 64 + 32 + lane];
        }
        __syncthreads();
#pragma unroll
        for (int p = 0; p < 16; p++) {
            int i = tid + p * 256;
            int e = i & 63, f = i >> 6;
            float hu = sHU[e * 65 + f], hv = sHV[e * 65 + f];
            sF[f * 64 + e]        = fabsf(hu - hv);
            sF[(64 + f) * 64 + e] = hu * hv;
        }
        __syncthreads();
        ull a[8];
#pragma unroll
        for (int i = 0; i < 8; i++) a[i] = 0ull;
        const float* fbase = sF + wid * 8;
#pragma unroll 4
        for (int k = 0; k < 128; k++) {
            float2 w = *(const float2*)&sW[k * 64 + 2 * lane];
            ull w0, w1;
            asm("mov.b64 %0, {%1, %1};" : "=l"(w0) : "f"(w.x));
            asm("mov.b64 %0, {%1, %1};" : "=l"(w1) : "f"(w.y));
            ulonglong2 fA = *(const ulonglong2*)(fbase + k * 64);
            ulonglong2 fB = *(const ulonglong2*)(fbase + k * 64 + 4);
            FMA2(a[0], fA.x, w0); FMA2(a[1], fA.y, w0);
            FMA2(a[2], fB.x, w0); FMA2(a[3], fB.y, w0);
            FMA2(a[4], fA.x, w1); FMA2(a[5], fA.y, w1);
            FMA2(a[6], fB.x, w1); FMA2(a[7], fB.y, w1);
        }
#pragma unroll
        for (int q = 0; q < 8; q++) {
            int e = wid * 8 + q;
            int u = sU[e], v = sV[e];
            union { ull uu; float f[2]; } c0, c1;
            c0.uu = a[q >> 1];
            c1.uu = a[4 + (q >> 1)];
            float v0 = c0.f[q & 1];
            float v1 = c1.f[q & 1];
            float2 au = *(const float2*)&A12[(size_t)u * 128 + 2 * lane];
            float2 av = *(const float2*)&A12[(size_t)v * 128 + 64 + 2 * lane];
            float t0 = v0 + au.x + av.x + ba2.x;
            float t1 = v1 + au.y + av.y + ba2.y;
            float r = fmaxf(t0, 0.f) * wb2.x + fmaxf(t1, 0.f) * wb2.y;
#pragma unroll
            for (int o = 16; o; o >>= 1) r += __shfl_xor_sync(0xffffffffu, r, o);
            if (lane == 0) {
                float l = (r + bbv) * invt;
                int ge = tile * 64 + e;
                float term;
                if (ge < EP) {
                    float ls = fminf(l, 0.f) - log1pf(expf(-fabsf(l)));
                    term = pw * ls;
                } else {
                    float ls = fminf(-l, 0.f) - log1pf(expf(-fabsf(l)));
                    term = ls;
                }
                dsum += (double)term;
            }
        }
    }
#pragma unroll
    for (int o = 16; o; o >>= 1) dsum += __shfl_xor_sync(0xffffffffu, dsum, o);
    __shared__ double sred[8];
    if (lane == 0) sred[wid] = dsum;
    __syncthreads();
    if (tid == 0) {
        double t = 0.0;
        for (int i = 0; i < 8; i++) t += sred[i];
        atomicAdd(acc, t);
    }
}

__global__ void finalize_kernel(const double* __restrict__ acc,
                                const double* __restrict__ accp,
                                float* __restrict__ out, int n)
{
    double kls = 0.0;
    for (int i = 0; i < 64; i++) kls += accp[i];
    double recon = -acc[0] / (double)ETOT;
    double kl = -0.5 * kls / ((double)Nn * 64.0);
    if (n >= 3) {
        out[0] = (float)(recon + kl);
        out[1] = (float)recon;
        out[2] = (float)kl;
    } else {
        out[0] = (float)(recon + kl);
    }
}

// ---------------- launch ----------------
extern "C" void kernel_launch(void* const* d_in, const int* in_sizes, int n_in,
                              void* d_out, int out_size)
{
    const float* x   = (const float*)d_in[0];
    const float* eps = (const float*)d_in[1];
    const int* edge_index = (const int*)d_in[2];
    const int* pos_edge   = (const int*)d_in[3];
    const int* neg_edge   = (const int*)d_in[4];
    const float* W1  = (const float*)d_in[5];
    const float* b1  = (const float*)d_in[6];
    const float* g1  = (const float*)d_in[7];
    const float* bt1 = (const float*)d_in[8];
    const float* Wmu = (const float*)d_in[9];
    const float* bmu = (const float*)d_in[10];
    const float* Wlv = (const float*)d_in[11];
    const float* blv = (const float*)d_in[12];
    const float* Wd1 = (const float*)d_in[13];
    const float* bd1 = (const float*)d_in[14];
    const float* Wd2 = (const float*)d_in[15];
    const float* bd2 = (const float*)d_in[16];
    const float* Wa  = (const float*)d_in[17];
    const float* ba  = (const float*)d_in[18];
    const float* Wb  = (const float*)d_in[19];
    const float* bb  = (const float*)d_in[20];
    const float* tau = (const float*)d_in[21];

    float *p_m, *p_h1, *p_tmulv, *p_z, *p_md, *p_hd, *p_hd2, *p_A12, *p_Wcat, *p_dis;
    int *p_degE, *p_degD, *p_startE, *p_startD, *p_curE, *p_curD, *p_permE, *p_permD;
    double *p_acc, *p_accp;
    cudaGetSymbolAddress((void**)&p_m, g_m);
    cudaGetSymbolAddress((void**)&p_h1, g_h1);
    cudaGetSymbolAddress((void**)&p_tmulv, g_tmulv);
    cudaGetSymbolAddress((void**)&p_z, g_z);
    cudaGetSymbolAddress((void**)&p_md, g_md);
    cudaGetSymbolAddress((void**)&p_hd, g_hd);
    cudaGetSymbolAddress((void**)&p_hd2, g_hd2);
    cudaGetSymbolAddress((void**)&p_A12, g_A12);
    cudaGetSymbolAddress((void**)&p_Wcat, g_Wcat);
    cudaGetSymbolAddress((void**)&p_dis, g_dis);
    cudaGetSymbolAddress((void**)&p_degE, g_degE);
    cudaGetSymbolAddress((void**)&p_degD, g_degD);
    cudaGetSymbolAddress((void**)&p_startE, g_startE);
    cudaGetSymbolAddress((void**)&p_startD, g_startD);
    cudaGetSymbolAddress((void**)&p_curE, g_curE);
    cudaGetSymbolAddress((void**)&p_curD, g_curD);
    cudaGetSymbolAddress((void**)&p_permE, g_permE);
    cudaGetSymbolAddress((void**)&p_permD, g_permD);
    cudaGetSymbolAddress((void**)&p_acc, g_acc);
    cudaGetSymbolAddress((void**)&p_accp, g_accp);

    const int* src = edge_index;
    const int* dst = edge_index + E2;
    const int* pu = pos_edge;
    const int* pv = pos_edge + EP;
    const int* nu = neg_edge;
    const int* nv = neg_edge + ENEG;

    // ---- CSR build ----
    zero_kernel<<<(Nn + 255) / 256, 256>>>(p_degE, p_degD, p_acc, p_accp);
    count_kernel<<<(E2 + 255) / 256, 256>>>(dst, pv, p_degE, p_degD);
    scan_kernel<<<2, 1024>>>(p_degE, p_startE, p_curE, p_degD, p_startD, p_curD, p_dis);
    fill_kernel<<<(E2 + 255) / 256, 256>>>(src, dst, pu, pv, p_curE, p_curD,
                                           p_permE, p_permD);

    // ---- encoder layer 1 ----
    {
        dim3 g(4, (Nn + 63) / 64);
        sgemm_kernel<<<g, 256>>>(x, W1, p_m, Nn, 256, 256, 256, 0);
    }
    gather_ln_kernel<<<Nn, 256>>>(p_m, p_permE, p_startE, b1, g1, bt1, p_h1);

    // ---- mu / logvar ----
    pack2_kernel<<<(256 * 64 + 255) / 256, 256>>>(Wmu, Wlv, p_Wcat, 256);
    {
        dim3 g(2, (Nn + 31) / 32);
        sgemm32_kernel<<<g, 128>>>(p_h1, p_Wcat, p_tmulv, Nn, 128, 256, 128, 0);
    }
    gather_zkl_kernel<<<Nn, 128>>>(p_tmulv, p_permE, p_startE, bmu, blv, eps,
                                   p_z, p_accp);

    // ---- decoder GCN pass 1 ----
    {
        dim3 g(1, (Nn + 31) / 32);
        sgemm32_kernel<<<g, 128>>>(p_z, Wd1, p_md, Nn, 64, 64, 64, 0);
    }
    scale_v4_kernel<<<(Nn * 16 + 255) / 256, 256>>>((float4*)p_md, p_dis);
    gather_dec_kernel<<<Nn / 4, 256>>>(p_md, p_permD, p_startD, p_dis, bd1, p_hd);

    // ---- decoder GCN pass 2 ----
    {
        dim3 g(1, (Nn + 31) / 32);
        sgemm32_kernel<<<g, 128>>>(p_hd, Wd2, p_md, Nn, 64, 64, 64, 0);
    }
    scale_v4_kernel<<<(Nn * 16 + 255) / 256, 256>>>((float4*)p_md, p_dis);
    gather_dec_kernel<<<Nn / 4, 256>>>(p_md, p_permD, p_startD, p_dis, bd2, p_hd2);

    // ---- per-node precompute [h@Wa1 | h@Wa2] ----
    pack2_kernel<<<(64 * 64 + 255) / 256, 256>>>(Wa, Wa + 64 * 64, p_Wcat, 64);
    {
        dim3 g(2, (Nn + 31) / 32);
        sgemm32_kernel<<<g, 128>>>(p_hd2, p_Wcat, p_A12, Nn, 128, 64, 128, 0);
    }

    // ---- fused edge decoder + loss ----
    {
        int smem = (8192 + 8192 + 4160 + 4160) * 4 + 128 * 4;   // 99328 B
        cudaFuncSetAttribute(edge_loss_kernel, cudaFuncAttributeMaxDynamicSharedMemorySize, smem);
        edge_loss_kernel<<<296, 256, smem>>>(p_hd2, p_A12, Wa, ba, Wb, bb, tau,
                                             pu, pv, nu, nv, p_acc);
    }

    finalize_kernel<<<1, 1>>>(p_acc, p_accp, (float*)d_out, out_size);

    (void)in_sizes; (void)n_in;
}

// round 8
// speedup vs baseline: 1.3336x; 1.3336x over previous
#include <cuda_runtime.h>
#include <math.h>
#include <stdint.h>

#define Nn    20000
#define HIDF  256
#define ZF    64
#define EP    120000
#define E2    240000
#define ENEG  600000
#define ETOT  720000

typedef unsigned long long ull;

// ---------------- scratch (static device globals; no allocation) ----------------
__device__ __align__(16) float g_m[Nn * HIDF];
__device__ __align__(16) float g_h1[Nn * HIDF];
__device__ __align__(16) float g_tmulv[Nn * 128];
__device__ __align__(16) float g_z[Nn * ZF];
__device__ __align__(16) float g_md[Nn * ZF];
__device__ __align__(16) float g_hd[Nn * ZF];
__device__ __align__(16) float g_hd2[Nn * ZF];
__device__ __align__(16) float g_A12[Nn * 128];
__device__ __align__(16) float g_Wcat[256 * 128];
__device__ float g_dis[Nn];
__device__ __align__(16) int g_degE[Nn];
__device__ __align__(16) int g_degD[Nn];
__device__ int g_startE[Nn + 1];
__device__ int g_startD[Nn + 1];
__device__ int g_curE[Nn];
__device__ int g_curD[Nn];
__device__ int g_permE[E2];
__device__ int g_permD[EP];
__device__ double g_acc[2];
__device__ double g_accp[64];

#define FMA2(c, a, b) asm("fma.rn.f32x2 %0, %1, %2, %0;" : "+l"(c) : "l"(a), "l"(b))

__device__ __forceinline__ uint32_t f2tf32(float x)
{
    uint32_t r;
    asm("cvt.rna.tf32.f32 %0, %1;" : "=r"(r) : "f"(x));
    return r;
}

__device__ __forceinline__ void mma_tf32(float& c0, float& c1, float& c2, float& c3,
    uint32_t a0, uint32_t a1, uint32_t a2, uint32_t a3, uint32_t b0, uint32_t b1)
{
    asm("mma.sync.aligned.m16n8k8.row.col.f32.tf32.tf32.f32 "
        "{%0,%1,%2,%3}, {%4,%5,%6,%7}, {%8,%9}, {%0,%1,%2,%3};"
        : "+f"(c0), "+f"(c1), "+f"(c2), "+f"(c3)
        : "r"(a0), "r"(a1), "r"(a2), "r"(a3), "r"(b0), "r"(b1));
}

// ---------------- zero ----------------
__global__ __launch_bounds__(256) void zero_kernel(int* degE, int* degD,
                                                   double* acc, double* accp)
{
    int idx = blockIdx.x * blockDim.x + threadIdx.x;
    if (idx < Nn) { degE[idx] = 0; degD[idx] = 0; }
    if (idx < 64) accp[idx] = 0.0;
    if (idx < 2) acc[idx] = 0.0;
}

// ---------------- degree count ----------------
__global__ __launch_bounds__(256) void count_kernel(
    const int* __restrict__ dst, const int* __restrict__ pd,
    int* __restrict__ degE, int* __restrict__ degD)
{
    int idx = blockIdx.x * blockDim.x + threadIdx.x;
    if (idx < E2) atomicAdd(&degE[dst[idx]], 1);
    if (idx < EP) atomicAdd(&degD[pd[idx]], 1);
}

// ---------------- exclusive scan of degrees ----------------
__global__ __launch_bounds__(1024) void scan_kernel(
    const int* __restrict__ degE, int* startE, int* curE,
    const int* __restrict__ degD, int* startD, int* curD, float* dis)
{
    const int* deg = (blockIdx.x == 0) ? degE : degD;
    int* start     = (blockIdx.x == 0) ? startE : startD;
    int* cur       = (blockIdx.x == 0) ? curE : curD;
    int t = threadIdx.x;
    int base = t * 20;
    int local[20];
    int sum = 0;
#pragma unroll
    for (int i = 0; i < 20; i++) {
        int idx = base + i;
        int v = (idx < Nn) ? deg[idx] : 0;
        local[i] = sum;
        sum += v;
    }
    __shared__ int ps[1024];
    ps[t] = sum;
    __syncthreads();
    for (int off = 1; off < 1024; off <<= 1) {
        int v = (t >= off) ? ps[t - off] : 0;
        __syncthreads();
        ps[t] += v;
        __syncthreads();
    }
    int offset = (t > 0) ? ps[t - 1] : 0;
#pragma unroll
    for (int i = 0; i < 20; i++) {
        int idx = base + i;
        if (idx < Nn) {
            int s = offset + local[i];
            start[idx] = s;
            cur[idx] = s;
            if (blockIdx.x == 1) dis[idx] = rsqrtf((float)deg[idx] + 1.0f);
        }
    }
    if (t == 1023) start[Nn] = ps[1023];
}

// ---------------- CSR fill ----------------
__global__ __launch_bounds__(256) void fill_kernel(
    const int* __restrict__ src, const int* __restrict__ dst,
    const int* __restrict__ ps, const int* __restrict__ pd,
    int* __restrict__ curE, int* __restrict__ curD,
    int* __restrict__ permE, int* __restrict__ permD)
{
    int idx = blockIdx.x * blockDim.x + threadIdx.x;
    if (idx < E2) {
        int slot = atomicAdd(&curE[dst[idx]], 1);
        permE[slot] = src[idx];
    }
    if (idx < EP) {
        int slot = atomicAdd(&curD[pd[idx]], 1);
        permD[slot] = ps[idx];
    }
}

// ---------------- SGEMM BM=64 ----------------
__global__ __launch_bounds__(256) void sgemm_kernel(
    const float* __restrict__ A, const float* __restrict__ B, float* __restrict__ C,
    int M, int Ncols, int K, int ldc, int coff)
{
    __shared__ float As2[16][128];
    __shared__ float Bs[16][64];
    int tid = threadIdx.x;
    int m0 = blockIdx.y * 64;
    int n0 = blockIdx.x * 64;
    int ty = tid >> 4, tx = tid & 15;
    int am = tid >> 2, ak = (tid & 3) * 4;
    int bk = tid >> 4, bn = (tid & 15) * 4;

    ull acc[4][2];
#pragma unroll
    for (int i = 0; i < 4; i++) { acc[i][0] = 0ull; acc[i][1] = 0ull; }

    for (int k0 = 0; k0 < K; k0 += 16) {
        float4 va = make_float4(0.f, 0.f, 0.f, 0.f);
        int gm = m0 + am;
        if (gm < M) va = *(const float4*)(A + (size_t)gm * K + k0 + ak);
        As2[ak + 0][2 * am] = va.x; As2[ak + 0][2 * am + 1] = va.x;
        As2[ak + 1][2 * am] = va.y; As2[ak + 1][2 * am + 1] = va.y;
        As2[ak + 2][2 * am] = va.z; As2[ak + 2][2 * am + 1] = va.z;
        As2[ak + 3][2 * am] = va.w; As2[ak + 3][2 * am + 1] = va.w;
        *(float4*)&Bs[bk][bn] = *(const float4*)(B + (size_t)(k0 + bk) * Ncols + n0 + bn);
        __syncthreads();
#pragma unroll
        for (int kk = 0; kk < 16; kk++) {
            ull a0 = *(const ull*)&As2[kk][(ty * 4 + 0) * 2];
            ull a1 = *(const ull*)&As2[kk][(ty * 4 + 1) * 2];
            ull a2 = *(const ull*)&As2[kk][(ty * 4 + 2) * 2];
            ull a3 = *(const ull*)&As2[kk][(ty * 4 + 3) * 2];
            union { float4 f4; ull u[2]; } bu;
            bu.f4 = *(const float4*)&Bs[kk][tx * 4];
            FMA2(acc[0][0], a0, bu.u[0]); FMA2(acc[0][1], a0, bu.u[1]);
            FMA2(acc[1][0], a1, bu.u[0]); FMA2(acc[1][1], a1, bu.u[1]);
            FMA2(acc[2][0], a2, bu.u[0]); FMA2(acc[2][1], a2, bu.u[1]);
            FMA2(acc[3][0], a3, bu.u[0]); FMA2(acc[3][1], a3, bu.u[1]);
        }
        __syncthreads();
    }
#pragma unroll
    for (int i = 0; i < 4; i++) {
        int gm = m0 + ty * 4 + i;
        if (gm < M) {
            union { ull u[2]; float f[4]; } r;
            r.u[0] = acc[i][0]; r.u[1] = acc[i][1];
            *(float4*)(C + (size_t)gm * ldc + coff + n0 + tx * 4) =
                make_float4(r.f[0], r.f[1], r.f[2], r.f[3]);
        }
    }
}

// ---------------- SGEMM BM=32 (128 threads); optional per-row output scale ------
__global__ __launch_bounds__(128) void sgemm32_kernel(
    const float* __restrict__ A, const float* __restrict__ B, float* __restrict__ C,
    int M, int Ncols, int K, int ldc, int coff, const float* __restrict__ rs)
{
    __shared__ float As2[16][64];
    __shared__ float Bs[16][64];
    int tid = threadIdx.x;
    int m0 = blockIdx.y * 32;
    int n0 = blockIdx.x * 64;
    int ty = tid >> 4, tx = tid & 15;
    int am = tid >> 2, ak = (tid & 3) * 4;
    int bk = tid >> 4, bn = (tid & 15) * 4;

    ull acc[4][2];
#pragma unroll
    for (int i = 0; i < 4; i++) { acc[i][0] = 0ull; acc[i][1] = 0ull; }

    for (int k0 = 0; k0 < K; k0 += 16) {
        float4 va = make_float4(0.f, 0.f, 0.f, 0.f);
        int gm = m0 + am;
        if (gm < M) va = *(const float4*)(A + (size_t)gm * K + k0 + ak);
        As2[ak + 0][2 * am] = va.x; As2[ak + 0][2 * am + 1] = va.x;
        As2[ak + 1][2 * am] = va.y; As2[ak + 1][2 * am + 1] = va.y;
        As2[ak + 2][2 * am] = va.z; As2[ak + 2][2 * am + 1] = va.z;
        As2[ak + 3][2 * am] = va.w; As2[ak + 3][2 * am + 1] = va.w;
        *(float4*)&Bs[bk][bn]     = *(const float4*)(B + (size_t)(k0 + bk) * Ncols + n0 + bn);
        *(float4*)&Bs[bk + 8][bn] = *(const float4*)(B + (size_t)(k0 + bk + 8) * Ncols + n0 + bn);
        __syncthreads();
#pragma unroll
        for (int kk = 0; kk < 16; kk++) {
            ull a0 = *(const ull*)&As2[kk][(ty * 4 + 0) * 2];
            ull a1 = *(const ull*)&As2[kk][(ty * 4 + 1) * 2];
            ull a2 = *(const ull*)&As2[kk][(ty * 4 + 2) * 2];
            ull a3 = *(const ull*)&As2[kk][(ty * 4 + 3) * 2];
            union { float4 f4; ull u[2]; } bu;
            bu.f4 = *(const float4*)&Bs[kk][tx * 4];
            FMA2(acc[0][0], a0, bu.u[0]); FMA2(acc[0][1], a0, bu.u[1]);
            FMA2(acc[1][0], a1, bu.u[0]); FMA2(acc[1][1], a1, bu.u[1]);
            FMA2(acc[2][0], a2, bu.u[0]); FMA2(acc[2][1], a2, bu.u[1]);
            FMA2(acc[3][0], a3, bu.u[0]); FMA2(acc[3][1], a3, bu.u[1]);
        }
        __syncthreads();
    }
#pragma unroll
    for (int i = 0; i < 4; i++) {
        int gm = m0 + ty * 4 + i;
        if (gm < M) {
            union { ull u[2]; float f[4]; } r;
            r.u[0] = acc[i][0]; r.u[1] = acc[i][1];
            float sc = rs ? rs[gm] : 1.0f;
            *(float4*)(C + (size_t)gm * ldc + coff + n0 + tx * 4) =
                make_float4(r.f[0] * sc, r.f[1] * sc, r.f[2] * sc, r.f[3] * sc);
        }
    }
}

// ---------------- weight pack ----------------
__global__ __launch_bounds__(256) void pack2_kernel(
    const float* __restrict__ A, const float* __restrict__ B,
    float* __restrict__ out, int K)
{
    int idx = blockIdx.x * blockDim.x + threadIdx.x;
    if (idx >= K * 64) return;
    int k = idx >> 6, j = idx & 63;
    out[k * 128 + j]      = A[k * 64 + j];
    out[k * 128 + 64 + j] = B[k * 64 + j];
}

// ---------------- fused gather + bias + LayerNorm + relu ----------------
__global__ __launch_bounds__(256) void gather_ln_kernel(
    const float* __restrict__ m, const int* __restrict__ perm,
    const int* __restrict__ start, const float* __restrict__ b1,
    const float* __restrict__ g1, const float* __restrict__ bt1,
    float* __restrict__ h1)
{
    __shared__ int sidx[256];
    __shared__ float red[8];
    int n = blockIdx.x;
    int j = threadIdx.x;
    int lane = j & 31, w = j >> 5;
    int s0 = start[n], s1 = start[n + 1];
    int deg = s1 - s0;
    int cnt = deg < 256 ? deg : 256;
    if (j < cnt) sidx[j] = perm[s0 + j];
    __syncthreads();
    float a0 = 0.f, a1 = 0.f, a2 = 0.f, a3 = 0.f;
    int k = 0;
    for (; k + 4 <= cnt; k += 4) {
        a0 += m[(size_t)sidx[k + 0] * 256 + j];
        a1 += m[(size_t)sidx[k + 1] * 256 + j];
        a2 += m[(size_t)sidx[k + 2] * 256 + j];
        a3 += m[(size_t)sidx[k + 3] * 256 + j];
    }
    for (; k < cnt; k++) a0 += m[(size_t)sidx[k] * 256 + j];
    for (int k2 = 256; k2 < deg; k2++) a0 += m[(size_t)perm[s0 + k2] * 256 + j];
    float v = (a0 + a1) + (a2 + a3) + b1[j];
    float s = v;
#pragma unroll
    for (int o = 16; o; o >>= 1) s += __shfl_xor_sync(0xffffffffu, s, o);
    if (lane == 0) red[w] = s;
    __syncthreads();
    float tot = 0.f;
#pragma unroll
    for (int i = 0; i < 8; i++) tot += red[i];
    float mu = tot * (1.f / 256.f);
    __syncthreads();
    float d = v - mu;
    float q = d * d;
#pragma unroll
    for (int o = 16; o; o >>= 1) q += __shfl_xor_sync(0xffffffffu, q, o);
    if (lane == 0) red[w] = q;
    __syncthreads();
    float tq = 0.f;
#pragma unroll
    for (int i = 0; i < 8; i++) tq += red[i];
    float var = tq * (1.f / 256.f);
    float o = d * rsqrtf(var + 1e-5f) * g1[j] + bt1[j];
    h1[(size_t)n * 256 + j] = fmaxf(o, 0.f);
}

// ---------------- fused gather + z-reparam + KL ----------------
__global__ __launch_bounds__(128) void gather_zkl_kernel(
    const float* __restrict__ t, const int* __restrict__ perm,
    const int* __restrict__ start, const float* __restrict__ bmu,
    const float* __restrict__ blv, const float* __restrict__ eps,
    float* __restrict__ z, double* __restrict__ accp)
{
    __shared__ int sidx[128];
    __shared__ float row[128];
    __shared__ double sred[4];
    int n = blockIdx.x;
    int j = threadIdx.x;
    int lane = j & 31, w = j >> 5;
    int s0 = start[n], s1 = start[n + 1];
    int deg = s1 - s0;
    int cnt = deg < 128 ? deg : 128;
    if (j < cnt) sidx[j] = perm[s0 + j];
    __syncthreads();
    float a0 = 0.f, a1 = 0.f, a2 = 0.f, a3 = 0.f;
    int k = 0;
    for (; k + 4 <= cnt; k += 4) {
        a0 += t[(size_t)sidx[k + 0] * 128 + j];
        a1 += t[(size_t)sidx[k + 1] * 128 + j];
        a2 += t[(size_t)sidx[k + 2] * 128 + j];
        a3 += t[(size_t)sidx[k + 3] * 128 + j];
    }
    for (; k < cnt; k++) a0 += t[(size_t)sidx[k] * 128 + j];
    for (int k2 = 128; k2 < deg; k2++) a0 += t[(size_t)perm[s0 + k2] * 128 + j];
    row[j] = (a0 + a1) + (a2 + a3);
    __syncthreads();
    double local = 0.0;
    if (j < 64) {
        float mu = row[j] + bmu[j];
        float lv = row[j + 64] + blv[j];
        z[(size_t)n * 64 + j] = mu + eps[(size_t)n * 64 + j] * expf(0.5f * lv);
        local = (double)(1.f + lv - mu * mu - expf(lv));
    }
#pragma unroll
    for (int o = 16; o; o >>= 1) local += __shfl_xor_sync(0xffffffffu, local, o);
    if (lane == 0) sred[w] = local;
    __syncthreads();
    if (j == 0) {
        double tt = sred[0] + sred[1] + sred[2] + sred[3];
        atomicAdd(&accp[n & 63], tt);
    }
}

// ---------------- fused decoder gather + selfloop + bias + relu ----------------
__global__ __launch_bounds__(256) void gather_dec_kernel(
    const float* __restrict__ msc, const int* __restrict__ perm,
    const int* __restrict__ start, const float* __restrict__ dis,
    const float* __restrict__ bd, float* __restrict__ outp)
{
    __shared__ int sidx[4][64];
    int tid = threadIdx.x;
    int g = tid >> 6, j = tid & 63;
    int n = blockIdx.x * 4 + g;
    int s0 = start[n], s1 = start[n + 1];
    int deg = s1 - s0;
    int cnt = deg < 64 ? deg : 64;
    if (j < cnt) sidx[g][j] = perm[s0 + j];
    __syncthreads();
    float a0 = 0.f, a1 = 0.f, a2 = 0.f, a3 = 0.f;
    int k = 0;
    for (; k + 4 <= cnt; k += 4) {
        a0 += msc[(size_t)sidx[g][k + 0] * 64 + j];
        a1 += msc[(size_t)sidx[g][k + 1] * 64 + j];
        a2 += msc[(size_t)sidx[g][k + 2] * 64 + j];
        a3 += msc[(size_t)sidx[g][k + 3] * 64 + j];
    }
    for (; k < cnt; k++) a0 += msc[(size_t)sidx[g][k] * 64 + j];
    for (int k2 = 64; k2 < deg; k2++) a0 += msc[(size_t)perm[s0 + k2] * 64 + j];
    float v = (a0 + a1) + (a2 + a3) + msc[(size_t)n * 64 + j];
    v = v * dis[n] + bd[j];
    outp[(size_t)n * 64 + j] = fmaxf(v, 0.f);
}

// ---------------- fused edge decoder + BCE loss: tf32 mma.sync mainloop --------
// 64-edge tiles. 8 warps: warp w -> m-tile mt=w&3 (16 edges), n-half nh=w>>2 (32 cols).
__global__ __launch_bounds__(256) void edge_loss_kernel(
    const float* __restrict__ h, const float* __restrict__ A12,
    const float* __restrict__ Wa, const float* __restrict__ ba,
    const float* __restrict__ Wb, const float* __restrict__ bb,
    const float* __restrict__ tau,
    const int* __restrict__ pu, const int* __restrict__ pv,
    const int* __restrict__ nu, const int* __restrict__ nv,
    double* __restrict__ acc)
{
    extern __shared__ float sm[];
    float* sWB    = sm;                 // B fragments: 16kt x 8nt x 32 x 2 = 8192
    float* sFA    = sWB + 8192;         // A fragments: (4mt*16kt*4slot) x 33 = 8448
    float* sHU    = sFA + 8448;         // 64 x 65 = 4160
    float* sHV    = sHU + 4160;         // 4160
    float* sLogit = sHV + 4160;         // 64
    int* sU = (int*)(sLogit + 64);      // 64
    int* sV = sU + 64;                  // 64
    uint32_t* uWB = (uint32_t*)sWB;
    uint32_t* uFA = (uint32_t*)sFA;

    int tid = threadIdx.x;
    int lane = tid & 31, wid = tid >> 5;
    int mt = wid & 3, nh = wid >> 2;

    // Build B fragments once (tf32). b0:(k=ln%4, n=ln/4), b1:(k=ln%4+4, n=ln/4)
    const float* W34 = Wa + 128 * 64;
    for (int i = tid; i < 8192; i += 256) {
        int s  = i & 1;
        int ln = (i >> 1) & 31;
        int nt = (i >> 6) & 7;
        int kt = i >> 9;
        int kk = kt * 8 + (ln & 3) + 4 * s;
        int nn = nt * 8 + (ln >> 2);
        uWB[i] = f2tf32(W34[kk * 64 + nn]);
    }

    float tc = fmaxf(tau[0], 1e-4f);
    float invt = 1.0f / tc;
    float bbv = bb[0];
    float2 baR[4], wbR[4];
#pragma unroll
    for (int nt = 0; nt < 4; nt++) {
        int j0 = nh * 32 + nt * 8 + 2 * (lane & 3);
        baR[nt] = *(const float2*)&ba[j0];
        wbR[nt] = *(const float2*)&Wb[j0];
    }
    const float pw = (float)ENEG / (float)EP;
    double dsum = 0.0;

    int eg0 = mt * 16 + (lane >> 2);   // this thread's edge rows in C fragment
    int eg1 = eg0 + 8;

    // phase-B constants for this thread
    int ebld = tid & 63;               // edge this thread builds
    int f0   = tid >> 6;               // 0..3
    int mtb  = ebld >> 4;
    int rb   = ebld & 15;
    int lf   = ((rb & 7) << 2) | (f0 & 3);
    int rhi  = rb >> 3;

    int nTiles = ETOT / 64;  // 11250
    for (int tile = blockIdx.x; tile < nTiles; tile += gridDim.x) {
        __syncthreads();
        if (tid < 64) {
            int ge = tile * 64 + tid;
            int u, v;
            if (ge < EP) { u = pu[ge]; v = pv[ge]; }
            else         { u = nu[ge - EP]; v = nv[ge - EP]; }
            sU[tid] = u; sV[tid] = v; sLogit[tid] = 0.f;
        }
        __syncthreads();
        // phase A: coalesced gather of h rows
#pragma unroll
        for (int ee = 0; ee < 8; ee++) {
            int e = wid * 8 + ee;
            int u = sU[e], v = sV[e];
            sHU[e * 65 + lane]      = h[(size_t)u * 64 + lane];
            sHU[e * 65 + 32 + lane] = h[(size_t)u * 64 + 32 + lane];
            sHV[e * 65 + lane]      = h[(size_t)v * 64 + lane];
            sHV[e * 65 + 32 + lane] = h[(size_t)v * 64 + 32 + lane];
        }
        __syncthreads();
        // phase B: feature build directly into A-fragment layout (tf32)
#pragma unroll
        for (int p = 0; p < 16; p++) {
            int f = f0 + 4 * p;                 // 0..63
            float hu = sHU[ebld * 65 + f], hv = sHV[ebld * 65 + f];
            uint32_t dfrag = f2tf32(fabsf(hu - hv));   // feature index f
            uint32_t mfrag = f2tf32(hu * hv);          // feature index 64+f
            int kt = f >> 3;
            int slot = rhi | (((f >> 2) & 1) << 1);
            int base = ((mtb * 16 + kt) * 4 + slot) * 33 + lf;
            uFA[base] = dfrag;
            uFA[base + 1056] = mfrag;           // kt+8 => +8*4*33
        }
        __syncthreads();
        // mainloop: 16 k-tiles of tf32 mma (m16n8k8)
        float a4[4][4];
#pragma unroll
        for (int i = 0; i < 4; i++) { a4[i][0] = a4[i][1] = a4[i][2] = a4[i][3] = 0.f; }
#pragma unroll 4
        for (int kt = 0; kt < 16; kt++) {
            int ab = (mt * 16 + kt) * 4 * 33 + lane;
            uint32_t A0 = uFA[ab], A1 = uFA[ab + 33], A2 = uFA[ab + 66], A3 = uFA[ab + 99];
#pragma unroll
            for (int nt = 0; nt < 4; nt++) {
                int bidx = ((kt * 8 + nh * 4 + nt) * 32 + lane) * 2;
                uint32_t B0 = uWB[bidx], B1 = uWB[bidx + 1];
                mma_tf32(a4[nt][0], a4[nt][1], a4[nt][2], a4[nt][3],
                         A0, A1, A2, A3, B0, B1);
            }
        }
        // epilogue: + A12 + ba, relu, *Wb, quad-reduce, smem-atomic combine
        {
            int u0 = sU[eg0], v0 = sV[eg0], u1 = sU[eg1], v1 = sV[eg1];
            float p0 = 0.f, p1 = 0.f;
#pragma unroll
            for (int nt = 0; nt < 4; nt++) {
                int j0 = nh * 32 + nt * 8 + 2 * (lane & 3);
                float2 au0 = *(const float2*)&A12[(size_t)u0 * 128 + j0];
                float2 av0 = *(const float2*)&A12[(size_t)v0 * 128 + 64 + j0];
                float2 au1 = *(const float2*)&A12[(size_t)u1 * 128 + j0];
                float2 av1 = *(const float2*)&A12[(size_t)v1 * 128 + 64 + j0];
                float t0 = a4[nt][0] + au0.x + av0.x + baR[nt].x;
                float t1 = a4[nt][1] + au0.y + av0.y + baR[nt].y;
                float t2 = a4[nt][2] + au1.x + av1.x + baR[nt].x;
                float t3 = a4[nt][3] + au1.y + av1.y + baR[nt].y;
                p0 += fmaxf(t0, 0.f) * wbR[nt].x + fmaxf(t1, 0.f) * wbR[nt].y;
                p1 += fmaxf(t2, 0.f) * wbR[nt].x + fmaxf(t3, 0.f) * wbR[nt].y;
            }
            p0 += __shfl_xor_sync(0xffffffffu, p0, 1);
            p0 += __shfl_xor_sync(0xffffffffu, p0, 2);
            p1 += __shfl_xor_sync(0xffffffffu, p1, 1);
            p1 += __shfl_xor_sync(0xffffffffu, p1, 2);
            if ((lane & 3) == 0) {
                atomicAdd(&sLogit[eg0], p0);
                atomicAdd(&sLogit[eg1], p1);
            }
        }
        __syncthreads();
        if (tid < 64) {
            float l = (sLogit[tid] + bbv) * invt;
            int ge = tile * 64 + tid;
            float term;
            if (ge < EP) {
                float ls = fminf(l, 0.f) - log1pf(expf(-fabsf(l)));
                term = pw * ls;
            } else {
                float ls = fminf(-l, 0.f) - log1pf(expf(-fabsf(l)));
                term = ls;
            }
            dsum += (double)term;
        }
    }
#pragma unroll
    for (int o = 16; o; o >>= 1) dsum += __shfl_xor_sync(0xffffffffu, dsum, o);
    __shared__ double sredd[8];
    int lane2 = tid & 31, wid2 = tid >> 5;
    if (lane2 == 0) sredd[wid2] = dsum;
    __syncthreads();
    if (tid == 0) {
        double t = 0.0;
        for (int i = 0; i < 8; i++) t += sredd[i];
        atomicAdd(acc, t);
    }
}

__global__ void finalize_kernel(const double* __restrict__ acc,
                                const double* __restrict__ accp,
                                float* __restrict__ out, int n)
{
    double kls = 0.0;
    for (int i = 0; i < 64; i++) kls += accp[i];
    double recon = -acc[0] / (double)ETOT;
    double kl = -0.5 * kls / ((double)Nn * 64.0);
    if (n >= 3) {
        out[0] = (float)(recon + kl);
        out[1] = (float)recon;
        out[2] = (float)kl;
    } else {
        out[0] = (float)(recon + kl);
    }
}

// ---------------- launch ----------------
extern "C" void kernel_launch(void* const* d_in, const int* in_sizes, int n_in,
                              void* d_out, int out_size)
{
    const float* x   = (const float*)d_in[0];
    const float* eps = (const float*)d_in[1];
    const int* edge_index = (const int*)d_in[2];
    const int* pos_edge   = (const int*)d_in[3];
    const int* neg_edge   = (const int*)d_in[4];
    const float* W1  = (const float*)d_in[5];
    const float* b1  = (const float*)d_in[6];
    const float* g1  = (const float*)d_in[7];
    const float* bt1 = (const float*)d_in[8];
    const float* Wmu = (const float*)d_in[9];
    const float* bmu = (const float*)d_in[10];
    const float* Wlv = (const float*)d_in[11];
    const float* blv = (const float*)d_in[12];
    const float* Wd1 = (const float*)d_in[13];
    const float* bd1 = (const float*)d_in[14];
    const float* Wd2 = (const float*)d_in[15];
    const float* bd2 = (const float*)d_in[16];
    const float* Wa  = (const float*)d_in[17];
    const float* ba  = (const float*)d_in[18];
    const float* Wb  = (const float*)d_in[19];
    const float* bb  = (const float*)d_in[20];
    const float* tau = (const float*)d_in[21];

    float *p_m, *p_h1, *p_tmulv, *p_z, *p_md, *p_hd, *p_hd2, *p_A12, *p_Wcat, *p_dis;
    int *p_degE, *p_degD, *p_startE, *p_startD, *p_curE, *p_curD, *p_permE, *p_permD;
    double *p_acc, *p_accp;
    cudaGetSymbolAddress((void**)&p_m, g_m);
    cudaGetSymbolAddress((void**)&p_h1, g_h1);
    cudaGetSymbolAddress((void**)&p_tmulv, g_tmulv);
    cudaGetSymbolAddress((void**)&p_z, g_z);
    cudaGetSymbolAddress((void**)&p_md, g_md);
    cudaGetSymbolAddress((void**)&p_hd, g_hd);
    cudaGetSymbolAddress((void**)&p_hd2, g_hd2);
    cudaGetSymbolAddress((void**)&p_A12, g_A12);
    cudaGetSymbolAddress((void**)&p_Wcat, g_Wcat);
    cudaGetSymbolAddress((void**)&p_dis, g_dis);
    cudaGetSymbolAddress((void**)&p_degE, g_degE);
    cudaGetSymbolAddress((void**)&p_degD, g_degD);
    cudaGetSymbolAddress((void**)&p_startE, g_startE);
    cudaGetSymbolAddress((void**)&p_startD, g_startD);
    cudaGetSymbolAddress((void**)&p_curE, g_curE);
    cudaGetSymbolAddress((void**)&p_curD, g_curD);
    cudaGetSymbolAddress((void**)&p_permE, g_permE);
    cudaGetSymbolAddress((void**)&p_permD, g_permD);
    cudaGetSymbolAddress((void**)&p_acc, g_acc);
    cudaGetSymbolAddress((void**)&p_accp, g_accp);

    const int* src = edge_index;
    const int* dst = edge_index + E2;
    const int* pu = pos_edge;
    const int* pv = pos_edge + EP;
    const int* nu = neg_edge;
    const int* nv = neg_edge + ENEG;

    // ---- CSR build ----
    zero_kernel<<<(Nn + 255) / 256, 256>>>(p_degE, p_degD, p_acc, p_accp);
    count_kernel<<<(E2 + 255) / 256, 256>>>(dst, pv, p_degE, p_degD);
    scan_kernel<<<2, 1024>>>(p_degE, p_startE, p_curE, p_degD, p_startD, p_curD, p_dis);
    fill_kernel<<<(E2 + 255) / 256, 256>>>(src, dst, pu, pv, p_curE, p_curD,
                                           p_permE, p_permD);

    // ---- encoder layer 1 ----
    {
        dim3 g(4, (Nn + 63) / 64);
        sgemm_kernel<<<g, 256>>>(x, W1, p_m, Nn, 256, 256, 256, 0);
    }
    gather_ln_kernel<<<Nn, 256>>>(p_m, p_permE, p_startE, b1, g1, bt1, p_h1);

    // ---- mu / logvar ----
    pack2_kernel<<<(256 * 64 + 255) / 256, 256>>>(Wmu, Wlv, p_Wcat, 256);
    {
        dim3 g(2, (Nn + 31) / 32);
        sgemm32_kernel<<<g, 128>>>(p_h1, p_Wcat, p_tmulv, Nn, 128, 256, 128, 0,
                                   (const float*)0);
    }
    gather_zkl_kernel<<<Nn, 128>>>(p_tmulv, p_permE, p_startE, bmu, blv, eps,
                                   p_z, p_accp);

    // ---- decoder GCN pass 1 (dis-scaling fused into GEMM epilogue) ----
    {
        dim3 g(1, (Nn + 31) / 32);
        sgemm32_kernel<<<g, 128>>>(p_z, Wd1, p_md, Nn, 64, 64, 64, 0, p_dis);
    }
    gather_dec_kernel<<<Nn / 4, 256>>>(p_md, p_permD, p_startD, p_dis, bd1, p_hd);

    // ---- decoder GCN pass 2 ----
    {
        dim3 g(1, (Nn + 31) / 32);
        sgemm32_kernel<<<g, 128>>>(p_hd, Wd2, p_md, Nn, 64, 64, 64, 0, p_dis);
    }
    gather_dec_kernel<<<Nn / 4, 256>>>(p_md, p_permD, p_startD, p_dis, bd2, p_hd2);

    // ---- per-node precompute [h@Wa1 | h@Wa2] ----
    pack2_kernel<<<(64 * 64 + 255) / 256, 256>>>(Wa, Wa + 64 * 64, p_Wcat, 64);
    {
        dim3 g(2, (Nn + 31) / 32);
        sgemm32_kernel<<<g, 128>>>(p_hd2, p_Wcat, p_A12, Nn, 128, 64, 128, 0,
                                   (const float*)0);
    }

    // ---- fused edge decoder + loss (tf32 mma) ----
    {
        int smem = (8192 + 8448 + 4160 + 4160 + 64) * 4 + 128 * 4;   // 100608 B
        cudaFuncSetAttribute(edge_loss_kernel, cudaFuncAttributeMaxDynamicSharedMemorySize, smem);
        edge_loss_kernel<<<296, 256, smem>>>(p_hd2, p_A12, Wa, ba, Wb, bb, tau,
                                             pu, pv, nu, nv, p_acc);
    }

    finalize_kernel<<<1, 1>>>(p_acc, p_accp, (float*)d_out, out_size);

    (void)in_sizes; (void)n_in;
}

// round 9
// speedup vs baseline: 1.3604x; 1.0201x over previous
#include <cuda_runtime.h>
#include <math.h>
#include <stdint.h>

#define Nn    20000
#define HIDF  256
#define ZF    64
#define EP    120000
#define E2    240000
#define ENEG  600000
#define ETOT  720000

typedef unsigned long long ull;

// ---------------- scratch (static device globals; no allocation) ----------------
__device__ __align__(16) float g_m[Nn * HIDF];
__device__ __align__(16) float g_h1[Nn * HIDF];
__device__ __align__(16) float g_tmulv[Nn * 128];
__device__ __align__(16) float g_z[Nn * ZF];
__device__ __align__(16) float g_md[Nn * ZF];
__device__ __align__(16) float g_hd[Nn * ZF];
__device__ __align__(16) float g_hd2[Nn * ZF];
__device__ __align__(16) float g_A12[Nn * 128];
__device__ float g_dis[Nn];
__device__ __align__(16) int g_degE[Nn];
__device__ __align__(16) int g_degD[Nn];
__device__ int g_startE[Nn + 1];
__device__ int g_startD[Nn + 1];
__device__ int g_curE[Nn];
__device__ int g_curD[Nn];
__device__ int g_permE[E2];
__device__ int g_permD[EP];
__device__ double g_acc[2];
__device__ double g_accp[64];

__device__ __forceinline__ uint32_t f2tf32(float x)
{
    uint32_t r;
    asm("cvt.rna.tf32.f32 %0, %1;" : "=r"(r) : "f"(x));
    return r;
}

__device__ __forceinline__ void mma_tf32(float& c0, float& c1, float& c2, float& c3,
    uint32_t a0, uint32_t a1, uint32_t a2, uint32_t a3, uint32_t b0, uint32_t b1)
{
    asm("mma.sync.aligned.m16n8k8.row.col.f32.tf32.tf32.f32 "
        "{%0,%1,%2,%3}, {%4,%5,%6,%7}, {%8,%9}, {%0,%1,%2,%3};"
        : "+f"(c0), "+f"(c1), "+f"(c2), "+f"(c3)
        : "r"(a0), "r"(a1), "r"(a2), "r"(a3), "r"(b0), "r"(b1));
}

// ---------------- zero ----------------
__global__ __launch_bounds__(256) void zero_kernel(int* degE, int* degD,
                                                   double* acc, double* accp)
{
    int idx = blockIdx.x * blockDim.x + threadIdx.x;
    if (idx < Nn) { degE[idx] = 0; degD[idx] = 0; }
    if (idx < 64) accp[idx] = 0.0;
    if (idx < 2) acc[idx] = 0.0;
}

// ---------------- degree count ----------------
__global__ __launch_bounds__(256) void count_kernel(
    const int* __restrict__ dst, const int* __restrict__ pd,
    int* __restrict__ degE, int* __restrict__ degD)
{
    int idx = blockIdx.x * blockDim.x + threadIdx.x;
    if (idx < E2) atomicAdd(&degE[dst[idx]], 1);
    if (idx < EP) atomicAdd(&degD[pd[idx]], 1);
}

// ---------------- exclusive scan of degrees ----------------
__global__ __launch_bounds__(1024) void scan_kernel(
    const int* __restrict__ degE, int* startE, int* curE,
    const int* __restrict__ degD, int* startD, int* curD, float* dis)
{
    const int* deg = (blockIdx.x == 0) ? degE : degD;
    int* start     = (blockIdx.x == 0) ? startE : startD;
    int* cur       = (blockIdx.x == 0) ? curE : curD;
    int t = threadIdx.x;
    int base = t * 20;
    int local[20];
    int sum = 0;
#pragma unroll
    for (int i = 0; i < 20; i++) {
        int idx = base + i;
        int v = (idx < Nn) ? deg[idx] : 0;
        local[i] = sum;
        sum += v;
    }
    __shared__ int ps[1024];
    ps[t] = sum;
    __syncthreads();
    for (int off = 1; off < 1024; off <<= 1) {
        int v = (t >= off) ? ps[t - off] : 0;
        __syncthreads();
        ps[t] += v;
        __syncthreads();
    }
    int offset = (t > 0) ? ps[t - 1] : 0;
#pragma unroll
    for (int i = 0; i < 20; i++) {
        int idx = base + i;
        if (idx < Nn) {
            int s = offset + local[i];
            start[idx] = s;
            cur[idx] = s;
            if (blockIdx.x == 1) dis[idx] = rsqrtf((float)deg[idx] + 1.0f);
        }
    }
    if (t == 1023) start[Nn] = ps[1023];
}

// ---------------- CSR fill ----------------
__global__ __launch_bounds__(256) void fill_kernel(
    const int* __restrict__ src, const int* __restrict__ dst,
    const int* __restrict__ ps, const int* __restrict__ pd,
    int* __restrict__ curE, int* __restrict__ curD,
    int* __restrict__ permE, int* __restrict__ permD)
{
    int idx = blockIdx.x * blockDim.x + threadIdx.x;
    if (idx < E2) {
        int slot = atomicAdd(&curE[dst[idx]], 1);
        permE[slot] = src[idx];
    }
    if (idx < EP) {
        int slot = atomicAdd(&curD[pd[idx]], 1);
        permD[slot] = ps[idx];
    }
}

// ---------------- tf32 tensor-core GEMM: C[M,ldc](+coff+n0) = A[M,K] @ B[K,bstride] tile
// BM=64, BN=64, BK=32. 8 warps: warp w -> mt=w&3 (16 rows), nh=w>>2 (32 cols).
__global__ __launch_bounds__(256) void tgemm_kernel(
    const float* __restrict__ A, const float* __restrict__ B, float* __restrict__ C,
    int M, int K, int bstride, int ldc, int coff, const float* __restrict__ rs)
{
    __shared__ uint32_t sA[2048];   // ((mt*4+kt)*32+lane)*4 + reg   (LDS.128-able)
    __shared__ uint32_t sB[2048];   // ((kt*8+nt)*32+ln)*2 + s       (LDS.64-able)
    int tid = threadIdx.x;
    int lane = tid & 31, wid = tid >> 5;
    int mt = wid & 3, nh = wid >> 2;
    int m0 = blockIdx.y * 64;
    int n0 = blockIdx.x * 64;

    float c[4][4];
#pragma unroll
    for (int i = 0; i < 4; i++) { c[i][0] = c[i][1] = c[i][2] = c[i][3] = 0.f; }

    int arow = tid >> 2;            // 0..63
    int acb  = (tid & 3) * 8;       // col base within 32-chunk
    int brow = tid >> 3;            // 0..31 (k within chunk)
    int bnb  = (tid & 7) * 8;       // n within 64

    for (int k0 = 0; k0 < K; k0 += 32) {
        // ---- build A fragments ----
        int gm = m0 + arow;
#pragma unroll
        for (int q = 0; q < 2; q++) {
            float4 v = (gm < M)
                ? *(const float4*)(A + (size_t)gm * K + k0 + acb + q * 4)
                : make_float4(0.f, 0.f, 0.f, 0.f);
            float e[4] = {v.x, v.y, v.z, v.w};
#pragma unroll
            for (int t2 = 0; t2 < 4; t2++) {
                int kl = acb + q * 4 + t2;
                int amt = arow >> 4, akt = kl >> 3;
                int rr = arow & 15, cc = kl & 7;
                int ln = ((rr & 7) << 2) | (cc & 3);
                int rg = (rr >> 3) | (((cc >> 2) & 1) << 1);
                sA[((amt * 4 + akt) * 32 + ln) * 4 + rg] = f2tf32(e[t2]);
            }
        }
        // ---- build B fragments ----
#pragma unroll
        for (int q = 0; q < 2; q++) {
            float4 v = *(const float4*)(B + (size_t)(k0 + brow) * bstride + n0 + bnb + q * 4);
            float e[4] = {v.x, v.y, v.z, v.w};
#pragma unroll
            for (int t2 = 0; t2 < 4; t2++) {
                int nl = bnb + q * 4 + t2;
                int bkt = brow >> 3, bnt = nl >> 3;
                int ln = ((nl & 7) << 2) | (brow & 3);
                int s  = (brow >> 2) & 1;
                sB[((bkt * 8 + bnt) * 32 + ln) * 2 + s] = f2tf32(e[t2]);
            }
        }
        __syncthreads();
        // ---- mainloop ----
#pragma unroll
        for (int kt = 0; kt < 4; kt++) {
            uint4 av = *(const uint4*)&sA[((mt * 4 + kt) * 32 + lane) * 4];
#pragma unroll
            for (int nt2 = 0; nt2 < 4; nt2++) {
                int nt = nh * 4 + nt2;
                uint2 bv = *(const uint2*)&sB[((kt * 8 + nt) * 32 + lane) * 2];
                mma_tf32(c[nt2][0], c[nt2][1], c[nt2][2], c[nt2][3],
                         av.x, av.y, av.z, av.w, bv.x, bv.y);
            }
        }
        __syncthreads();
    }
    // ---- epilogue ----
    int r0 = m0 + mt * 16 + (lane >> 2);
    int r1 = r0 + 8;
    float sc0 = (r0 < M && rs) ? rs[r0] : 1.f;
    float sc1 = (r1 < M && rs) ? rs[r1] : 1.f;
#pragma unroll
    for (int nt2 = 0; nt2 < 4; nt2++) {
        int j = n0 + nh * 32 + nt2 * 8 + (lane & 3) * 2;
        if (r0 < M)
            *(float2*)(C + (size_t)r0 * ldc + coff + j) =
                make_float2(c[nt2][0] * sc0, c[nt2][1] * sc0);
        if (r1 < M)
            *(float2*)(C + (size_t)r1 * ldc + coff + j) =
                make_float2(c[nt2][2] * sc1, c[nt2][3] * sc1);
    }
}

// ---------------- fused gather + bias + LayerNorm + relu ----------------
__global__ __launch_bounds__(256) void gather_ln_kernel(
    const float* __restrict__ m, const int* __restrict__ perm,
    const int* __restrict__ start, const float* __restrict__ b1,
    const float* __restrict__ g1, const float* __restrict__ bt1,
    float* __restrict__ h1)
{
    __shared__ int sidx[256];
    __shared__ float red[8];
    int n = blockIdx.x;
    int j = threadIdx.x;
    int lane = j & 31, w = j >> 5;
    int s0 = start[n], s1 = start[n + 1];
    int deg = s1 - s0;
    int cnt = deg < 256 ? deg : 256;
    if (j < cnt) sidx[j] = perm[s0 + j];
    __syncthreads();
    float a0 = 0.f, a1 = 0.f, a2 = 0.f, a3 = 0.f;
    int k = 0;
    for (; k + 4 <= cnt; k += 4) {
        a0 += m[(size_t)sidx[k + 0] * 256 + j];
        a1 += m[(size_t)sidx[k + 1] * 256 + j];
        a2 += m[(size_t)sidx[k + 2] * 256 + j];
        a3 += m[(size_t)sidx[k + 3] * 256 + j];
    }
    for (; k < cnt; k++) a0 += m[(size_t)sidx[k] * 256 + j];
    for (int k2 = 256; k2 < deg; k2++) a0 += m[(size_t)perm[s0 + k2] * 256 + j];
    float v = (a0 + a1) + (a2 + a3) + b1[j];
    float s = v;
#pragma unroll
    for (int o = 16; o; o >>= 1) s += __shfl_xor_sync(0xffffffffu, s, o);
    if (lane == 0) red[w] = s;
    __syncthreads();
    float tot = 0.f;
#pragma unroll
    for (int i = 0; i < 8; i++) tot += red[i];
    float mu = tot * (1.f / 256.f);
    __syncthreads();
    float d = v - mu;
    float q = d * d;
#pragma unroll
    for (int o = 16; o; o >>= 1) q += __shfl_xor_sync(0xffffffffu, q, o);
    if (lane == 0) red[w] = q;
    __syncthreads();
    float tq = 0.f;
#pragma unroll
    for (int i = 0; i < 8; i++) tq += red[i];
    float var = tq * (1.f / 256.f);
    float o = d * rsqrtf(var + 1e-5f) * g1[j] + bt1[j];
    h1[(size_t)n * 256 + j] = fmaxf(o, 0.f);
}

// ---------------- fused gather + z-reparam + KL ----------------
__global__ __launch_bounds__(128) void gather_zkl_kernel(
    const float* __restrict__ t, const int* __restrict__ perm,
    const int* __restrict__ start, const float* __restrict__ bmu,
    const float* __restrict__ blv, const float* __restrict__ eps,
    float* __restrict__ z, double* __restrict__ accp)
{
    __shared__ int sidx[128];
    __shared__ float row[128];
    __shared__ double sred[4];
    int n = blockIdx.x;
    int j = threadIdx.x;
    int lane = j & 31, w = j >> 5;
    int s0 = start[n], s1 = start[n + 1];
    int deg = s1 - s0;
    int cnt = deg < 128 ? deg : 128;
    if (j < cnt) sidx[j] = perm[s0 + j];
    __syncthreads();
    float a0 = 0.f, a1 = 0.f, a2 = 0.f, a3 = 0.f;
    int k = 0;
    for (; k + 4 <= cnt; k += 4) {
        a0 += t[(size_t)sidx[k + 0] * 128 + j];
        a1 += t[(size_t)sidx[k + 1] * 128 + j];
        a2 += t[(size_t)sidx[k + 2] * 128 + j];
        a3 += t[(size_t)sidx[k + 3] * 128 + j];
    }
    for (; k < cnt; k++) a0 += t[(size_t)sidx[k] * 128 + j];
    for (int k2 = 128; k2 < deg; k2++) a0 += t[(size_t)perm[s0 + k2] * 128 + j];
    row[j] = (a0 + a1) + (a2 + a3);
    __syncthreads();
    double local = 0.0;
    if (j < 64) {
        float mu = row[j] + bmu[j];
        float lv = row[j + 64] + blv[j];
        z[(size_t)n * 64 + j] = mu + eps[(size_t)n * 64 + j] * expf(0.5f * lv);
        local = (double)(1.f + lv - mu * mu - expf(lv));
    }
#pragma unroll
    for (int o = 16; o; o >>= 1) local += __shfl_xor_sync(0xffffffffu, local, o);
    if (lane == 0) sred[w] = local;
    __syncthreads();
    if (j == 0) {
        double tt = sred[0] + sred[1] + sred[2] + sred[3];
        atomicAdd(&accp[n & 63], tt);
    }
}

// ---------------- fused decoder gather + selfloop + bias + relu ----------------
__global__ __launch_bounds__(256) void gather_dec_kernel(
    const float* __restrict__ msc, const int* __restrict__ perm,
    const int* __restrict__ start, const float* __restrict__ dis,
    const float* __restrict__ bd, float* __restrict__ outp)
{
    __shared__ int sidx[4][64];
    int tid = threadIdx.x;
    int g = tid >> 6, j = tid & 63;
    int n = blockIdx.x * 4 + g;
    int s0 = start[n], s1 = start[n + 1];
    int deg = s1 - s0;
    int cnt = deg < 64 ? deg : 64;
    if (j < cnt) sidx[g][j] = perm[s0 + j];
    __syncthreads();
    float a0 = 0.f, a1 = 0.f, a2 = 0.f, a3 = 0.f;
    int k = 0;
    for (; k + 4 <= cnt; k += 4) {
        a0 += msc[(size_t)sidx[g][k + 0] * 64 + j];
        a1 += msc[(size_t)sidx[g][k + 1] * 64 + j];
        a2 += msc[(size_t)sidx[g][k + 2] * 64 + j];
        a3 += msc[(size_t)sidx[g][k + 3] * 64 + j];
    }
    for (; k < cnt; k++) a0 += msc[(size_t)sidx[g][k] * 64 + j];
    for (int k2 = 64; k2 < deg; k2++) a0 += msc[(size_t)perm[s0 + k2] * 64 + j];
    float v = (a0 + a1) + (a2 + a3) + msc[(size_t)n * 64 + j];
    v = v * dis[n] + bd[j];
    outp[(size_t)n * 64 + j] = fmaxf(v, 0.f);
}

// ---------------- fused edge decoder + BCE loss: tf32 mma.sync mainloop --------
__global__ __launch_bounds__(256) void edge_loss_kernel(
    const float* __restrict__ h, const float* __restrict__ A12,
    const float* __restrict__ Wa, const float* __restrict__ ba,
    const float* __restrict__ Wb, const float* __restrict__ bb,
    const float* __restrict__ tau,
    const int* __restrict__ pu, const int* __restrict__ pv,
    const int* __restrict__ nu, const int* __restrict__ nv,
    double* __restrict__ acc)
{
    extern __shared__ float sm[];
    float* sWB    = sm;                 // 8192
    float* sFA    = sWB + 8192;         // 8448
    float* sHU    = sFA + 8448;         // 4160
    float* sHV    = sHU + 4160;         // 4160
    float* sLogit = sHV + 4160;         // 64
    int* sU = (int*)(sLogit + 64);
    int* sV = sU + 64;
    uint32_t* uWB = (uint32_t*)sWB;
    uint32_t* uFA = (uint32_t*)sFA;

    int tid = threadIdx.x;
    int lane = tid & 31, wid = tid >> 5;
    int mt = wid & 3, nh = wid >> 2;

    const float* W34 = Wa + 128 * 64;
    for (int i = tid; i < 8192; i += 256) {
        int s  = i & 1;
        int ln = (i >> 1) & 31;
        int nt = (i >> 6) & 7;
        int kt = i >> 9;
        int kk = kt * 8 + (ln & 3) + 4 * s;
        int nn = nt * 8 + (ln >> 2);
        uWB[i] = f2tf32(W34[kk * 64 + nn]);
    }

    float tc = fmaxf(tau[0], 1e-4f);
    float invt = 1.0f / tc;
    float bbv = bb[0];
    float2 baR[4], wbR[4];
#pragma unroll
    for (int nt = 0; nt < 4; nt++) {
        int j0 = nh * 32 + nt * 8 + 2 * (lane & 3);
        baR[nt] = *(const float2*)&ba[j0];
        wbR[nt] = *(const float2*)&Wb[j0];
    }
    const float pw = (float)ENEG / (float)EP;
    double dsum = 0.0;

    int eg0 = mt * 16 + (lane >> 2);
    int eg1 = eg0 + 8;

    int ebld = tid & 63;
    int f0   = tid >> 6;
    int mtb  = ebld >> 4;
    int rb   = ebld & 15;
    int lf   = ((rb & 7) << 2) | (f0 & 3);
    int rhi  = rb >> 3;

    int nTiles = ETOT / 64;
    for (int tile = blockIdx.x; tile < nTiles; tile += gridDim.x) {
        __syncthreads();
        if (tid < 64) {
            int ge = tile * 64 + tid;
            int u, v;
            if (ge < EP) { u = pu[ge]; v = pv[ge]; }
            else         { u = nu[ge - EP]; v = nv[ge - EP]; }
            sU[tid] = u; sV[tid] = v; sLogit[tid] = 0.f;
        }
        __syncthreads();
#pragma unroll
        for (int ee = 0; ee < 8; ee++) {
            int e = wid * 8 + ee;
            int u = sU[e], v = sV[e];
            sHU[e * 65 + lane]      = h[(size_t)u * 64 + lane];
            sHU[e * 65 + 32 + lane] = h[(size_t)u * 64 + 32 + lane];
            sHV[e * 65 + lane]      = h[(size_t)v * 64 + lane];
            sHV[e * 65 + 32 + lane] = h[(size_t)v * 64 + 32 + lane];
        }
        __syncthreads();
#pragma unroll
        for (int p = 0; p < 16; p++) {
            int f = f0 + 4 * p;
            float hu = sHU[ebld * 65 + f], hv = sHV[ebld * 65 + f];
            uint32_t dfrag = f2tf32(fabsf(hu - hv));
            uint32_t mfrag = f2tf32(hu * hv);
            int kt = f >> 3;
            int slot = rhi | (((f >> 2) & 1) << 1);
            int base = ((mtb * 16 + kt) * 4 + slot) * 33 + lf;
            uFA[base] = dfrag;
            uFA[base + 1056] = mfrag;
        }
        __syncthreads();
        float a4[4][4];
#pragma unroll
        for (int i = 0; i < 4; i++) { a4[i][0] = a4[i][1] = a4[i][2] = a4[i][3] = 0.f; }
#pragma unroll 4
        for (int kt = 0; kt < 16; kt++) {
            int ab = (mt * 16 + kt) * 4 * 33 + lane;
            uint32_t A0 = uFA[ab], A1 = uFA[ab + 33], A2 = uFA[ab + 66], A3 = uFA[ab + 99];
#pragma unroll
            for (int nt = 0; nt < 4; nt++) {
                int bidx = ((kt * 8 + nh * 4 + nt) * 32 + lane) * 2;
                uint32_t B0 = uWB[bidx], B1 = uWB[bidx + 1];
                mma_tf32(a4[nt][0], a4[nt][1], a4[nt][2], a4[nt][3],
                         A0, A1, A2, A3, B0, B1);
            }
        }
        {
            int u0 = sU[eg0], v0 = sV[eg0], u1 = sU[eg1], v1 = sV[eg1];
            float p0 = 0.f, p1 = 0.f;
#pragma unroll
            for (int nt = 0; nt < 4; nt++) {
                int j0 = nh * 32 + nt * 8 + 2 * (lane & 3);
                float2 au0 = *(const float2*)&A12[(size_t)u0 * 128 + j0];
                float2 av0 = *(const float2*)&A12[(size_t)v0 * 128 + 64 + j0];
                float2 au1 = *(const float2*)&A12[(size_t)u1 * 128 + j0];
                float2 av1 = *(const float2*)&A12[(size_t)v1 * 128 + 64 + j0];
                float t0 = a4[nt][0] + au0.x + av0.x + baR[nt].x;
                float t1 = a4[nt][1] + au0.y + av0.y + baR[nt].y;
                float t2 = a4[nt][2] + au1.x + av1.x + baR[nt].x;
                float t3 = a4[nt][3] + au1.y + av1.y + baR[nt].y;
                p0 += fmaxf(t0, 0.f) * wbR[nt].x + fmaxf(t1, 0.f) * wbR[nt].y;
                p1 += fmaxf(t2, 0.f) * wbR[nt].x + fmaxf(t3, 0.f) * wbR[nt].y;
            }
            p0 += __shfl_xor_sync(0xffffffffu, p0, 1);
            p0 += __shfl_xor_sync(0xffffffffu, p0, 2);
            p1 += __shfl_xor_sync(0xffffffffu, p1, 1);
            p1 += __shfl_xor_sync(0xffffffffu, p1, 2);
            if ((lane & 3) == 0) {
                atomicAdd(&sLogit[eg0], p0);
                atomicAdd(&sLogit[eg1], p1);
            }
        }
        __syncthreads();
        if (tid < 64) {
            float l = (sLogit[tid] + bbv) * invt;
            int ge = tile * 64 + tid;
            float term;
            if (ge < EP) {
                float ls = fminf(l, 0.f) - log1pf(expf(-fabsf(l)));
                term = pw * ls;
            } else {
                float ls = fminf(-l, 0.f) - log1pf(expf(-fabsf(l)));
                term = ls;
            }
            dsum += (double)term;
        }
    }
#pragma unroll
    for (int o = 16; o; o >>= 1) dsum += __shfl_xor_sync(0xffffffffu, dsum, o);
    __shared__ double sredd[8];
    int lane2 = tid & 31, wid2 = tid >> 5;
    if (lane2 == 0) sredd[wid2] = dsum;
    __syncthreads();
    if (tid == 0) {
        double t = 0.0;
        for (int i = 0; i < 8; i++) t += sredd[i];
        atomicAdd(acc, t);
    }
}

__global__ void finalize_kernel(const double* __restrict__ acc,
                                const double* __restrict__ accp,
                                float* __restrict__ out, int n)
{
    double kls = 0.0;
    for (int i = 0; i < 64; i++) kls += accp[i];
    double recon = -acc[0] / (double)ETOT;
    double kl = -0.5 * kls / ((double)Nn * 64.0);
    if (n >= 3) {
        out[0] = (float)(recon + kl);
        out[1] = (float)recon;
        out[2] = (float)kl;
    } else {
        out[0] = (float)(recon + kl);
    }
}

// ---------------- launch ----------------
extern "C" void kernel_launch(void* const* d_in, const int* in_sizes, int n_in,
                              void* d_out, int out_size)
{
    const float* x   = (const float*)d_in[0];
    const float* eps = (const float*)d_in[1];
    const int* edge_index = (const int*)d_in[2];
    const int* pos_edge   = (const int*)d_in[3];
    const int* neg_edge   = (const int*)d_in[4];
    const float* W1  = (const float*)d_in[5];
    const float* b1  = (const float*)d_in[6];
    const float* g1  = (const float*)d_in[7];
    const float* bt1 = (const float*)d_in[8];
    const float* Wmu = (const float*)d_in[9];
    const float* bmu = (const float*)d_in[10];
    const float* Wlv = (const float*)d_in[11];
    const float* blv = (const float*)d_in[12];
    const float* Wd1 = (const float*)d_in[13];
    const float* bd1 = (const float*)d_in[14];
    const float* Wd2 = (const float*)d_in[15];
    const float* bd2 = (const float*)d_in[16];
    const float* Wa  = (const float*)d_in[17];
    const float* ba  = (const float*)d_in[18];
    const float* Wb  = (const float*)d_in[19];
    const float* bb  = (const float*)d_in[20];
    const float* tau = (const float*)d_in[21];

    float *p_m, *p_h1, *p_tmulv, *p_z, *p_md, *p_hd, *p_hd2, *p_A12, *p_dis;
    int *p_degE, *p_degD, *p_startE, *p_startD, *p_curE, *p_curD, *p_permE, *p_permD;
    double *p_acc, *p_accp;
    cudaGetSymbolAddress((void**)&p_m, g_m);
    cudaGetSymbolAddress((void**)&p_h1, g_h1);
    cudaGetSymbolAddress((void**)&p_tmulv, g_tmulv);
    cudaGetSymbolAddress((void**)&p_z, g_z);
    cudaGetSymbolAddress((void**)&p_md, g_md);
    cudaGetSymbolAddress((void**)&p_hd, g_hd);
    cudaGetSymbolAddress((void**)&p_hd2, g_hd2);
    cudaGetSymbolAddress((void**)&p_A12, g_A12);
    cudaGetSymbolAddress((void**)&p_dis, g_dis);
    cudaGetSymbolAddress((void**)&p_degE, g_degE);
    cudaGetSymbolAddress((void**)&p_degD, g_degD);
    cudaGetSymbolAddress((void**)&p_startE, g_startE);
    cudaGetSymbolAddress((void**)&p_startD, g_startD);
    cudaGetSymbolAddress((void**)&p_curE, g_curE);
    cudaGetSymbolAddress((void**)&p_curD, g_curD);
    cudaGetSymbolAddress((void**)&p_permE, g_permE);
    cudaGetSymbolAddress((void**)&p_permD, g_permD);
    cudaGetSymbolAddress((void**)&p_acc, g_acc);
    cudaGetSymbolAddress((void**)&p_accp, g_accp);

    const int* src = edge_index;
    const int* dst = edge_index + E2;
    const int* pu = pos_edge;
    const int* pv = pos_edge + EP;
    const int* nu = neg_edge;
    const int* nv = neg_edge + ENEG;

    int mby = (Nn + 63) / 64;   // 313

    // ---- CSR build ----
    zero_kernel<<<(Nn + 255) / 256, 256>>>(p_degE, p_degD, p_acc, p_accp);
    count_kernel<<<(E2 + 255) / 256, 256>>>(dst, pv, p_degE, p_degD);
    scan_kernel<<<2, 1024>>>(p_degE, p_startE, p_curE, p_degD, p_startD, p_curD, p_dis);
    fill_kernel<<<(E2 + 255) / 256, 256>>>(src, dst, pu, pv, p_curE, p_curD,
                                           p_permE, p_permD);

    // ---- encoder layer 1 (tf32 tensor GEMM) ----
    {
        dim3 g(4, mby);
        tgemm_kernel<<<g, 256>>>(x, W1, p_m, Nn, 256, 256, 256, 0, (const float*)0);
    }
    gather_ln_kernel<<<Nn, 256>>>(p_m, p_permE, p_startE, b1, g1, bt1, p_h1);

    // ---- mu / logvar ----
    {
        dim3 g(1, mby);
        tgemm_kernel<<<g, 256>>>(p_h1, Wmu, p_tmulv, Nn, 256, 64, 128, 0, (const float*)0);
        tgemm_kernel<<<g, 256>>>(p_h1, Wlv, p_tmulv, Nn, 256, 64, 128, 64, (const float*)0);
    }
    gather_zkl_kernel<<<Nn, 128>>>(p_tmulv, p_permE, p_startE, bmu, blv, eps,
                                   p_z, p_accp);

    // ---- decoder GCN pass 1 (dis-scaling fused) ----
    {
        dim3 g(1, mby);
        tgemm_kernel<<<g, 256>>>(p_z, Wd1, p_md, Nn, 64, 64, 64, 0, p_dis);
    }
    gather_dec_kernel<<<Nn / 4, 256>>>(p_md, p_permD, p_startD, p_dis, bd1, p_hd);

    // ---- decoder GCN pass 2 ----
    {
        dim3 g(1, mby);
        tgemm_kernel<<<g, 256>>>(p_hd, Wd2, p_md, Nn, 64, 64, 64, 0, p_dis);
    }
    gather_dec_kernel<<<Nn / 4, 256>>>(p_md, p_permD, p_startD, p_dis, bd2, p_hd2);

    // ---- per-node precompute [h@Wa1 | h@Wa2] ----
    {
        dim3 g(1, mby);
        tgemm_kernel<<<g, 256>>>(p_hd2, Wa, p_A12, Nn, 64, 64, 128, 0, (const float*)0);
        tgemm_kernel<<<g, 256>>>(p_hd2, Wa + 64 * 64, p_A12, Nn, 64, 64, 128, 64, (const float*)0);
    }

    // ---- fused edge decoder + loss (tf32 mma) ----
    {
        int smem = (8192 + 8448 + 4160 + 4160 + 64) * 4 + 128 * 4;   // 100608 B
        cudaFuncSetAttribute(edge_loss_kernel, cudaFuncAttributeMaxDynamicSharedMemorySize, smem);
        edge_loss_kernel<<<296, 256, smem>>>(p_hd2, p_A12, Wa, ba, Wb, bb, tau,
                                             pu, pv, nu, nv, p_acc);
    }

    finalize_kernel<<<1, 1>>>(p_acc, p_accp, (float*)d_out, out_size);

    (void)in_sizes; (void)n_in;
}

// round 10
// speedup vs baseline: 1.5806x; 1.1619x over previous
#include <cuda_runtime.h>
#include <math.h>
#include <stdint.h>

#define Nn    20000
#define HIDF  256
#define ZF    64
#define EP    120000
#define E2    240000
#define ENEG  600000
#define ETOT  720000

typedef unsigned long long ull;

// ---------------- scratch (static device globals; no allocation) ----------------
__device__ __align__(16) float g_m[Nn * HIDF];
__device__ __align__(16) float g_h1[Nn * HIDF];
__device__ __align__(16) float g_tmulv[Nn * 128];
__device__ __align__(16) float g_z[Nn * ZF];
__device__ __align__(16) float g_md[Nn * ZF];
__device__ __align__(16) float g_hd[Nn * ZF];
__device__ __align__(16) float g_hd2[Nn * ZF];
__device__ __align__(16) float g_A12[Nn * 128];
__device__ float g_dis[Nn];
__device__ __align__(16) int g_degE[Nn];
__device__ __align__(16) int g_degD[Nn];
__device__ int g_startE[Nn + 1];
__device__ int g_startD[Nn + 1];
__device__ int g_curE[Nn];
__device__ int g_curD[Nn];
__device__ int g_permE[E2];
__device__ int g_permD[EP];
__device__ double g_acc[2];
__device__ double g_accp[64];

__device__ __forceinline__ uint32_t f2tf32(float x)
{
    uint32_t r;
    asm("cvt.rna.tf32.f32 %0, %1;" : "=r"(r) : "f"(x));
    return r;
}

__device__ __forceinline__ void mma_tf32(float& c0, float& c1, float& c2, float& c3,
    uint32_t a0, uint32_t a1, uint32_t a2, uint32_t a3, uint32_t b0, uint32_t b1)
{
    asm("mma.sync.aligned.m16n8k8.row.col.f32.tf32.tf32.f32 "
        "{%0,%1,%2,%3}, {%4,%5,%6,%7}, {%8,%9}, {%0,%1,%2,%3};"
        : "+f"(c0), "+f"(c1), "+f"(c2), "+f"(c3)
        : "r"(a0), "r"(a1), "r"(a2), "r"(a3), "r"(b0), "r"(b1));
}

// ---------------- zero ----------------
__global__ __launch_bounds__(256) void zero_kernel(int* degE, int* degD,
                                                   double* acc, double* accp)
{
    int idx = blockIdx.x * blockDim.x + threadIdx.x;
    if (idx < Nn) { degE[idx] = 0; degD[idx] = 0; }
    if (idx < 64) accp[idx] = 0.0;
    if (idx < 2) acc[idx] = 0.0;
}

// ---------------- degree count ----------------
__global__ __launch_bounds__(256) void count_kernel(
    const int* __restrict__ dst, const int* __restrict__ pd,
    int* __restrict__ degE, int* __restrict__ degD)
{
    int idx = blockIdx.x * blockDim.x + threadIdx.x;
    if (idx < E2) atomicAdd(&degE[dst[idx]], 1);
    if (idx < EP) atomicAdd(&degD[pd[idx]], 1);
}

// ---------------- exclusive scan of degrees ----------------
__global__ __launch_bounds__(1024) void scan_kernel(
    const int* __restrict__ degE, int* startE, int* curE,
    const int* __restrict__ degD, int* startD, int* curD, float* dis)
{
    const int* deg = (blockIdx.x == 0) ? degE : degD;
    int* start     = (blockIdx.x == 0) ? startE : startD;
    int* cur       = (blockIdx.x == 0) ? curE : curD;
    int t = threadIdx.x;
    int base = t * 20;
    int local[20];
    int sum = 0;
#pragma unroll
    for (int i = 0; i < 20; i++) {
        int idx = base + i;
        int v = (idx < Nn) ? deg[idx] : 0;
        local[i] = sum;
        sum += v;
    }
    __shared__ int ps[1024];
    ps[t] = sum;
    __syncthreads();
    for (int off = 1; off < 1024; off <<= 1) {
        int v = (t >= off) ? ps[t - off] : 0;
        __syncthreads();
        ps[t] += v;
        __syncthreads();
    }
    int offset = (t > 0) ? ps[t - 1] : 0;
#pragma unroll
    for (int i = 0; i < 20; i++) {
        int idx = base + i;
        if (idx < Nn) {
            int s = offset + local[i];
            start[idx] = s;
            cur[idx] = s;
            if (blockIdx.x == 1) dis[idx] = rsqrtf((float)deg[idx] + 1.0f);
        }
    }
    if (t == 1023) start[Nn] = ps[1023];
}

// ---------------- CSR fill ----------------
__global__ __launch_bounds__(256) void fill_kernel(
    const int* __restrict__ src, const int* __restrict__ dst,
    const int* __restrict__ ps, const int* __restrict__ pd,
    int* __restrict__ curE, int* __restrict__ curD,
    int* __restrict__ permE, int* __restrict__ permD)
{
    int idx = blockIdx.x * blockDim.x + threadIdx.x;
    if (idx < E2) {
        int slot = atomicAdd(&curE[dst[idx]], 1);
        permE[slot] = src[idx];
    }
    if (idx < EP) {
        int slot = atomicAdd(&curD[pd[idx]], 1);
        permD[slot] = ps[idx];
    }
}

// ---------------- tf32 tensor-core GEMM ----------------
// If B2 != null: blockIdx.x selects weight B(0)/B2(1), n0=0, coff += blockIdx.x*64.
// Else: n0 = blockIdx.x*64 (normal N tiling).
__global__ __launch_bounds__(256) void tgemm_kernel(
    const float* __restrict__ A, const float* __restrict__ B,
    const float* __restrict__ B2, float* __restrict__ C,
    int M, int K, int bstride, int ldc, int coff, const float* __restrict__ rs)
{
    __shared__ uint32_t sA[2048];
    __shared__ uint32_t sB[2048];
    int tid = threadIdx.x;
    int lane = tid & 31, wid = tid >> 5;
    int mt = wid & 3, nh = wid >> 2;
    int m0 = blockIdx.y * 64;
    int n0, co;
    const float* Bp;
    if (B2) { Bp = blockIdx.x ? B2 : B; n0 = 0; co = coff + blockIdx.x * 64; }
    else    { Bp = B; n0 = blockIdx.x * 64; co = coff; }

    float c[4][4];
#pragma unroll
    for (int i = 0; i < 4; i++) { c[i][0] = c[i][1] = c[i][2] = c[i][3] = 0.f; }

    int arow = tid >> 2;
    int acb  = (tid & 3) * 8;
    int brow = tid >> 3;
    int bnb  = (tid & 7) * 8;

    for (int k0 = 0; k0 < K; k0 += 32) {
        int gm = m0 + arow;
#pragma unroll
        for (int q = 0; q < 2; q++) {
            float4 v = (gm < M)
                ? *(const float4*)(A + (size_t)gm * K + k0 + acb + q * 4)
                : make_float4(0.f, 0.f, 0.f, 0.f);
            float e[4] = {v.x, v.y, v.z, v.w};
#pragma unroll
            for (int t2 = 0; t2 < 4; t2++) {
                int kl = acb + q * 4 + t2;
                int amt = arow >> 4, akt = kl >> 3;
                int rr = arow & 15, cc = kl & 7;
                int ln = ((rr & 7) << 2) | (cc & 3);
                int rg = (rr >> 3) | (((cc >> 2) & 1) << 1);
                sA[((amt * 4 + akt) * 32 + ln) * 4 + rg] = f2tf32(e[t2]);
            }
        }
#pragma unroll
        for (int q = 0; q < 2; q++) {
            float4 v = *(const float4*)(Bp + (size_t)(k0 + brow) * bstride + n0 + bnb + q * 4);
            float e[4] = {v.x, v.y, v.z, v.w};
#pragma unroll
            for (int t2 = 0; t2 < 4; t2++) {
                int nl = bnb + q * 4 + t2;
                int bkt = brow >> 3, bnt = nl >> 3;
                int ln = ((nl & 7) << 2) | (brow & 3);
                int s  = (brow >> 2) & 1;
                sB[((bkt * 8 + bnt) * 32 + ln) * 2 + s] = f2tf32(e[t2]);
            }
        }
        __syncthreads();
#pragma unroll
        for (int kt = 0; kt < 4; kt++) {
            uint4 av = *(const uint4*)&sA[((mt * 4 + kt) * 32 + lane) * 4];
#pragma unroll
            for (int nt2 = 0; nt2 < 4; nt2++) {
                int nt = nh * 4 + nt2;
                uint2 bv = *(const uint2*)&sB[((kt * 8 + nt) * 32 + lane) * 2];
                mma_tf32(c[nt2][0], c[nt2][1], c[nt2][2], c[nt2][3],
                         av.x, av.y, av.z, av.w, bv.x, bv.y);
            }
        }
        __syncthreads();
    }
    int r0 = m0 + mt * 16 + (lane >> 2);
    int r1 = r0 + 8;
    float sc0 = (r0 < M && rs) ? rs[r0] : 1.f;
    float sc1 = (r1 < M && rs) ? rs[r1] : 1.f;
#pragma unroll
    for (int nt2 = 0; nt2 < 4; nt2++) {
        int j = n0 + nh * 32 + nt2 * 8 + (lane & 3) * 2;
        if (r0 < M)
            *(float2*)(C + (size_t)r0 * ldc + co + j) =
                make_float2(c[nt2][0] * sc0, c[nt2][1] * sc0);
        if (r1 < M)
            *(float2*)(C + (size_t)r1 * ldc + co + j) =
                make_float2(c[nt2][2] * sc1, c[nt2][3] * sc1);
    }
}

// ---------------- fused gather + bias + LayerNorm + relu ----------------
__global__ __launch_bounds__(256) void gather_ln_kernel(
    const float* __restrict__ m, const int* __restrict__ perm,
    const int* __restrict__ start, const float* __restrict__ b1,
    const float* __restrict__ g1, const float* __restrict__ bt1,
    float* __restrict__ h1)
{
    __shared__ int sidx[256];
    __shared__ float red[8];
    int n = blockIdx.x;
    int j = threadIdx.x;
    int lane = j & 31, w = j >> 5;
    int s0 = start[n], s1 = start[n + 1];
    int deg = s1 - s0;
    int cnt = deg < 256 ? deg : 256;
    if (j < cnt) sidx[j] = perm[s0 + j];
    __syncthreads();
    float a0 = 0.f, a1 = 0.f, a2 = 0.f, a3 = 0.f;
    int k = 0;
    for (; k + 4 <= cnt; k += 4) {
        a0 += m[(size_t)sidx[k + 0] * 256 + j];
        a1 += m[(size_t)sidx[k + 1] * 256 + j];
        a2 += m[(size_t)sidx[k + 2] * 256 + j];
        a3 += m[(size_t)sidx[k + 3] * 256 + j];
    }
    for (; k < cnt; k++) a0 += m[(size_t)sidx[k] * 256 + j];
    for (int k2 = 256; k2 < deg; k2++) a0 += m[(size_t)perm[s0 + k2] * 256 + j];
    float v = (a0 + a1) + (a2 + a3) + b1[j];
    float s = v;
#pragma unroll
    for (int o = 16; o; o >>= 1) s += __shfl_xor_sync(0xffffffffu, s, o);
    if (lane == 0) red[w] = s;
    __syncthreads();
    float tot = 0.f;
#pragma unroll
    for (int i = 0; i < 8; i++) tot += red[i];
    float mu = tot * (1.f / 256.f);
    __syncthreads();
    float d = v - mu;
    float q = d * d;
#pragma unroll
    for (int o = 16; o; o >>= 1) q += __shfl_xor_sync(0xffffffffu, q, o);
    if (lane == 0) red[w] = q;
    __syncthreads();
    float tq = 0.f;
#pragma unroll
    for (int i = 0; i < 8; i++) tq += red[i];
    float var = tq * (1.f / 256.f);
    float o = d * rsqrtf(var + 1e-5f) * g1[j] + bt1[j];
    h1[(size_t)n * 256 + j] = fmaxf(o, 0.f);
}

// ---------------- fused gather + z-reparam + KL ----------------
__global__ __launch_bounds__(128) void gather_zkl_kernel(
    const float* __restrict__ t, const int* __restrict__ perm,
    const int* __restrict__ start, const float* __restrict__ bmu,
    const float* __restrict__ blv, const float* __restrict__ eps,
    float* __restrict__ z, double* __restrict__ accp)
{
    __shared__ int sidx[128];
    __shared__ float row[128];
    __shared__ double sred[4];
    int n = blockIdx.x;
    int j = threadIdx.x;
    int lane = j & 31, w = j >> 5;
    int s0 = start[n], s1 = start[n + 1];
    int deg = s1 - s0;
    int cnt = deg < 128 ? deg : 128;
    if (j < cnt) sidx[j] = perm[s0 + j];
    __syncthreads();
    float a0 = 0.f, a1 = 0.f, a2 = 0.f, a3 = 0.f;
    int k = 0;
    for (; k + 4 <= cnt; k += 4) {
        a0 += t[(size_t)sidx[k + 0] * 128 + j];
        a1 += t[(size_t)sidx[k + 1] * 128 + j];
        a2 += t[(size_t)sidx[k + 2] * 128 + j];
        a3 += t[(size_t)sidx[k + 3] * 128 + j];
    }
    for (; k < cnt; k++) a0 += t[(size_t)sidx[k] * 128 + j];
    for (int k2 = 128; k2 < deg; k2++) a0 += t[(size_t)perm[s0 + k2] * 128 + j];
    row[j] = (a0 + a1) + (a2 + a3);
    __syncthreads();
    double local = 0.0;
    if (j < 64) {
        float mu = row[j] + bmu[j];
        float lv = row[j + 64] + blv[j];
        z[(size_t)n * 64 + j] = mu + eps[(size_t)n * 64 + j] * expf(0.5f * lv);
        local = (double)(1.f + lv - mu * mu - expf(lv));
    }
#pragma unroll
    for (int o = 16; o; o >>= 1) local += __shfl_xor_sync(0xffffffffu, local, o);
    if (lane == 0) sred[w] = local;
    __syncthreads();
    if (j == 0) {
        double tt = sred[0] + sred[1] + sred[2] + sred[3];
        atomicAdd(&accp[n & 63], tt);
    }
}

// ---------------- fused decoder gather + selfloop + bias + relu ----------------
__global__ __launch_bounds__(256) void gather_dec_kernel(
    const float* __restrict__ msc, const int* __restrict__ perm,
    const int* __restrict__ start, const float* __restrict__ dis,
    const float* __restrict__ bd, float* __restrict__ outp)
{
    __shared__ int sidx[4][64];
    int tid = threadIdx.x;
    int g = tid >> 6, j = tid & 63;
    int n = blockIdx.x * 4 + g;
    int s0 = start[n], s1 = start[n + 1];
    int deg = s1 - s0;
    int cnt = deg < 64 ? deg : 64;
    if (j < cnt) sidx[g][j] = perm[s0 + j];
    __syncthreads();
    float a0 = 0.f, a1 = 0.f, a2 = 0.f, a3 = 0.f;
    int k = 0;
    for (; k + 4 <= cnt; k += 4) {
        a0 += msc[(size_t)sidx[g][k + 0] * 64 + j];
        a1 += msc[(size_t)sidx[g][k + 1] * 64 + j];
        a2 += msc[(size_t)sidx[g][k + 2] * 64 + j];
        a3 += msc[(size_t)sidx[g][k + 3] * 64 + j];
    }
    for (; k < cnt; k++) a0 += msc[(size_t)sidx[g][k] * 64 + j];
    for (int k2 = 64; k2 < deg; k2++) a0 += msc[(size_t)perm[s0 + k2] * 64 + j];
    float v = (a0 + a1) + (a2 + a3) + msc[(size_t)n * 64 + j];
    v = v * dis[n] + bd[j];
    outp[(size_t)n * 64 + j] = fmaxf(v, 0.f);
}

// ---------------- fused edge decoder + BCE loss: pipelined tf32 mma ----------------
// 64-edge tiles; h-row gather for tile t+1 prefetched into registers during tile t's mma.
__global__ __launch_bounds__(256) void edge_loss_kernel(
    const float* __restrict__ h, const float* __restrict__ A12,
    const float* __restrict__ Wa, const float* __restrict__ ba,
    const float* __restrict__ Wb, const float* __restrict__ bb,
    const float* __restrict__ tau,
    const int* __restrict__ pu, const int* __restrict__ pv,
    const int* __restrict__ nu, const int* __restrict__ nv,
    double* __restrict__ acc)
{
    extern __shared__ float sm[];
    float* sWB    = sm;                 // 8192
    float* sFA    = sWB + 8192;         // 8448
    float* sHU    = sFA + 8448;         // 4160
    float* sHV    = sHU + 4160;         // 4160
    float* sLogit = sHV + 4160;         // 2 x 64
    int* sU = (int*)(sLogit + 128);     // 2 x 64
    int* sV = sU + 128;                 // 2 x 64
    uint32_t* uWB = (uint32_t*)sWB;
    uint32_t* uFA = (uint32_t*)sFA;

    int tid = threadIdx.x;
    int lane = tid & 31, wid = tid >> 5;
    int mt = wid & 3, nh = wid >> 2;

    const float* W34 = Wa + 128 * 64;
    for (int i = tid; i < 8192; i += 256) {
        int s  = i & 1;
        int ln = (i >> 1) & 31;
        int nt = (i >> 6) & 7;
        int kt = i >> 9;
        int kk = kt * 8 + (ln & 3) + 4 * s;
        int nn = nt * 8 + (ln >> 2);
        uWB[i] = f2tf32(W34[kk * 64 + nn]);
    }

    float tc = fmaxf(tau[0], 1e-4f);
    float invt = 1.0f / tc;
    float bbv = bb[0];
    float2 baR[4], wbR[4];
#pragma unroll
    for (int nt = 0; nt < 4; nt++) {
        int j0 = nh * 32 + nt * 8 + 2 * (lane & 3);
        baR[nt] = *(const float2*)&ba[j0];
        wbR[nt] = *(const float2*)&Wb[j0];
    }
    const float pw = (float)ENEG / (float)EP;
    double dsum = 0.0;

    int eg0 = mt * 16 + (lane >> 2);
    int eg1 = eg0 + 8;

    int ebld = tid & 63;
    int f0   = tid >> 6;
    int mtb  = ebld >> 4;
    int rb   = ebld & 15;
    int lf   = ((rb & 7) << 2) | (f0 & 3);
    int rhi  = rb >> 3;

    const int nTiles = ETOT / 64;
    const int stride = gridDim.x;

    // ---- prologue: indices + h prefetch for first tile ----
    float hR[32];
    if (tid < 64) {
        int ge = blockIdx.x * 64 + tid;
        int u, v;
        if (ge < EP) { u = pu[ge]; v = pv[ge]; }
        else         { u = nu[ge - EP]; v = nv[ge - EP]; }
        sU[tid] = u; sV[tid] = v;
    }
    __syncthreads();
#pragma unroll
    for (int ee = 0; ee < 8; ee++) {
        int e = wid * 8 + ee;
        int u = sU[e], v = sV[e];
        hR[ee * 4 + 0] = h[(size_t)u * 64 + lane];
        hR[ee * 4 + 1] = h[(size_t)u * 64 + 32 + lane];
        hR[ee * 4 + 2] = h[(size_t)v * 64 + lane];
        hR[ee * 4 + 3] = h[(size_t)v * 64 + 32 + lane];
    }

    int buf = 0;
    for (int tile = blockIdx.x; tile < nTiles; tile += stride) {
        int nb = buf ^ 1;
        // step 1: commit prefetched h to smem
#pragma unroll
        for (int ee = 0; ee < 8; ee++) {
            int e = wid * 8 + ee;
            sHU[e * 65 + lane]      = hR[ee * 4 + 0];
            sHU[e * 65 + 32 + lane] = hR[ee * 4 + 1];
            sHV[e * 65 + lane]      = hR[ee * 4 + 2];
            sHV[e * 65 + 32 + lane] = hR[ee * 4 + 3];
        }
        // step 2: indices for next tile + logit reset for current
        if (tid < 64) {
            int ntile = tile + stride;
            int gt = (ntile < nTiles) ? ntile : tile;
            int ge = gt * 64 + tid;
            int u, v;
            if (ge < EP) { u = pu[ge]; v = pv[ge]; }
            else         { u = nu[ge - EP]; v = nv[ge - EP]; }
            sU[nb * 64 + tid] = u; sV[nb * 64 + tid] = v;
            sLogit[buf * 64 + tid] = 0.f;
        }
        __syncthreads();  // A
        // phase B: build A fragments (tf32) from sHU/sHV
#pragma unroll
        for (int p = 0; p < 16; p++) {
            int f = f0 + 4 * p;
            float hu = sHU[ebld * 65 + f], hv = sHV[ebld * 65 + f];
            uint32_t dfrag = f2tf32(fabsf(hu - hv));
            uint32_t mfrag = f2tf32(hu * hv);
            int kt = f >> 3;
            int slot = rhi | (((f >> 2) & 1) << 1);
            int base = ((mtb * 16 + kt) * 4 + slot) * 33 + lf;
            uFA[base] = dfrag;
            uFA[base + 1056] = mfrag;
        }
        __syncthreads();  // B
        // prefetch next tile's h rows into registers (overlaps with mma below)
#pragma unroll
        for (int ee = 0; ee < 8; ee++) {
            int e = wid * 8 + ee;
            int u = sU[nb * 64 + e], v = sV[nb * 64 + e];
            hR[ee * 4 + 0] = h[(size_t)u * 64 + lane];
            hR[ee * 4 + 1] = h[(size_t)u * 64 + 32 + lane];
            hR[ee * 4 + 2] = h[(size_t)v * 64 + lane];
            hR[ee * 4 + 3] = h[(size_t)v * 64 + 32 + lane];
        }
        // mma mainloop
        float a4[4][4];
#pragma unroll
        for (int i = 0; i < 4; i++) { a4[i][0] = a4[i][1] = a4[i][2] = a4[i][3] = 0.f; }
#pragma unroll 4
        for (int kt = 0; kt < 16; kt++) {
            int ab = (mt * 16 + kt) * 4 * 33 + lane;
            uint32_t A0 = uFA[ab], A1 = uFA[ab + 33], A2 = uFA[ab + 66], A3 = uFA[ab + 99];
#pragma unroll
            for (int nt = 0; nt < 4; nt++) {
                int bidx = ((kt * 8 + nh * 4 + nt) * 32 + lane) * 2;
                uint32_t B0 = uWB[bidx], B1 = uWB[bidx + 1];
                mma_tf32(a4[nt][0], a4[nt][1], a4[nt][2], a4[nt][3],
                         A0, A1, A2, A3, B0, B1);
            }
        }
        // epilogue
        {
            int u0 = sU[buf * 64 + eg0], v0 = sV[buf * 64 + eg0];
            int u1 = sU[buf * 64 + eg1], v1 = sV[buf * 64 + eg1];
            float p0 = 0.f, p1 = 0.f;
#pragma unroll
            for (int nt = 0; nt < 4; nt++) {
                int j0 = nh * 32 + nt * 8 + 2 * (lane & 3);
                float2 au0 = *(const float2*)&A12[(size_t)u0 * 128 + j0];
                float2 av0 = *(const float2*)&A12[(size_t)v0 * 128 + 64 + j0];
                float2 au1 = *(const float2*)&A12[(size_t)u1 * 128 + j0];
                float2 av1 = *(const float2*)&A12[(size_t)v1 * 128 + 64 + j0];
                float t0 = a4[nt][0] + au0.x + av0.x + baR[nt].x;
                float t1 = a4[nt][1] + au0.y + av0.y + baR[nt].y;
                float t2 = a4[nt][2] + au1.x + av1.x + baR[nt].x;
                float t3 = a4[nt][3] + au1.y + av1.y + baR[nt].y;
                p0 += fmaxf(t0, 0.f) * wbR[nt].x + fmaxf(t1, 0.f) * wbR[nt].y;
                p1 += fmaxf(t2, 0.f) * wbR[nt].x + fmaxf(t3, 0.f) * wbR[nt].y;
            }
            p0 += __shfl_xor_sync(0xffffffffu, p0, 1);
            p0 += __shfl_xor_sync(0xffffffffu, p0, 2);
            p1 += __shfl_xor_sync(0xffffffffu, p1, 1);
            p1 += __shfl_xor_sync(0xffffffffu, p1, 2);
            if ((lane & 3) == 0) {
                atomicAdd(&sLogit[buf * 64 + eg0], p0);
                atomicAdd(&sLogit[buf * 64 + eg1], p1);
            }
        }
        __syncthreads();  // C
        if (tid < 64) {
            float l = (sLogit[buf * 64 + tid] + bbv) * invt;
            int ge = tile * 64 + tid;
            float term;
            if (ge < EP) {
                float ls = fminf(l, 0.f) - log1pf(expf(-fabsf(l)));
                term = pw * ls;
            } else {
                float ls = fminf(-l, 0.f) - log1pf(expf(-fabsf(l)));
                term = ls;
            }
            dsum += (double)term;
        }
        buf = nb;
    }
#pragma unroll
    for (int o = 16; o; o >>= 1) dsum += __shfl_xor_sync(0xffffffffu, dsum, o);
    __shared__ double sredd[8];
    if (lane == 0) sredd[wid] = dsum;
    __syncthreads();
    if (tid == 0) {
        double t = 0.0;
        for (int i = 0; i < 8; i++) t += sredd[i];
        atomicAdd(acc, t);
    }
}

__global__ void finalize_kernel(const double* __restrict__ acc,
                                const double* __restrict__ accp,
                                float* __restrict__ out, int n)
{
    double kls = 0.0;
    for (int i = 0; i < 64; i++) kls += accp[i];
    double recon = -acc[0] / (double)ETOT;
    double kl = -0.5 * kls / ((double)Nn * 64.0);
    if (n >= 3) {
        out[0] = (float)(recon + kl);
        out[1] = (float)recon;
        out[2] = (float)kl;
    } else {
        out[0] = (float)(recon + kl);
    }
}

// ---------------- launch ----------------
extern "C" void kernel_launch(void* const* d_in, const int* in_sizes, int n_in,
                              void* d_out, int out_size)
{
    const float* x   = (const float*)d_in[0];
    const float* eps = (const float*)d_in[1];
    const int* edge_index = (const int*)d_in[2];
    const int* pos_edge   = (const int*)d_in[3];
    const int* neg_edge   = (const int*)d_in[4];
    const float* W1  = (const float*)d_in[5];
    const float* b1  = (const float*)d_in[6];
    const float* g1  = (const float*)d_in[7];
    const float* bt1 = (const float*)d_in[8];
    const float* Wmu = (const float*)d_in[9];
    const float* bmu = (const float*)d_in[10];
    const float* Wlv = (const float*)d_in[11];
    const float* blv = (const float*)d_in[12];
    const float* Wd1 = (const float*)d_in[13];
    const float* bd1 = (const float*)d_in[14];
    const float* Wd2 = (const float*)d_in[15];
    const float* bd2 = (const float*)d_in[16];
    const float* Wa  = (const float*)d_in[17];
    const float* ba  = (const float*)d_in[18];
    const float* Wb  = (const float*)d_in[19];
    const float* bb  = (const float*)d_in[20];
    const float* tau = (const float*)d_in[21];

    float *p_m, *p_h1, *p_tmulv, *p_z, *p_md, *p_hd, *p_hd2, *p_A12, *p_dis;
    int *p_degE, *p_degD, *p_startE, *p_startD, *p_curE, *p_curD, *p_permE, *p_permD;
    double *p_acc, *p_accp;
    cudaGetSymbolAddress((void**)&p_m, g_m);
    cudaGetSymbolAddress((void**)&p_h1, g_h1);
    cudaGetSymbolAddress((void**)&p_tmulv, g_tmulv);
    cudaGetSymbolAddress((void**)&p_z, g_z);
    cudaGetSymbolAddress((void**)&p_md, g_md);
    cudaGetSymbolAddress((void**)&p_hd, g_hd);
    cudaGetSymbolAddress((void**)&p_hd2, g_hd2);
    cudaGetSymbolAddress((void**)&p_A12, g_A12);
    cudaGetSymbolAddress((void**)&p_dis, g_dis);
    cudaGetSymbolAddress((void**)&p_degE, g_degE);
    cudaGetSymbolAddress((void**)&p_degD, g_degD);
    cudaGetSymbolAddress((void**)&p_startE, g_startE);
    cudaGetSymbolAddress((void**)&p_startD, g_startD);
    cudaGetSymbolAddress((void**)&p_curE, g_curE);
    cudaGetSymbolAddress((void**)&p_curD, g_curD);
    cudaGetSymbolAddress((void**)&p_permE, g_permE);
    cudaGetSymbolAddress((void**)&p_permD, g_permD);
    cudaGetSymbolAddress((void**)&p_acc, g_acc);
    cudaGetSymbolAddress((void**)&p_accp, g_accp);

    const int* src = edge_index;
    const int* dst = edge_index + E2;
    const int* pu = pos_edge;
    const int* pv = pos_edge + EP;
    const int* nu = neg_edge;
    const int* nv = neg_edge + ENEG;

    int mby = (Nn + 63) / 64;   // 313

    // ---- CSR build ----
    zero_kernel<<<(Nn + 255) / 256, 256>>>(p_degE, p_degD, p_acc, p_accp);
    count_kernel<<<(E2 + 255) / 256, 256>>>(dst, pv, p_degE, p_degD);
    scan_kernel<<<2, 1024>>>(p_degE, p_startE, p_curE, p_degD, p_startD, p_curD, p_dis);
    fill_kernel<<<(E2 + 255) / 256, 256>>>(src, dst, pu, pv, p_curE, p_curD,
                                           p_permE, p_permD);

    // ---- encoder layer 1 ----
    {
        dim3 g(4, mby);
        tgemm_kernel<<<g, 256>>>(x, W1, (const float*)0, p_m, Nn, 256, 256, 256, 0,
                                 (const float*)0);
    }
    gather_ln_kernel<<<Nn, 256>>>(p_m, p_permE, p_startE, b1, g1, bt1, p_h1);

    // ---- mu / logvar (one fused launch; grid.x selects weight) ----
    {
        dim3 g(2, mby);
        tgemm_kernel<<<g, 256>>>(p_h1, Wmu, Wlv, p_tmulv, Nn, 256, 64, 128, 0,
                                 (const float*)0);
    }
    gather_zkl_kernel<<<Nn, 128>>>(p_tmulv, p_permE, p_startE, bmu, blv, eps,
                                   p_z, p_accp);

    // ---- decoder GCN pass 1 ----
    {
        dim3 g(1, mby);
        tgemm_kernel<<<g, 256>>>(p_z, Wd1, (const float*)0, p_md, Nn, 64, 64, 64, 0, p_dis);
    }
    gather_dec_kernel<<<Nn / 4, 256>>>(p_md, p_permD, p_startD, p_dis, bd1, p_hd);

    // ---- decoder GCN pass 2 ----
    {
        dim3 g(1, mby);
        tgemm_kernel<<<g, 256>>>(p_hd, Wd2, (const float*)0, p_md, Nn, 64, 64, 64, 0, p_dis);
    }
    gather_dec_kernel<<<Nn / 4, 256>>>(p_md, p_permD, p_startD, p_dis, bd2, p_hd2);

    // ---- per-node precompute [h@Wa1 | h@Wa2] (one fused launch) ----
    {
        dim3 g(2, mby);
        tgemm_kernel<<<g, 256>>>(p_hd2, Wa, Wa + 64 * 64, p_A12, Nn, 64, 64, 128, 0,
                                 (const float*)0);
    }

    // ---- fused edge decoder + loss (pipelined tf32 mma) ----
    {
        int smem = (8192 + 8448 + 4160 + 4160 + 128) * 4 + 256 * 4;   // 101376 B
        cudaFuncSetAttribute(edge_loss_kernel, cudaFuncAttributeMaxDynamicSharedMemorySize, smem);
        edge_loss_kernel<<<296, 256, smem>>>(p_hd2, p_A12, Wa, ba, Wb, bb, tau,
                                             pu, pv, nu, nv, p_acc);
    }

    finalize_kernel<<<1, 1>>>(p_acc, p_accp, (float*)d_out, out_size);

    (void)in_sizes; (void)n_in;
}

// round 11
// speedup vs baseline: 1.8642x; 1.1794x over previous
#include <cuda_runtime.h>
#include <math.h>
#include <stdint.h>

#define Nn    20000
#define HIDF  256
#define ZF    64
#define EP    120000
#define E2    240000
#define ENEG  600000
#define ETOT  720000

typedef unsigned long long ull;

// ---------------- scratch (static device globals; no allocation) ----------------
__device__ __align__(16) float g_m[Nn * HIDF];
__device__ __align__(16) float g_h1[Nn * HIDF];
__device__ __align__(16) float g_tmulv[Nn * 128];
__device__ __align__(16) float g_z[Nn * ZF];
__device__ __align__(16) float g_md[Nn * ZF];
__device__ __align__(16) float g_hd[Nn * ZF];
__device__ __align__(16) float g_hd2[Nn * ZF];
__device__ __align__(16) float g_A12[Nn * 128];
__device__ float g_dis[Nn];
__device__ __align__(16) int g_degE[Nn];
__device__ __align__(16) int g_degD[Nn];
__device__ int g_startE[Nn + 1];
__device__ int g_startD[Nn + 1];
__device__ int g_curE[Nn];
__device__ int g_curD[Nn];
__device__ int g_permE[E2];
__device__ int g_permD[EP];
__device__ double g_acc[2];
__device__ double g_accp[64];

__device__ __forceinline__ uint32_t f2tf32(float x)
{
    uint32_t r;
    asm("cvt.rna.tf32.f32 %0, %1;" : "=r"(r) : "f"(x));
    return r;
}

__device__ __forceinline__ void mma_tf32(float& c0, float& c1, float& c2, float& c3,
    uint32_t a0, uint32_t a1, uint32_t a2, uint32_t a3, uint32_t b0, uint32_t b1)
{
    asm("mma.sync.aligned.m16n8k8.row.col.f32.tf32.tf32.f32 "
        "{%0,%1,%2,%3}, {%4,%5,%6,%7}, {%8,%9}, {%0,%1,%2,%3};"
        : "+f"(c0), "+f"(c1), "+f"(c2), "+f"(c3)
        : "r"(a0), "r"(a1), "r"(a2), "r"(a3), "r"(b0), "r"(b1));
}

// ---------------- zero ----------------
__global__ __launch_bounds__(256) void zero_kernel(int* degE, int* degD,
                                                   double* acc, double* accp)
{
    int idx = blockIdx.x * blockDim.x + threadIdx.x;
    if (idx < Nn) { degE[idx] = 0; degD[idx] = 0; }
    if (idx < 64) accp[idx] = 0.0;
    if (idx < 2) acc[idx] = 0.0;
}

// ---------------- degree count ----------------
__global__ __launch_bounds__(256) void count_kernel(
    const int* __restrict__ dst, const int* __restrict__ pd,
    int* __restrict__ degE, int* __restrict__ degD)
{
    int idx = blockIdx.x * blockDim.x + threadIdx.x;
    if (idx < E2) atomicAdd(&degE[dst[idx]], 1);
    if (idx < EP) atomicAdd(&degD[pd[idx]], 1);
}

// ---------------- exclusive scan of degrees ----------------
__global__ __launch_bounds__(1024) void scan_kernel(
    const int* __restrict__ degE, int* startE, int* curE,
    const int* __restrict__ degD, int* startD, int* curD, float* dis)
{
    const int* deg = (blockIdx.x == 0) ? degE : degD;
    int* start     = (blockIdx.x == 0) ? startE : startD;
    int* cur       = (blockIdx.x == 0) ? curE : curD;
    int t = threadIdx.x;
    int base = t * 20;
    int local[20];
    int sum = 0;
#pragma unroll
    for (int i = 0; i < 20; i++) {
        int idx = base + i;
        int v = (idx < Nn) ? deg[idx] : 0;
        local[i] = sum;
        sum += v;
    }
    __shared__ int ps[1024];
    ps[t] = sum;
    __syncthreads();
    for (int off = 1; off < 1024; off <<= 1) {
        int v = (t >= off) ? ps[t - off] : 0;
        __syncthreads();
        ps[t] += v;
        __syncthreads();
    }
    int offset = (t > 0) ? ps[t - 1] : 0;
#pragma unroll
    for (int i = 0; i < 20; i++) {
        int idx = base + i;
        if (idx < Nn) {
            int s = offset + local[i];
            start[idx] = s;
            cur[idx] = s;
            if (blockIdx.x == 1) dis[idx] = rsqrtf((float)deg[idx] + 1.0f);
        }
    }
    if (t == 1023) start[Nn] = ps[1023];
}

// ---------------- CSR fill ----------------
__global__ __launch_bounds__(256) void fill_kernel(
    const int* __restrict__ src, const int* __restrict__ dst,
    const int* __restrict__ ps, const int* __restrict__ pd,
    int* __restrict__ curE, int* __restrict__ curD,
    int* __restrict__ permE, int* __restrict__ permD)
{
    int idx = blockIdx.x * blockDim.x + threadIdx.x;
    if (idx < E2) {
        int slot = atomicAdd(&curE[dst[idx]], 1);
        permE[slot] = src[idx];
    }
    if (idx < EP) {
        int slot = atomicAdd(&curD[pd[idx]], 1);
        permD[slot] = ps[idx];
    }
}

// ---------------- tf32 tensor-core GEMM (plain-tile smem, padded strides) --------
// sA: [64][36] (pad 36 -> fragment LDS bank = (4r+c)%32, conflict-free)
// sB: [32][72] (pad 72 -> fragment LDS bank = (8k+n)%32, conflict-free)
// If B2 != null: blockIdx.x selects weight B(0)/B2(1), n0=0, coff += blockIdx.x*64.
__global__ __launch_bounds__(256) void tgemm_kernel(
    const float* __restrict__ A, const float* __restrict__ B,
    const float* __restrict__ B2, float* __restrict__ C,
    int M, int K, int bstride, int ldc, int coff, const float* __restrict__ rs)
{
    __shared__ uint32_t sA[64 * 36];
    __shared__ uint32_t sB[32 * 72];
    int tid = threadIdx.x;
    int lane = tid & 31, wid = tid >> 5;
    int mt = wid & 3, nh = wid >> 2;
    int m0 = blockIdx.y * 64;
    int n0, co;
    const float* Bp;
    if (B2) { Bp = blockIdx.x ? B2 : B; n0 = 0; co = coff + blockIdx.x * 64; }
    else    { Bp = B; n0 = blockIdx.x * 64; co = coff; }

    float c[4][4];
#pragma unroll
    for (int i = 0; i < 4; i++) { c[i][0] = c[i][1] = c[i][2] = c[i][3] = 0.f; }

    int arow = tid >> 2;            // 0..63
    int acb  = (tid & 3) * 8;       // 0,8,16,24
    int brow = tid >> 3;            // 0..31
    int bnb  = (tid & 7) * 8;       // 0..56

    int fr = lane >> 2;             // fragment row within 8
    int fc = lane & 3;              // fragment col within 4

    for (int k0 = 0; k0 < K; k0 += 32) {
        int gm = m0 + arow;
#pragma unroll
        for (int q = 0; q < 2; q++) {
            float4 v = (gm < M)
                ? *(const float4*)(A + (size_t)gm * K + k0 + acb + q * 4)
                : make_float4(0.f, 0.f, 0.f, 0.f);
            uint4 u;
            u.x = f2tf32(v.x); u.y = f2tf32(v.y); u.z = f2tf32(v.z); u.w = f2tf32(v.w);
            *(uint4*)&sA[arow * 36 + acb + q * 4] = u;
        }
#pragma unroll
        for (int q = 0; q < 2; q++) {
            float4 v = *(const float4*)(Bp + (size_t)(k0 + brow) * bstride + n0 + bnb + q * 4);
            uint4 u;
            u.x = f2tf32(v.x); u.y = f2tf32(v.y); u.z = f2tf32(v.z); u.w = f2tf32(v.w);
            *(uint4*)&sB[brow * 72 + bnb + q * 4] = u;
        }
        __syncthreads();
#pragma unroll
        for (int kt = 0; kt < 4; kt++) {
            int ra = (mt * 16 + fr) * 36 + kt * 8 + fc;
            uint32_t A0 = sA[ra];
            uint32_t A1 = sA[ra + 8 * 36];
            uint32_t A2 = sA[ra + 4];
            uint32_t A3 = sA[ra + 8 * 36 + 4];
#pragma unroll
            for (int nt2 = 0; nt2 < 4; nt2++) {
                int nt = nh * 4 + nt2;
                int rb = (kt * 8 + fc) * 72 + nt * 8 + fr;
                uint32_t B0 = sB[rb];
                uint32_t B1 = sB[rb + 4 * 72];
                mma_tf32(c[nt2][0], c[nt2][1], c[nt2][2], c[nt2][3],
                         A0, A1, A2, A3, B0, B1);
            }
        }
        __syncthreads();
    }
    int r0 = m0 + mt * 16 + fr;
    int r1 = r0 + 8;
    float sc0 = (r0 < M && rs) ? rs[r0] : 1.f;
    float sc1 = (r1 < M && rs) ? rs[r1] : 1.f;
#pragma unroll
    for (int nt2 = 0; nt2 < 4; nt2++) {
        int j = n0 + nh * 32 + nt2 * 8 + fc * 2;
        if (r0 < M)
            *(float2*)(C + (size_t)r0 * ldc + co + j) =
                make_float2(c[nt2][0] * sc0, c[nt2][1] * sc0);
        if (r1 < M)
            *(float2*)(C + (size_t)r1 * ldc + co + j) =
                make_float2(c[nt2][2] * sc1, c[nt2][3] * sc1);
    }
}

// ---------------- fused gather + bias + LayerNorm + relu ----------------
__global__ __launch_bounds__(256) void gather_ln_kernel(
    const float* __restrict__ m, const int* __restrict__ perm,
    const int* __restrict__ start, const float* __restrict__ b1,
    const float* __restrict__ g1, const float* __restrict__ bt1,
    float* __restrict__ h1)
{
    __shared__ int sidx[256];
    __shared__ float red[8];
    int n = blockIdx.x;
    int j = threadIdx.x;
    int lane = j & 31, w = j >> 5;
    int s0 = start[n], s1 = start[n + 1];
    int deg = s1 - s0;
    int cnt = deg < 256 ? deg : 256;
    if (j < cnt) sidx[j] = perm[s0 + j];
    __syncthreads();
    float a0 = 0.f, a1 = 0.f, a2 = 0.f, a3 = 0.f;
    int k = 0;
    for (; k + 4 <= cnt; k += 4) {
        a0 += m[(size_t)sidx[k + 0] * 256 + j];
        a1 += m[(size_t)sidx[k + 1] * 256 + j];
        a2 += m[(size_t)sidx[k + 2] * 256 + j];
        a3 += m[(size_t)sidx[k + 3] * 256 + j];
    }
    for (; k < cnt; k++) a0 += m[(size_t)sidx[k] * 256 + j];
    for (int k2 = 256; k2 < deg; k2++) a0 += m[(size_t)perm[s0 + k2] * 256 + j];
    float v = (a0 + a1) + (a2 + a3) + b1[j];
    float s = v;
#pragma unroll
    for (int o = 16; o; o >>= 1) s += __shfl_xor_sync(0xffffffffu, s, o);
    if (lane == 0) red[w] = s;
    __syncthreads();
    float tot = 0.f;
#pragma unroll
    for (int i = 0; i < 8; i++) tot += red[i];
    float mu = tot * (1.f / 256.f);
    __syncthreads();
    float d = v - mu;
    float q = d * d;
#pragma unroll
    for (int o = 16; o; o >>= 1) q += __shfl_xor_sync(0xffffffffu, q, o);
    if (lane == 0) red[w] = q;
    __syncthreads();
    float tq = 0.f;
#pragma unroll
    for (int i = 0; i < 8; i++) tq += red[i];
    float var = tq * (1.f / 256.f);
    float o = d * rsqrtf(var + 1e-5f) * g1[j] + bt1[j];
    h1[(size_t)n * 256 + j] = fmaxf(o, 0.f);
}

// ---------------- fused gather + z-reparam + KL ----------------
__global__ __launch_bounds__(128) void gather_zkl_kernel(
    const float* __restrict__ t, const int* __restrict__ perm,
    const int* __restrict__ start, const float* __restrict__ bmu,
    const float* __restrict__ blv, const float* __restrict__ eps,
    float* __restrict__ z, double* __restrict__ accp)
{
    __shared__ int sidx[128];
    __shared__ float row[128];
    __shared__ double sred[4];
    int n = blockIdx.x;
    int j = threadIdx.x;
    int lane = j & 31, w = j >> 5;
    int s0 = start[n], s1 = start[n + 1];
    int deg = s1 - s0;
    int cnt = deg < 128 ? deg : 128;
    if (j < cnt) sidx[j] = perm[s0 + j];
    __syncthreads();
    float a0 = 0.f, a1 = 0.f, a2 = 0.f, a3 = 0.f;
    int k = 0;
    for (; k + 4 <= cnt; k += 4) {
        a0 += t[(size_t)sidx[k + 0] * 128 + j];
        a1 += t[(size_t)sidx[k + 1] * 128 + j];
        a2 += t[(size_t)sidx[k + 2] * 128 + j];
        a3 += t[(size_t)sidx[k + 3] * 128 + j];
    }
    for (; k < cnt; k++) a0 += t[(size_t)sidx[k] * 128 + j];
    for (int k2 = 128; k2 < deg; k2++) a0 += t[(size_t)perm[s0 + k2] * 128 + j];
    row[j] = (a0 + a1) + (a2 + a3);
    __syncthreads();
    double local = 0.0;
    if (j < 64) {
        float mu = row[j] + bmu[j];
        float lv = row[j + 64] + blv[j];
        z[(size_t)n * 64 + j] = mu + eps[(size_t)n * 64 + j] * expf(0.5f * lv);
        local = (double)(1.f + lv - mu * mu - expf(lv));
    }
#pragma unroll
    for (int o = 16; o; o >>= 1) local += __shfl_xor_sync(0xffffffffu, local, o);
    if (lane == 0) sred[w] = local;
    __syncthreads();
    if (j == 0) {
        double tt = sred[0] + sred[1] + sred[2] + sred[3];
        atomicAdd(&accp[n & 63], tt);
    }
}

// ---------------- fused decoder gather + selfloop + bias + relu ----------------
__global__ __launch_bounds__(256) void gather_dec_kernel(
    const float* __restrict__ msc, const int* __restrict__ perm,
    const int* __restrict__ start, const float* __restrict__ dis,
    const float* __restrict__ bd, float* __restrict__ outp)
{
    __shared__ int sidx[4][64];
    int tid = threadIdx.x;
    int g = tid >> 6, j = tid & 63;
    int n = blockIdx.x * 4 + g;
    int s0 = start[n], s1 = start[n + 1];
    int deg = s1 - s0;
    int cnt = deg < 64 ? deg : 64;
    if (j < cnt) sidx[g][j] = perm[s0 + j];
    __syncthreads();
    float a0 = 0.f, a1 = 0.f, a2 = 0.f, a3 = 0.f;
    int k = 0;
    for (; k + 4 <= cnt; k += 4) {
        a0 += msc[(size_t)sidx[g][k + 0] * 64 + j];
        a1 += msc[(size_t)sidx[g][k + 1] * 64 + j];
        a2 += msc[(size_t)sidx[g][k + 2] * 64 + j];
        a3 += msc[(size_t)sidx[g][k + 3] * 64 + j];
    }
    for (; k < cnt; k++) a0 += msc[(size_t)sidx[g][k] * 64 + j];
    for (int k2 = 64; k2 < deg; k2++) a0 += msc[(size_t)perm[s0 + k2] * 64 + j];
    float v = (a0 + a1) + (a2 + a3) + msc[(size_t)n * 64 + j];
    v = v * dis[n] + bd[j];
    outp[(size_t)n * 64 + j] = fmaxf(v, 0.f);
}

// ---------------- fused edge decoder + BCE loss: pipelined tf32 mma ----------------
// 64-edge tiles; next tile's h rows AND current tile's A12 rows prefetched into
// registers so their latency hides under the fragment build + mma phases.
__global__ __launch_bounds__(256, 2) void edge_loss_kernel(
    const float* __restrict__ h, const float* __restrict__ A12,
    const float* __restrict__ Wa, const float* __restrict__ ba,
    const float* __restrict__ Wb, const float* __restrict__ bb,
    const float* __restrict__ tau,
    const int* __restrict__ pu, const int* __restrict__ pv,
    const int* __restrict__ nu, const int* __restrict__ nv,
    double* __restrict__ acc)
{
    extern __shared__ float sm[];
    float* sWB    = sm;                 // 8192
    float* sFA    = sWB + 8192;         // 8448
    float* sHU    = sFA + 8448;         // 4160
    float* sHV    = sHU + 4160;         // 4160
    float* sLogit = sHV + 4160;         // 2 x 64
    int* sU = (int*)(sLogit + 128);     // 2 x 64
    int* sV = sU + 128;                 // 2 x 64
    uint32_t* uWB = (uint32_t*)sWB;
    uint32_t* uFA = (uint32_t*)sFA;

    int tid = threadIdx.x;
    int lane = tid & 31, wid = tid >> 5;
    int mt = wid & 3, nh = wid >> 2;

    const float* W34 = Wa + 128 * 64;
    for (int i = tid; i < 8192; i += 256) {
        int s  = i & 1;
        int ln = (i >> 1) & 31;
        int nt = (i >> 6) & 7;
        int kt = i >> 9;
        int kk = kt * 8 + (ln & 3) + 4 * s;
        int nn = nt * 8 + (ln >> 2);
        uWB[i] = f2tf32(W34[kk * 64 + nn]);
    }

    float tc = fmaxf(tau[0], 1e-4f);
    float invt = 1.0f / tc;
    float bbv = bb[0];
    float2 baR[4], wbR[4];
#pragma unroll
    for (int nt = 0; nt < 4; nt++) {
        int j0 = nh * 32 + nt * 8 + 2 * (lane & 3);
        baR[nt] = *(const float2*)&ba[j0];
        wbR[nt] = *(const float2*)&Wb[j0];
    }
    const float pw = (float)ENEG / (float)EP;
    double dsum = 0.0;

    int eg0 = mt * 16 + (lane >> 2);
    int eg1 = eg0 + 8;

    int ebld = tid & 63;
    int f0   = tid >> 6;
    int mtb  = ebld >> 4;
    int rb   = ebld & 15;
    int lf   = ((rb & 7) << 2) | (f0 & 3);
    int rhi  = rb >> 3;

    const int nTiles = ETOT / 64;
    const int stride = gridDim.x;

    // ---- prologue ----
    float hR[32];
    if (tid < 64) {
        int ge = blockIdx.x * 64 + tid;
        int u, v;
        if (ge < EP) { u = pu[ge]; v = pv[ge]; }
        else         { u = nu[ge - EP]; v = nv[ge - EP]; }
        sU[tid] = u; sV[tid] = v;
    }
    __syncthreads();
#pragma unroll
    for (int ee = 0; ee < 8; ee++) {
        int e = wid * 8 + ee;
        int u = sU[e], v = sV[e];
        hR[ee * 4 + 0] = h[(size_t)u * 64 + lane];
        hR[ee * 4 + 1] = h[(size_t)u * 64 + 32 + lane];
        hR[ee * 4 + 2] = h[(size_t)v * 64 + lane];
        hR[ee * 4 + 3] = h[(size_t)v * 64 + 32 + lane];
    }

    int buf = 0;
    for (int tile = blockIdx.x; tile < nTiles; tile += stride) {
        int nb = buf ^ 1;
        // A12 prefetch for CURRENT tile (indices valid since previous sync)
        int cu0 = sU[buf * 64 + eg0], cv0 = sV[buf * 64 + eg0];
        int cu1 = sU[buf * 64 + eg1], cv1 = sV[buf * 64 + eg1];
        float2 au0R[4], av0R[4], au1R[4], av1R[4];
#pragma unroll
        for (int nt = 0; nt < 4; nt++) {
            int j0 = nh * 32 + nt * 8 + 2 * (lane & 3);
            au0R[nt] = *(const float2*)&A12[(size_t)cu0 * 128 + j0];
            av0R[nt] = *(const float2*)&A12[(size_t)cv0 * 128 + 64 + j0];
            au1R[nt] = *(const float2*)&A12[(size_t)cu1 * 128 + j0];
            av1R[nt] = *(const float2*)&A12[(size_t)cv1 * 128 + 64 + j0];
        }
        // commit prefetched h to smem
#pragma unroll
        for (int ee = 0; ee < 8; ee++) {
            int e = wid * 8 + ee;
            sHU[e * 65 + lane]      = hR[ee * 4 + 0];
            sHU[e * 65 + 32 + lane] = hR[ee * 4 + 1];
            sHV[e * 65 + lane]      = hR[ee * 4 + 2];
            sHV[e * 65 + 32 + lane] = hR[ee * 4 + 3];
        }
        // next-tile indices + logit reset
        if (tid < 64) {
            int ntile = tile + stride;
            int gt = (ntile < nTiles) ? ntile : tile;
            int ge = gt * 64 + tid;
            int u, v;
            if (ge < EP) { u = pu[ge]; v = pv[ge]; }
            else         { u = nu[ge - EP]; v = nv[ge - EP]; }
            sU[nb * 64 + tid] = u; sV[nb * 64 + tid] = v;
            sLogit[buf * 64 + tid] = 0.f;
        }
        __syncthreads();  // A
        // build A fragments (tf32)
#pragma unroll
        for (int p = 0; p < 16; p++) {
            int f = f0 + 4 * p;
            float hu = sHU[ebld * 65 + f], hv = sHV[ebld * 65 + f];
            uint32_t dfrag = f2tf32(fabsf(hu - hv));
            uint32_t mfrag = f2tf32(hu * hv);
            int kt = f >> 3;
            int slot = rhi | (((f >> 2) & 1) << 1);
            int base = ((mtb * 16 + kt) * 4 + slot) * 33 + lf;
            uFA[base] = dfrag;
            uFA[base + 1056] = mfrag;
        }
        __syncthreads();  // B
        // prefetch next tile's h rows (overlaps mma)
#pragma unroll
        for (int ee = 0; ee < 8; ee++) {
            int e = wid * 8 + ee;
            int u = sU[nb * 64 + e], v = sV[nb * 64 + e];
            hR[ee * 4 + 0] = h[(size_t)u * 64 + lane];
            hR[ee * 4 + 1] = h[(size_t)u * 64 + 32 + lane];
            hR[ee * 4 + 2] = h[(size_t)v * 64 + lane];
            hR[ee * 4 + 3] = h[(size_t)v * 64 + 32 + lane];
        }
        // mma mainloop
        float a4[4][4];
#pragma unroll
        for (int i = 0; i < 4; i++) { a4[i][0] = a4[i][1] = a4[i][2] = a4[i][3] = 0.f; }
#pragma unroll 4
        for (int kt = 0; kt < 16; kt++) {
            int ab = (mt * 16 + kt) * 4 * 33 + lane;
            uint32_t A0 = uFA[ab], A1 = uFA[ab + 33], A2 = uFA[ab + 66], A3 = uFA[ab + 99];
#pragma unroll
            for (int nt = 0; nt < 4; nt++) {
                int bidx = ((kt * 8 + nh * 4 + nt) * 32 + lane) * 2;
                uint32_t B0 = uWB[bidx], B1 = uWB[bidx + 1];
                mma_tf32(a4[nt][0], a4[nt][1], a4[nt][2], a4[nt][3],
                         A0, A1, A2, A3, B0, B1);
            }
        }
        // epilogue (uses prefetched A12)
        {
            float p0 = 0.f, p1 = 0.f;
#pragma unroll
            for (int nt = 0; nt < 4; nt++) {
                float t0 = a4[nt][0] + au0R[nt].x + av0R[nt].x + baR[nt].x;
                float t1 = a4[nt][1] + au0R[nt].y + av0R[nt].y + baR[nt].y;
                float t2 = a4[nt][2] + au1R[nt].x + av1R[nt].x + baR[nt].x;
                float t3 = a4[nt][3] + au1R[nt].y + av1R[nt].y + baR[nt].y;
                p0 += fmaxf(t0, 0.f) * wbR[nt].x + fmaxf(t1, 0.f) * wbR[nt].y;
                p1 += fmaxf(t2, 0.f) * wbR[nt].x + fmaxf(t3, 0.f) * wbR[nt].y;
            }
            p0 += __shfl_xor_sync(0xffffffffu, p0, 1);
            p0 += __shfl_xor_sync(0xffffffffu, p0, 2);
            p1 += __shfl_xor_sync(0xffffffffu, p1, 1);
            p1 += __shfl_xor_sync(0xffffffffu, p1, 2);
            if ((lane & 3) == 0) {
                atomicAdd(&sLogit[buf * 64 + eg0], p0);
                atomicAdd(&sLogit[buf * 64 + eg1], p1);
            }
        }
        __syncthreads();  // C
        if (tid < 64) {
            float l = (sLogit[buf * 64 + tid] + bbv) * invt;
            int ge = tile * 64 + tid;
            float term;
            if (ge < EP) {
                float ls = fminf(l, 0.f) - log1pf(expf(-fabsf(l)));
                term = pw * ls;
            } else {
                float ls = fminf(-l, 0.f) - log1pf(expf(-fabsf(l)));
                term = ls;
            }
            dsum += (double)term;
        }
        buf = nb;
    }
#pragma unroll
    for (int o = 16; o; o >>= 1) dsum += __shfl_xor_sync(0xffffffffu, dsum, o);
    __shared__ double sredd[8];
    if (lane == 0) sredd[wid] = dsum;
    __syncthreads();
    if (tid == 0) {
        double t = 0.0;
        for (int i = 0; i < 8; i++) t += sredd[i];
        atomicAdd(acc, t);
    }
}

__global__ void finalize_kernel(const double* __restrict__ acc,
                                const double* __restrict__ accp,
                                float* __restrict__ out, int n)
{
    double kls = 0.0;
    for (int i = 0; i < 64; i++) kls += accp[i];
    double recon = -acc[0] / (double)ETOT;
    double kl = -0.5 * kls / ((double)Nn * 64.0);
    if (n >= 3) {
        out[0] = (float)(recon + kl);
        out[1] = (float)recon;
        out[2] = (float)kl;
    } else {
        out[0] = (float)(recon + kl);
    }
}

// ---------------- launch ----------------
extern "C" void kernel_launch(void* const* d_in, const int* in_sizes, int n_in,
                              void* d_out, int out_size)
{
    const float* x   = (const float*)d_in[0];
    const float* eps = (const float*)d_in[1];
    const int* edge_index = (const int*)d_in[2];
    const int* pos_edge   = (const int*)d_in[3];
    const int* neg_edge   = (const int*)d_in[4];
    const float* W1  = (const float*)d_in[5];
    const float* b1  = (const float*)d_in[6];
    const float* g1  = (const float*)d_in[7];
    const float* bt1 = (const float*)d_in[8];
    const float* Wmu = (const float*)d_in[9];
    const float* bmu = (const float*)d_in[10];
    const float* Wlv = (const float*)d_in[11];
    const float* blv = (const float*)d_in[12];
    const float* Wd1 = (const float*)d_in[13];
    const float* bd1 = (const float*)d_in[14];
    const float* Wd2 = (const float*)d_in[15];
    const float* bd2 = (const float*)d_in[16];
    const float* Wa  = (const float*)d_in[17];
    const float* ba  = (const float*)d_in[18];
    const float* Wb  = (const float*)d_in[19];
    const float* bb  = (const float*)d_in[20];
    const float* tau = (const float*)d_in[21];

    float *p_m, *p_h1, *p_tmulv, *p_z, *p_md, *p_hd, *p_hd2, *p_A12, *p_dis;
    int *p_degE, *p_degD, *p_startE, *p_startD, *p_curE, *p_curD, *p_permE, *p_permD;
    double *p_acc, *p_accp;
    cudaGetSymbolAddress((void**)&p_m, g_m);
    cudaGetSymbolAddress((void**)&p_h1, g_h1);
    cudaGetSymbolAddress((void**)&p_tmulv, g_tmulv);
    cudaGetSymbolAddress((void**)&p_z, g_z);
    cudaGetSymbolAddress((void**)&p_md, g_md);
    cudaGetSymbolAddress((void**)&p_hd, g_hd);
    cudaGetSymbolAddress((void**)&p_hd2, g_hd2);
    cudaGetSymbolAddress((void**)&p_A12, g_A12);
    cudaGetSymbolAddress((void**)&p_dis, g_dis);
    cudaGetSymbolAddress((void**)&p_degE, g_degE);
    cudaGetSymbolAddress((void**)&p_degD, g_degD);
    cudaGetSymbolAddress((void**)&p_startE, g_startE);
    cudaGetSymbolAddress((void**)&p_startD, g_startD);
    cudaGetSymbolAddress((void**)&p_curE, g_curE);
    cudaGetSymbolAddress((void**)&p_curD, g_curD);
    cudaGetSymbolAddress((void**)&p_permE, g_permE);
    cudaGetSymbolAddress((void**)&p_permD, g_permD);
    cudaGetSymbolAddress((void**)&p_acc, g_acc);
    cudaGetSymbolAddress((void**)&p_accp, g_accp);

    const int* src = edge_index;
    const int* dst = edge_index + E2;
    const int* pu = pos_edge;
    const int* pv = pos_edge + EP;
    const int* nu = neg_edge;
    const int* nv = neg_edge + ENEG;

    int mby = (Nn + 63) / 64;   // 313

    // ---- CSR build ----
    zero_kernel<<<(Nn + 255) / 256, 256>>>(p_degE, p_degD, p_acc, p_accp);
    count_kernel<<<(E2 + 255) / 256, 256>>>(dst, pv, p_degE, p_degD);
    scan_kernel<<<2, 1024>>>(p_degE, p_startE, p_curE, p_degD, p_startD, p_curD, p_dis);
    fill_kernel<<<(E2 + 255) / 256, 256>>>(src, dst, pu, pv, p_curE, p_curD,
                                           p_permE, p_permD);

    // ---- encoder layer 1 ----
    {
        dim3 g(4, mby);
        tgemm_kernel<<<g, 256>>>(x, W1, (const float*)0, p_m, Nn, 256, 256, 256, 0,
                                 (const float*)0);
    }
    gather_ln_kernel<<<Nn, 256>>>(p_m, p_permE, p_startE, b1, g1, bt1, p_h1);

    // ---- mu / logvar (one fused launch; grid.x selects weight) ----
    {
        dim3 g(2, mby);
        tgemm_kernel<<<g, 256>>>(p_h1, Wmu, Wlv, p_tmulv, Nn, 256, 64, 128, 0,
                                 (const float*)0);
    }
    gather_zkl_kernel<<<Nn, 128>>>(p_tmulv, p_permE, p_startE, bmu, blv, eps,
                                   p_z, p_accp);

    // ---- decoder GCN pass 1 ----
    {
        dim3 g(1, mby);
        tgemm_kernel<<<g, 256>>>(p_z, Wd1, (const float*)0, p_md, Nn, 64, 64, 64, 0, p_dis);
    }
    gather_dec_kernel<<<Nn / 4, 256>>>(p_md, p_permD, p_startD, p_dis, bd1, p_hd);

    // ---- decoder GCN pass 2 ----
    {
        dim3 g(1, mby);
        tgemm_kernel<<<g, 256>>>(p_hd, Wd2, (const float*)0, p_md, Nn, 64, 64, 64, 0, p_dis);
    }
    gather_dec_kernel<<<Nn / 4, 256>>>(p_md, p_permD, p_startD, p_dis, bd2, p_hd2);

    // ---- per-node precompute [h@Wa1 | h@Wa2] (one fused launch) ----
    {
        dim3 g(2, mby);
        tgemm_kernel<<<g, 256>>>(p_hd2, Wa, Wa + 64 * 64, p_A12, Nn, 64, 64, 128, 0,
                                 (const float*)0);
    }

    // ---- fused edge decoder + loss (pipelined tf32 mma) ----
    {
        int smem = (8192 + 8448 + 4160 + 4160 + 128) * 4 + 256 * 4;   // 101376 B
        cudaFuncSetAttribute(edge_loss_kernel, cudaFuncAttributeMaxDynamicSharedMemorySize, smem);
        edge_loss_kernel<<<296, 256, smem>>>(p_hd2, p_A12, Wa, ba, Wb, bb, tau,
                                             pu, pv, nu, nv, p_acc);
    }

    finalize_kernel<<<1, 1>>>(p_acc, p_accp, (float*)d_out, out_size);

    (void)in_sizes; (void)n_in;
}

// round 12
// speedup vs baseline: 2.0527x; 1.1011x over previous
#include <cuda_runtime.h>
#include <math.h>
#include <stdint.h>

#define Nn    20000
#define HIDF  256
#define ZF    64
#define EP    120000
#define E2    240000
#define ENEG  600000
#define ETOT  720000

typedef unsigned long long ull;

// ---------------- scratch (static device globals; no allocation) ----------------
__device__ __align__(16) float g_m[Nn * HIDF];
__device__ __align__(16) float g_h1[Nn * HIDF];
__device__ __align__(16) float g_tmulv[Nn * 128];
__device__ __align__(16) float g_z[Nn * ZF];
__device__ __align__(16) float g_md[Nn * ZF];
__device__ __align__(16) float g_hd[Nn * ZF];
__device__ __align__(16) float g_hd2[Nn * ZF];
__device__ __align__(16) float g_A12[Nn * 128];
__device__ float g_dis[Nn];
__device__ __align__(16) int g_degE[Nn];
__device__ __align__(16) int g_degD[Nn];
__device__ int g_startE[Nn + 1];
__device__ int g_startD[Nn + 1];
__device__ int g_curE[Nn];
__device__ int g_curD[Nn];
__device__ int g_permE[E2];
__device__ int g_permD[EP];
__device__ double g_acc[2];
__device__ double g_accp[64];

__device__ __forceinline__ uint32_t f2tf32(float x)
{
    uint32_t r;
    asm("cvt.rna.tf32.f32 %0, %1;" : "=r"(r) : "f"(x));
    return r;
}

__device__ __forceinline__ void mma_tf32(float& c0, float& c1, float& c2, float& c3,
    uint32_t a0, uint32_t a1, uint32_t a2, uint32_t a3, uint32_t b0, uint32_t b1)
{
    asm("mma.sync.aligned.m16n8k8.row.col.f32.tf32.tf32.f32 "
        "{%0,%1,%2,%3}, {%4,%5,%6,%7}, {%8,%9}, {%0,%1,%2,%3};"
        : "+f"(c0), "+f"(c1), "+f"(c2), "+f"(c3)
        : "r"(a0), "r"(a1), "r"(a2), "r"(a3), "r"(b0), "r"(b1));
}

// ---------------- zero ----------------
__global__ __launch_bounds__(256) void zero_kernel(int* degE, int* degD,
                                                   double* acc, double* accp)
{
    int idx = blockIdx.x * blockDim.x + threadIdx.x;
    if (idx < Nn) { degE[idx] = 0; degD[idx] = 0; }
    if (idx < 64) accp[idx] = 0.0;
    if (idx < 2) acc[idx] = 0.0;
}

// ---------------- degree count ----------------
__global__ __launch_bounds__(256) void count_kernel(
    const int* __restrict__ dst, const int* __restrict__ pd,
    int* __restrict__ degE, int* __restrict__ degD)
{
    int idx = blockIdx.x * blockDim.x + threadIdx.x;
    if (idx < E2) atomicAdd(&degE[dst[idx]], 1);
    if (idx < EP) atomicAdd(&degD[pd[idx]], 1);
}

// ---------------- exclusive scan of degrees ----------------
__global__ __launch_bounds__(1024) void scan_kernel(
    const int* __restrict__ degE, int* startE, int* curE,
    const int* __restrict__ degD, int* startD, int* curD, float* dis)
{
    const int* deg = (blockIdx.x == 0) ? degE : degD;
    int* start     = (blockIdx.x == 0) ? startE : startD;
    int* cur       = (blockIdx.x == 0) ? curE : curD;
    int t = threadIdx.x;
    int base = t * 20;
    int local[20];
    int sum = 0;
#pragma unroll
    for (int i = 0; i < 20; i++) {
        int idx = base + i;
        int v = (idx < Nn) ? deg[idx] : 0;
        local[i] = sum;
        sum += v;
    }
    __shared__ int ps[1024];
    ps[t] = sum;
    __syncthreads();
    for (int off = 1; off < 1024; off <<= 1) {
        int v = (t >= off) ? ps[t - off] : 0;
        __syncthreads();
        ps[t] += v;
        __syncthreads();
    }
    int offset = (t > 0) ? ps[t - 1] : 0;
#pragma unroll
    for (int i = 0; i < 20; i++) {
        int idx = base + i;
        if (idx < Nn) {
            int s = offset + local[i];
            start[idx] = s;
            cur[idx] = s;
            if (blockIdx.x == 1) dis[idx] = rsqrtf((float)deg[idx] + 1.0f);
        }
    }
    if (t == 1023) start[Nn] = ps[1023];
}

// ---------------- CSR fill ----------------
__global__ __launch_bounds__(256) void fill_kernel(
    const int* __restrict__ src, const int* __restrict__ dst,
    const int* __restrict__ ps, const int* __restrict__ pd,
    int* __restrict__ curE, int* __restrict__ curD,
    int* __restrict__ permE, int* __restrict__ permD)
{
    int idx = blockIdx.x * blockDim.x + threadIdx.x;
    if (idx < E2) {
        int slot = atomicAdd(&curE[dst[idx]], 1);
        permE[slot] = src[idx];
    }
    if (idx < EP) {
        int slot = atomicAdd(&curD[pd[idx]], 1);
        permD[slot] = ps[idx];
    }
}

// ---------------- tf32 tensor-core GEMM (plain-tile smem, padded strides) --------
__global__ __launch_bounds__(256) void tgemm_kernel(
    const float* __restrict__ A, const float* __restrict__ B,
    const float* __restrict__ B2, float* __restrict__ C,
    int M, int K, int bstride, int ldc, int coff, const float* __restrict__ rs)
{
    __shared__ uint32_t sA[64 * 36];
    __shared__ uint32_t sB[32 * 72];
    int tid = threadIdx.x;
    int lane = tid & 31, wid = tid >> 5;
    int mt = wid & 3, nh = wid >> 2;
    int m0 = blockIdx.y * 64;
    int n0, co;
    const float* Bp;
    if (B2) { Bp = blockIdx.x ? B2 : B; n0 = 0; co = coff + blockIdx.x * 64; }
    else    { Bp = B; n0 = blockIdx.x * 64; co = coff; }

    float c[4][4];
#pragma unroll
    for (int i = 0; i < 4; i++) { c[i][0] = c[i][1] = c[i][2] = c[i][3] = 0.f; }

    int arow = tid >> 2;
    int acb  = (tid & 3) * 8;
    int brow = tid >> 3;
    int bnb  = (tid & 7) * 8;

    int fr = lane >> 2;
    int fc = lane & 3;

    for (int k0 = 0; k0 < K; k0 += 32) {
        int gm = m0 + arow;
#pragma unroll
        for (int q = 0; q < 2; q++) {
            float4 v = (gm < M)
                ? *(const float4*)(A + (size_t)gm * K + k0 + acb + q * 4)
                : make_float4(0.f, 0.f, 0.f, 0.f);
            uint4 u;
            u.x = f2tf32(v.x); u.y = f2tf32(v.y); u.z = f2tf32(v.z); u.w = f2tf32(v.w);
            *(uint4*)&sA[arow * 36 + acb + q * 4] = u;
        }
#pragma unroll
        for (int q = 0; q < 2; q++) {
            float4 v = *(const float4*)(Bp + (size_t)(k0 + brow) * bstride + n0 + bnb + q * 4);
            uint4 u;
            u.x = f2tf32(v.x); u.y = f2tf32(v.y); u.z = f2tf32(v.z); u.w = f2tf32(v.w);
            *(uint4*)&sB[brow * 72 + bnb + q * 4] = u;
        }
        __syncthreads();
#pragma unroll
        for (int kt = 0; kt < 4; kt++) {
            int ra = (mt * 16 + fr) * 36 + kt * 8 + fc;
            uint32_t A0 = sA[ra];
            uint32_t A1 = sA[ra + 8 * 36];
            uint32_t A2 = sA[ra + 4];
            uint32_t A3 = sA[ra + 8 * 36 + 4];
#pragma unroll
            for (int nt2 = 0; nt2 < 4; nt2++) {
                int nt = nh * 4 + nt2;
                int rb = (kt * 8 + fc) * 72 + nt * 8 + fr;
                uint32_t B0 = sB[rb];
                uint32_t B1 = sB[rb + 4 * 72];
                mma_tf32(c[nt2][0], c[nt2][1], c[nt2][2], c[nt2][3],
                         A0, A1, A2, A3, B0, B1);
            }
        }
        __syncthreads();
    }
    int r0 = m0 + mt * 16 + fr;
    int r1 = r0 + 8;
    float sc0 = (r0 < M && rs) ? rs[r0] : 1.f;
    float sc1 = (r1 < M && rs) ? rs[r1] : 1.f;
#pragma unroll
    for (int nt2 = 0; nt2 < 4; nt2++) {
        int j = n0 + nh * 32 + nt2 * 8 + fc * 2;
        if (r0 < M)
            *(float2*)(C + (size_t)r0 * ldc + co + j) =
                make_float2(c[nt2][0] * sc0, c[nt2][1] * sc0);
        if (r1 < M)
            *(float2*)(C + (size_t)r1 * ldc + co + j) =
                make_float2(c[nt2][2] * sc1, c[nt2][3] * sc1);
    }
}

// ---------------- fused gather + bias + LayerNorm + relu ----------------
__global__ __launch_bounds__(256) void gather_ln_kernel(
    const float* __restrict__ m, const int* __restrict__ perm,
    const int* __restrict__ start, const float* __restrict__ b1,
    const float* __restrict__ g1, const float* __restrict__ bt1,
    float* __restrict__ h1)
{
    __shared__ int sidx[256];
    __shared__ float red[8];
    int n = blockIdx.x;
    int j = threadIdx.x;
    int lane = j & 31, w = j >> 5;
    int s0 = start[n], s1 = start[n + 1];
    int deg = s1 - s0;
    int cnt = deg < 256 ? deg : 256;
    if (j < cnt) sidx[j] = perm[s0 + j];
    __syncthreads();
    float a0 = 0.f, a1 = 0.f, a2 = 0.f, a3 = 0.f;
    int k = 0;
    for (; k + 4 <= cnt; k += 4) {
        a0 += m[(size_t)sidx[k + 0] * 256 + j];
        a1 += m[(size_t)sidx[k + 1] * 256 + j];
        a2 += m[(size_t)sidx[k + 2] * 256 + j];
        a3 += m[(size_t)sidx[k + 3] * 256 + j];
    }
    for (; k < cnt; k++) a0 += m[(size_t)sidx[k] * 256 + j];
    for (int k2 = 256; k2 < deg; k2++) a0 += m[(size_t)perm[s0 + k2] * 256 + j];
    float v = (a0 + a1) + (a2 + a3) + b1[j];
    float s = v;
#pragma unroll
    for (int o = 16; o; o >>= 1) s += __shfl_xor_sync(0xffffffffu, s, o);
    if (lane == 0) red[w] = s;
    __syncthreads();
    float tot = 0.f;
#pragma unroll
    for (int i = 0; i < 8; i++) tot += red[i];
    float mu = tot * (1.f / 256.f);
    __syncthreads();
    float d = v - mu;
    float q = d * d;
#pragma unroll
    for (int o = 16; o; o >>= 1) q += __shfl_xor_sync(0xffffffffu, q, o);
    if (lane == 0) red[w] = q;
    __syncthreads();
    float tq = 0.f;
#pragma unroll
    for (int i = 0; i < 8; i++) tq += red[i];
    float var = tq * (1.f / 256.f);
    float o = d * rsqrtf(var + 1e-5f) * g1[j] + bt1[j];
    h1[(size_t)n * 256 + j] = fmaxf(o, 0.f);
}

// ---------------- fused gather + z-reparam + KL ----------------
__global__ __launch_bounds__(128) void gather_zkl_kernel(
    const float* __restrict__ t, const int* __restrict__ perm,
    const int* __restrict__ start, const float* __restrict__ bmu,
    const float* __restrict__ blv, const float* __restrict__ eps,
    float* __restrict__ z, double* __restrict__ accp)
{
    __shared__ int sidx[128];
    __shared__ float row[128];
    __shared__ double sred[4];
    int n = blockIdx.x;
    int j = threadIdx.x;
    int lane = j & 31, w = j >> 5;
    int s0 = start[n], s1 = start[n + 1];
    int deg = s1 - s0;
    int cnt = deg < 128 ? deg : 128;
    if (j < cnt) sidx[j] = perm[s0 + j];
    __syncthreads();
    float a0 = 0.f, a1 = 0.f, a2 = 0.f, a3 = 0.f;
    int k = 0;
    for (; k + 4 <= cnt; k += 4) {
        a0 += t[(size_t)sidx[k + 0] * 128 + j];
        a1 += t[(size_t)sidx[k + 1] * 128 + j];
        a2 += t[(size_t)sidx[k + 2] * 128 + j];
        a3 += t[(size_t)sidx[k + 3] * 128 + j];
    }
    for (; k < cnt; k++) a0 += t[(size_t)sidx[k] * 128 + j];
    for (int k2 = 128; k2 < deg; k2++) a0 += t[(size_t)perm[s0 + k2] * 128 + j];
    row[j] = (a0 + a1) + (a2 + a3);
    __syncthreads();
    double local = 0.0;
    if (j < 64) {
        float mu = row[j] + bmu[j];
        float lv = row[j + 64] + blv[j];
        z[(size_t)n * 64 + j] = mu + eps[(size_t)n * 64 + j] * expf(0.5f * lv);
        local = (double)(1.f + lv - mu * mu - expf(lv));
    }
#pragma unroll
    for (int o = 16; o; o >>= 1) local += __shfl_xor_sync(0xffffffffu, local, o);
    if (lane == 0) sred[w] = local;
    __syncthreads();
    if (j == 0) {
        double tt = sred[0] + sred[1] + sred[2] + sred[3];
        atomicAdd(&accp[n & 63], tt);
    }
}

// ---------------- fused decoder gather + selfloop + bias + relu ----------------
__global__ __launch_bounds__(256) void gather_dec_kernel(
    const float* __restrict__ msc, const int* __restrict__ perm,
    const int* __restrict__ start, const float* __restrict__ dis,
    const float* __restrict__ bd, float* __restrict__ outp)
{
    __shared__ int sidx[4][64];
    int tid = threadIdx.x;
    int g = tid >> 6, j = tid & 63;
    int n = blockIdx.x * 4 + g;
    int s0 = start[n], s1 = start[n + 1];
    int deg = s1 - s0;
    int cnt = deg < 64 ? deg : 64;
    if (j < cnt) sidx[g][j] = perm[s0 + j];
    __syncthreads();
    float a0 = 0.f, a1 = 0.f, a2 = 0.f, a3 = 0.f;
    int k = 0;
    for (; k + 4 <= cnt; k += 4) {
        a0 += msc[(size_t)sidx[g][k + 0] * 64 + j];
        a1 += msc[(size_t)sidx[g][k + 1] * 64 + j];
        a2 += msc[(size_t)sidx[g][k + 2] * 64 + j];
        a3 += msc[(size_t)sidx[g][k + 3] * 64 + j];
    }
    for (; k < cnt; k++) a0 += msc[(size_t)sidx[g][k] * 64 + j];
    for (int k2 = 64; k2 < deg; k2++) a0 += msc[(size_t)perm[s0 + k2] * 64 + j];
    float v = (a0 + a1) + (a2 + a3) + msc[(size_t)n * 64 + j];
    v = v * dis[n] + bd[j];
    outp[(size_t)n * 64 + j] = fmaxf(v, 0.f);
}

// ---------------- fused edge decoder + BCE loss: 1-sync pipelined tf32 mma --------
// Features are computed in registers from the gathered h rows and stored DIRECTLY
// into double-buffered A-fragment smem. Loss read is deferred one iteration so a
// single __syncthreads() per tile orders everything.
__global__ __launch_bounds__(256, 2) void edge_loss_kernel(
    const float* __restrict__ h, const float* __restrict__ A12,
    const float* __restrict__ Wa, const float* __restrict__ ba,
    const float* __restrict__ Wb, const float* __restrict__ bb,
    const float* __restrict__ tau,
    const int* __restrict__ pu, const int* __restrict__ pv,
    const int* __restrict__ nu, const int* __restrict__ nv,
    double* __restrict__ acc)
{
    extern __shared__ float sm[];
    float* sWB    = sm;                 // 8192
    float* sFA    = sWB + 8192;         // 2 x 8448 = 16896
    float* sLogit = sFA + 16896;        // 2 x 64
    int* sU = (int*)(sLogit + 128);     // 2 x 64
    int* sV = sU + 128;                 // 2 x 64
    uint32_t* uWB = (uint32_t*)sWB;
    uint32_t* uFA = (uint32_t*)sFA;

    int tid = threadIdx.x;
    int lane = tid & 31, wid = tid >> 5;
    int mt = wid & 3, nh = wid >> 2;

    const float* W34 = Wa + 128 * 64;
    for (int i = tid; i < 8192; i += 256) {
        int s  = i & 1;
        int ln = (i >> 1) & 31;
        int nt = (i >> 6) & 7;
        int kt = i >> 9;
        int kk = kt * 8 + (ln & 3) + 4 * s;
        int nn = nt * 8 + (ln >> 2);
        uWB[i] = f2tf32(W34[kk * 64 + nn]);
    }

    float tc = fmaxf(tau[0], 1e-4f);
    float invt = 1.0f / tc;
    float bbv = bb[0];
    float2 baR[4], wbR[4];
#pragma unroll
    for (int nt = 0; nt < 4; nt++) {
        int j0 = nh * 32 + nt * 8 + 2 * (lane & 3);
        baR[nt] = *(const float2*)&ba[j0];
        wbR[nt] = *(const float2*)&Wb[j0];
    }
    const float pw = (float)ENEG / (float)EP;
    double dsum = 0.0;

    int eg0 = mt * 16 + (lane >> 2);
    int eg1 = eg0 + 8;

    // feature-store constants: edges e in [8*wid, 8*wid+8)
    int mtbW = wid >> 1;       // e >> 4
    int rhiW = wid & 1;        // (e & 15) >> 3

    const int nTiles = ETOT / 64;
    const int stride = gridDim.x;

    // ---- prologue: tile0 indices + h prefetch; zero both logit buffers ----
    if (tid < 64) {
        int ge = blockIdx.x * 64 + tid;
        int u, v;
        if (ge < EP) { u = pu[ge]; v = pv[ge]; }
        else         { u = nu[ge - EP]; v = nv[ge - EP]; }
        sU[tid] = u; sV[tid] = v;
        sLogit[tid] = 0.f; sLogit[64 + tid] = 0.f;
    }
    __syncthreads();
    float hR[32];
#pragma unroll
    for (int ee = 0; ee < 8; ee++) {
        int e = wid * 8 + ee;
        int u = sU[e], v = sV[e];
        hR[ee * 4 + 0] = h[(size_t)u * 64 + lane];
        hR[ee * 4 + 1] = h[(size_t)u * 64 + 32 + lane];
        hR[ee * 4 + 2] = h[(size_t)v * 64 + lane];
        hR[ee * 4 + 3] = h[(size_t)v * 64 + 32 + lane];
    }

    int buf = 0;
    int lt = -1;
    for (int tile = blockIdx.x; tile < nTiles; tile += stride) {
        int nb = buf ^ 1;
        // A12 prefetch for CURRENT tile
        int cu0 = sU[buf * 64 + eg0], cv0 = sV[buf * 64 + eg0];
        int cu1 = sU[buf * 64 + eg1], cv1 = sV[buf * 64 + eg1];
        float2 au0R[4], av0R[4], au1R[4], av1R[4];
#pragma unroll
        for (int nt = 0; nt < 4; nt++) {
            int j0 = nh * 32 + nt * 8 + 2 * (lane & 3);
            au0R[nt] = *(const float2*)&A12[(size_t)cu0 * 128 + j0];
            av0R[nt] = *(const float2*)&A12[(size_t)cv0 * 128 + 64 + j0];
            au1R[nt] = *(const float2*)&A12[(size_t)cu1 * 128 + j0];
            av1R[nt] = *(const float2*)&A12[(size_t)cv1 * 128 + 64 + j0];
        }
        // features from registers -> A-fragment smem (buffer buf)
        {
            uint32_t* uF = uFA + buf * 8448;
#pragma unroll
            for (int ee = 0; ee < 8; ee++) {
                float hu0 = hR[ee * 4 + 0], hu1 = hR[ee * 4 + 1];
                float hv0 = hR[ee * 4 + 2], hv1 = hR[ee * 4 + 3];
                uint32_t v0 = f2tf32(fabsf(hu0 - hv0));
                uint32_t v1 = f2tf32(fabsf(hu1 - hv1));
                uint32_t v2 = f2tf32(hu0 * hv0);
                uint32_t v3 = f2tf32(hu1 * hv1);
                int lf = ee << 2;
                uint32_t vals[4] = {v0, v1, v2, v3};
#pragma unroll
                for (int q = 0; q < 4; q++) {
                    int k = q * 32 + lane;    // k in {lane, 32+lane, 64+lane, 96+lane}
                    int addr = ((mtbW * 16 + (k >> 3)) * 4 + rhiW + (((k >> 2) & 1) << 1)) * 33
                               + lf + (k & 3);
                    uF[addr] = vals[q];
                }
            }
        }
        // next-tile indices
        if (tid < 64) {
            int ntile = tile + stride;
            int gt = (ntile < nTiles) ? ntile : tile;
            int ge = gt * 64 + tid;
            int u, v;
            if (ge < EP) { u = pu[ge]; v = pv[ge]; }
            else         { u = nu[ge - EP]; v = nv[ge - EP]; }
            sU[nb * 64 + tid] = u; sV[nb * 64 + tid] = v;
        }
        __syncthreads();  // the ONLY barrier per tile
        // deferred loss for PREVIOUS tile (its logits live in sLogit[nb])
        if (lt >= 0 && tid < 64) {
            float l = (sLogit[nb * 64 + tid] + bbv) * invt;
            int ge = lt * 64 + tid;
            float term;
            if (ge < EP) {
                float ls = fminf(l, 0.f) - log1pf(expf(-fabsf(l)));
                term = pw * ls;
            } else {
                float ls = fminf(-l, 0.f) - log1pf(expf(-fabsf(l)));
                term = ls;
            }
            dsum += (double)term;
            sLogit[nb * 64 + tid] = 0.f;   // ready for tile+stride (same buffer)
        }
        // prefetch next tile's h rows (overlaps mma)
#pragma unroll
        for (int ee = 0; ee < 8; ee++) {
            int e = wid * 8 + ee;
            int u = sU[nb * 64 + e], v = sV[nb * 64 + e];
            hR[ee * 4 + 0] = h[(size_t)u * 64 + lane];
            hR[ee * 4 + 1] = h[(size_t)u * 64 + 32 + lane];
            hR[ee * 4 + 2] = h[(size_t)v * 64 + lane];
            hR[ee * 4 + 3] = h[(size_t)v * 64 + 32 + lane];
        }
        // mma mainloop on buffer buf
        float a4[4][4];
#pragma unroll
        for (int i = 0; i < 4; i++) { a4[i][0] = a4[i][1] = a4[i][2] = a4[i][3] = 0.f; }
        int fbase = buf * 8448;
#pragma unroll 4
        for (int kt = 0; kt < 16; kt++) {
            int ab = fbase + (mt * 16 + kt) * 132 + lane;
            uint32_t A0 = uFA[ab], A1 = uFA[ab + 33], A2 = uFA[ab + 66], A3 = uFA[ab + 99];
#pragma unroll
            for (int nt = 0; nt < 4; nt++) {
                int bidx = ((kt * 8 + nh * 4 + nt) * 32 + lane) * 2;
                uint32_t B0 = uWB[bidx], B1 = uWB[bidx + 1];
                mma_tf32(a4[nt][0], a4[nt][1], a4[nt][2], a4[nt][3],
                         A0, A1, A2, A3, B0, B1);
            }
        }
        // epilogue (prefetched A12) -> sLogit[buf]
        {
            float p0 = 0.f, p1 = 0.f;
#pragma unroll
            for (int nt = 0; nt < 4; nt++) {
                float t0 = a4[nt][0] + au0R[nt].x + av0R[nt].x + baR[nt].x;
                float t1 = a4[nt][1] + au0R[nt].y + av0R[nt].y + baR[nt].y;
                float t2 = a4[nt][2] + au1R[nt].x + av1R[nt].x + baR[nt].x;
                float t3 = a4[nt][3] + au1R[nt].y + av1R[nt].y + baR[nt].y;
                p0 += fmaxf(t0, 0.f) * wbR[nt].x + fmaxf(t1, 0.f) * wbR[nt].y;
                p1 += fmaxf(t2, 0.f) * wbR[nt].x + fmaxf(t3, 0.f) * wbR[nt].y;
            }
            p0 += __shfl_xor_sync(0xffffffffu, p0, 1);
            p0 += __shfl_xor_sync(0xffffffffu, p0, 2);
            p1 += __shfl_xor_sync(0xffffffffu, p1, 1);
            p1 += __shfl_xor_sync(0xffffffffu, p1, 2);
            if ((lane & 3) == 0) {
                atomicAdd(&sLogit[buf * 64 + eg0], p0);
                atomicAdd(&sLogit[buf * 64 + eg1], p1);
            }
        }
        lt = tile;
        buf = nb;
    }
    // drain: last tile's logits are in sLogit[buf^1]
    __syncthreads();
    if (lt >= 0 && tid < 64) {
        int pb = buf ^ 1;
        float l = (sLogit[pb * 64 + tid] + bbv) * invt;
        int ge = lt * 64 + tid;
        float term;
        if (ge < EP) {
            float ls = fminf(l, 0.f) - log1pf(expf(-fabsf(l)));
            term = pw * ls;
        } else {
            float ls = fminf(-l, 0.f) - log1pf(expf(-fabsf(l)));
            term = ls;
        }
        dsum += (double)term;
    }
#pragma unroll
    for (int o = 16; o; o >>= 1) dsum += __shfl_xor_sync(0xffffffffu, dsum, o);
    __shared__ double sredd[8];
    if (lane == 0) sredd[wid] = dsum;
    __syncthreads();
    if (tid == 0) {
        double t = 0.0;
        for (int i = 0; i < 8; i++) t += sredd[i];
        atomicAdd(acc, t);
    }
}

__global__ void finalize_kernel(const double* __restrict__ acc,
                                const double* __restrict__ accp,
                                float* __restrict__ out, int n)
{
    double kls = 0.0;
    for (int i = 0; i < 64; i++) kls += accp[i];
    double recon = -acc[0] / (double)ETOT;
    double kl = -0.5 * kls / ((double)Nn * 64.0);
    if (n >= 3) {
        out[0] = (float)(recon + kl);
        out[1] = (float)recon;
        out[2] = (float)kl;
    } else {
        out[0] = (float)(recon + kl);
    }
}

// ---------------- launch ----------------
extern "C" void kernel_launch(void* const* d_in, const int* in_sizes, int n_in,
                              void* d_out, int out_size)
{
    const float* x   = (const float*)d_in[0];
    const float* eps = (const float*)d_in[1];
    const int* edge_index = (const int*)d_in[2];
    const int* pos_edge   = (const int*)d_in[3];
    const int* neg_edge   = (const int*)d_in[4];
    const float* W1  = (const float*)d_in[5];
    const float* b1  = (const float*)d_in[6];
    const float* g1  = (const float*)d_in[7];
    const float* bt1 = (const float*)d_in[8];
    const float* Wmu = (const float*)d_in[9];
    const float* bmu = (const float*)d_in[10];
    const float* Wlv = (const float*)d_in[11];
    const float* blv = (const float*)d_in[12];
    const float* Wd1 = (const float*)d_in[13];
    const float* bd1 = (const float*)d_in[14];
    const float* Wd2 = (const float*)d_in[15];
    const float* bd2 = (const float*)d_in[16];
    const float* Wa  = (const float*)d_in[17];
    const float* ba  = (const float*)d_in[18];
    const float* Wb  = (const float*)d_in[19];
    const float* bb  = (const float*)d_in[20];
    const float* tau = (const float*)d_in[21];

    float *p_m, *p_h1, *p_tmulv, *p_z, *p_md, *p_hd, *p_hd2, *p_A12, *p_dis;
    int *p_degE, *p_degD, *p_startE, *p_startD, *p_curE, *p_curD, *p_permE, *p_permD;
    double *p_acc, *p_accp;
    cudaGetSymbolAddress((void**)&p_m, g_m);
    cudaGetSymbolAddress((void**)&p_h1, g_h1);
    cudaGetSymbolAddress((void**)&p_tmulv, g_tmulv);
    cudaGetSymbolAddress((void**)&p_z, g_z);
    cudaGetSymbolAddress((void**)&p_md, g_md);
    cudaGetSymbolAddress((void**)&p_hd, g_hd);
    cudaGetSymbolAddress((void**)&p_hd2, g_hd2);
    cudaGetSymbolAddress((void**)&p_A12, g_A12);
    cudaGetSymbolAddress((void**)&p_dis, g_dis);
    cudaGetSymbolAddress((void**)&p_degE, g_degE);
    cudaGetSymbolAddress((void**)&p_degD, g_degD);
    cudaGetSymbolAddress((void**)&p_startE, g_startE);
    cudaGetSymbolAddress((void**)&p_startD, g_startD);
    cudaGetSymbolAddress((void**)&p_curE, g_curE);
    cudaGetSymbolAddress((void**)&p_curD, g_curD);
    cudaGetSymbolAddress((void**)&p_permE, g_permE);
    cudaGetSymbolAddress((void**)&p_permD, g_permD);
    cudaGetSymbolAddress((void**)&p_acc, g_acc);
    cudaGetSymbolAddress((void**)&p_accp, g_accp);

    const int* src = edge_index;
    const int* dst = edge_index + E2;
    const int* pu = pos_edge;
    const int* pv = pos_edge + EP;
    const int* nu = neg_edge;
    const int* nv = neg_edge + ENEG;

    int mby = (Nn + 63) / 64;   // 313

    // ---- CSR build ----
    zero_kernel<<<(Nn + 255) / 256, 256>>>(p_degE, p_degD, p_acc, p_accp);
    count_kernel<<<(E2 + 255) / 256, 256>>>(dst, pv, p_degE, p_degD);
    scan_kernel<<<2, 1024>>>(p_degE, p_startE, p_curE, p_degD, p_startD, p_curD, p_dis);
    fill_kernel<<<(E2 + 255) / 256, 256>>>(src, dst, pu, pv, p_curE, p_curD,
                                           p_permE, p_permD);

    // ---- encoder layer 1 ----
    {
        dim3 g(4, mby);
        tgemm_kernel<<<g, 256>>>(x, W1, (const float*)0, p_m, Nn, 256, 256, 256, 0,
                                 (const float*)0);
    }
    gather_ln_kernel<<<Nn, 256>>>(p_m, p_permE, p_startE, b1, g1, bt1, p_h1);

    // ---- mu / logvar (one fused launch; grid.x selects weight) ----
    {
        dim3 g(2, mby);
        tgemm_kernel<<<g, 256>>>(p_h1, Wmu, Wlv, p_tmulv, Nn, 256, 64, 128, 0,
                                 (const float*)0);
    }
    gather_zkl_kernel<<<Nn, 128>>>(p_tmulv, p_permE, p_startE, bmu, blv, eps,
                                   p_z, p_accp);

    // ---- decoder GCN pass 1 ----
    {
        dim3 g(1, mby);
        tgemm_kernel<<<g, 256>>>(p_z, Wd1, (const float*)0, p_md, Nn, 64, 64, 64, 0, p_dis);
    }
    gather_dec_kernel<<<Nn / 4, 256>>>(p_md, p_permD, p_startD, p_dis, bd1, p_hd);

    // ---- decoder GCN pass 2 ----
    {
        dim3 g(1, mby);
        tgemm_kernel<<<g, 256>>>(p_hd, Wd2, (const float*)0, p_md, Nn, 64, 64, 64, 0, p_dis);
    }
    gather_dec_kernel<<<Nn / 4, 256>>>(p_md, p_permD, p_startD, p_dis, bd2, p_hd2);

    // ---- per-node precompute [h@Wa1 | h@Wa2] (one fused launch) ----
    {
        dim3 g(2, mby);
        tgemm_kernel<<<g, 256>>>(p_hd2, Wa, Wa + 64 * 64, p_A12, Nn, 64, 64, 128, 0,
                                 (const float*)0);
    }

    // ---- fused edge decoder + loss (1-sync pipelined tf32 mma) ----
    {
        int smem = (8192 + 16896 + 128) * 4 + 256 * 4;   // 101888 B
        cudaFuncSetAttribute(edge_loss_kernel, cudaFuncAttributeMaxDynamicSharedMemorySize, smem);
        edge_loss_kernel<<<296, 256, smem>>>(p_hd2, p_A12, Wa, ba, Wb, bb, tau,
                                             pu, pv, nu, nv, p_acc);
    }

    finalize_kernel<<<1, 1>>>(p_acc, p_accp, (float*)d_out, out_size);

    (void)in_sizes; (void)n_in;
}

// round 13
// speedup vs baseline: 2.1283x; 1.0368x over previous
#include <cuda_runtime.h>
#include <cuda_bf16.h>
#include <math.h>
#include <stdint.h>

#define Nn    20000
#define HIDF  256
#define ZF    64
#define EP    120000
#define E2    240000
#define ENEG  600000
#define ETOT  720000

typedef unsigned long long ull;

// ---------------- scratch (static device globals; no allocation) ----------------
__device__ __align__(16) float g_m[Nn * HIDF];
__device__ __align__(16) float g_h1[Nn * HIDF];
__device__ __align__(16) float g_tmulv[Nn * 128];
__device__ __align__(16) float g_z[Nn * ZF];
__device__ __align__(16) float g_md[Nn * ZF];
__device__ __align__(16) float g_hd[Nn * ZF];
__device__ __align__(16) float g_hd2[Nn * ZF];
__device__ __align__(16) __nv_bfloat16 g_A12b[Nn * 128];
__device__ __align__(16) __nv_bfloat16 g_h16[Nn * ZF];
__device__ float g_dis[Nn];
__device__ __align__(16) int g_degE[Nn];
__device__ __align__(16) int g_degD[Nn];
__device__ int g_startE[Nn + 1];
__device__ int g_startD[Nn + 1];
__device__ int g_curE[Nn];
__device__ int g_curD[Nn];
__device__ int g_permE[E2];
__device__ int g_permD[EP];
__device__ double g_acc[2];
__device__ double g_accp[64];

__device__ __forceinline__ uint32_t f2tf32(float x)
{
    uint32_t r;
    asm("cvt.rna.tf32.f32 %0, %1;" : "=r"(r) : "f"(x));
    return r;
}

__device__ __forceinline__ void mma_tf32(float& c0, float& c1, float& c2, float& c3,
    uint32_t a0, uint32_t a1, uint32_t a2, uint32_t a3, uint32_t b0, uint32_t b1)
{
    asm("mma.sync.aligned.m16n8k8.row.col.f32.tf32.tf32.f32 "
        "{%0,%1,%2,%3}, {%4,%5,%6,%7}, {%8,%9}, {%0,%1,%2,%3};"
        : "+f"(c0), "+f"(c1), "+f"(c2), "+f"(c3)
        : "r"(a0), "r"(a1), "r"(a2), "r"(a3), "r"(b0), "r"(b1));
}

// ---------------- zero ----------------
__global__ __launch_bounds__(256) void zero_kernel(int* degE, int* degD,
                                                   double* acc, double* accp)
{
    int idx = blockIdx.x * blockDim.x + threadIdx.x;
    if (idx < Nn) { degE[idx] = 0; degD[idx] = 0; }
    if (idx < 64) accp[idx] = 0.0;
    if (idx < 2) acc[idx] = 0.0;
}

// ---------------- degree count ----------------
__global__ __launch_bounds__(256) void count_kernel(
    const int* __restrict__ dst, const int* __restrict__ pd,
    int* __restrict__ degE, int* __restrict__ degD)
{
    int idx = blockIdx.x * blockDim.x + threadIdx.x;
    if (idx < E2) atomicAdd(&degE[dst[idx]], 1);
    if (idx < EP) atomicAdd(&degD[pd[idx]], 1);
}

// ---------------- exclusive scan of degrees ----------------
__global__ __launch_bounds__(1024) void scan_kernel(
    const int* __restrict__ degE, int* startE, int* curE,
    const int* __restrict__ degD, int* startD, int* curD, float* dis)
{
    const int* deg = (blockIdx.x == 0) ? degE : degD;
    int* start     = (blockIdx.x == 0) ? startE : startD;
    int* cur       = (blockIdx.x == 0) ? curE : curD;
    int t = threadIdx.x;
    int base = t * 20;
    int local[20];
    int sum = 0;
#pragma unroll
    for (int i = 0; i < 20; i++) {
        int idx = base + i;
        int v = (idx < Nn) ? deg[idx] : 0;
        local[i] = sum;
        sum += v;
    }
    __shared__ int ps[1024];
    ps[t] = sum;
    __syncthreads();
    for (int off = 1; off < 1024; off <<= 1) {
        int v = (t >= off) ? ps[t - off] : 0;
        __syncthreads();
        ps[t] += v;
        __syncthreads();
    }
    int offset = (t > 0) ? ps[t - 1] : 0;
#pragma unroll
    for (int i = 0; i < 20; i++) {
        int idx = base + i;
        if (idx < Nn) {
            int s = offset + local[i];
            start[idx] = s;
            cur[idx] = s;
            if (blockIdx.x == 1) dis[idx] = rsqrtf((float)deg[idx] + 1.0f);
        }
    }
    if (t == 1023) start[Nn] = ps[1023];
}

// ---------------- CSR fill ----------------
__global__ __launch_bounds__(256) void fill_kernel(
    const int* __restrict__ src, const int* __restrict__ dst,
    const int* __restrict__ ps, const int* __restrict__ pd,
    int* __restrict__ curE, int* __restrict__ curD,
    int* __restrict__ permE, int* __restrict__ permD)
{
    int idx = blockIdx.x * blockDim.x + threadIdx.x;
    if (idx < E2) {
        int slot = atomicAdd(&curE[dst[idx]], 1);
        permE[slot] = src[idx];
    }
    if (idx < EP) {
        int slot = atomicAdd(&curD[pd[idx]], 1);
        permD[slot] = ps[idx];
    }
}

// ---------------- tf32 tensor-core GEMM (plain-tile smem, padded strides) --------
// bf16out: store output as bf16 (C reinterpreted as __nv_bfloat16*).
__global__ __launch_bounds__(256) void tgemm_kernel(
    const float* __restrict__ A, const float* __restrict__ B,
    const float* __restrict__ B2, float* __restrict__ C,
    int M, int K, int bstride, int ldc, int coff, const float* __restrict__ rs,
    int bf16out)
{
    __shared__ uint32_t sA[64 * 36];
    __shared__ uint32_t sB[32 * 72];
    int tid = threadIdx.x;
    int lane = tid & 31, wid = tid >> 5;
    int mt = wid & 3, nh = wid >> 2;
    int m0 = blockIdx.y * 64;
    int n0, co;
    const float* Bp;
    if (B2) { Bp = blockIdx.x ? B2 : B; n0 = 0; co = coff + blockIdx.x * 64; }
    else    { Bp = B; n0 = blockIdx.x * 64; co = coff; }

    float c[4][4];
#pragma unroll
    for (int i = 0; i < 4; i++) { c[i][0] = c[i][1] = c[i][2] = c[i][3] = 0.f; }

    int arow = tid >> 2;
    int acb  = (tid & 3) * 8;
    int brow = tid >> 3;
    int bnb  = (tid & 7) * 8;

    int fr = lane >> 2;
    int fc = lane & 3;

    for (int k0 = 0; k0 < K; k0 += 32) {
        int gm = m0 + arow;
#pragma unroll
        for (int q = 0; q < 2; q++) {
            float4 v = (gm < M)
                ? *(const float4*)(A + (size_t)gm * K + k0 + acb + q * 4)
                : make_float4(0.f, 0.f, 0.f, 0.f);
            uint4 u;
            u.x = f2tf32(v.x); u.y = f2tf32(v.y); u.z = f2tf32(v.z); u.w = f2tf32(v.w);
            *(uint4*)&sA[arow * 36 + acb + q * 4] = u;
        }
#pragma unroll
        for (int q = 0; q < 2; q++) {
            float4 v = *(const float4*)(Bp + (size_t)(k0 + brow) * bstride + n0 + bnb + q * 4);
            uint4 u;
            u.x = f2tf32(v.x); u.y = f2tf32(v.y); u.z = f2tf32(v.z); u.w = f2tf32(v.w);
            *(uint4*)&sB[brow * 72 + bnb + q * 4] = u;
        }
        __syncthreads();
#pragma unroll
        for (int kt = 0; kt < 4; kt++) {
            int ra = (mt * 16 + fr) * 36 + kt * 8 + fc;
            uint32_t A0 = sA[ra];
            uint32_t A1 = sA[ra + 8 * 36];
            uint32_t A2 = sA[ra + 4];
            uint32_t A3 = sA[ra + 8 * 36 + 4];
#pragma unroll
            for (int nt2 = 0; nt2 < 4; nt2++) {
                int nt = nh * 4 + nt2;
                int rb = (kt * 8 + fc) * 72 + nt * 8 + fr;
                uint32_t B0 = sB[rb];
                uint32_t B1 = sB[rb + 4 * 72];
                mma_tf32(c[nt2][0], c[nt2][1], c[nt2][2], c[nt2][3],
                         A0, A1, A2, A3, B0, B1);
            }
        }
        __syncthreads();
    }
    int r0 = m0 + mt * 16 + fr;
    int r1 = r0 + 8;
    float sc0 = (r0 < M && rs) ? rs[r0] : 1.f;
    float sc1 = (r1 < M && rs) ? rs[r1] : 1.f;
#pragma unroll
    for (int nt2 = 0; nt2 < 4; nt2++) {
        int j = n0 + nh * 32 + nt2 * 8 + fc * 2;
        if (!bf16out) {
            if (r0 < M)
                *(float2*)(C + (size_t)r0 * ldc + co + j) =
                    make_float2(c[nt2][0] * sc0, c[nt2][1] * sc0);
            if (r1 < M)
                *(float2*)(C + (size_t)r1 * ldc + co + j) =
                    make_float2(c[nt2][2] * sc1, c[nt2][3] * sc1);
        } else {
            __nv_bfloat16* Cb = (__nv_bfloat16*)C;
            if (r0 < M)
                *(__nv_bfloat162*)(Cb + (size_t)r0 * ldc + co + j) =
                    __floats2bfloat162_rn(c[nt2][0] * sc0, c[nt2][1] * sc0);
            if (r1 < M)
                *(__nv_bfloat162*)(Cb + (size_t)r1 * ldc + co + j) =
                    __floats2bfloat162_rn(c[nt2][2] * sc1, c[nt2][3] * sc1);
        }
    }
}

// ---------------- fused gather + bias + LayerNorm + relu ----------------
__global__ __launch_bounds__(256) void gather_ln_kernel(
    const float* __restrict__ m, const int* __restrict__ perm,
    const int* __restrict__ start, const float* __restrict__ b1,
    const float* __restrict__ g1, const float* __restrict__ bt1,
    float* __restrict__ h1)
{
    __shared__ int sidx[256];
    __shared__ float red[8];
    int n = blockIdx.x;
    int j = threadIdx.x;
    int lane = j & 31, w = j >> 5;
    int s0 = start[n], s1 = start[n + 1];
    int deg = s1 - s0;
    int cnt = deg < 256 ? deg : 256;
    if (j < cnt) sidx[j] = perm[s0 + j];
    __syncthreads();
    float a0 = 0.f, a1 = 0.f, a2 = 0.f, a3 = 0.f;
    int k = 0;
    for (; k + 4 <= cnt; k += 4) {
        a0 += m[(size_t)sidx[k + 0] * 256 + j];
        a1 += m[(size_t)sidx[k + 1] * 256 + j];
        a2 += m[(size_t)sidx[k + 2] * 256 + j];
        a3 += m[(size_t)sidx[k + 3] * 256 + j];
    }
    for (; k < cnt; k++) a0 += m[(size_t)sidx[k] * 256 + j];
    for (int k2 = 256; k2 < deg; k2++) a0 += m[(size_t)perm[s0 + k2] * 256 + j];
    float v = (a0 + a1) + (a2 + a3) + b1[j];
    float s = v;
#pragma unroll
    for (int o = 16; o; o >>= 1) s += __shfl_xor_sync(0xffffffffu, s, o);
    if (lane == 0) red[w] = s;
    __syncthreads();
    float tot = 0.f;
#pragma unroll
    for (int i = 0; i < 8; i++) tot += red[i];
    float mu = tot * (1.f / 256.f);
    __syncthreads();
    float d = v - mu;
    float q = d * d;
#pragma unroll
    for (int o = 16; o; o >>= 1) q += __shfl_xor_sync(0xffffffffu, q, o);
    if (lane == 0) red[w] = q;
    __syncthreads();
    float tq = 0.f;
#pragma unroll
    for (int i = 0; i < 8; i++) tq += red[i];
    float var = tq * (1.f / 256.f);
    float o = d * rsqrtf(var + 1e-5f) * g1[j] + bt1[j];
    h1[(size_t)n * 256 + j] = fmaxf(o, 0.f);
}

// ---------------- fused gather + z-reparam + KL ----------------
__global__ __launch_bounds__(128) void gather_zkl_kernel(
    const float* __restrict__ t, const int* __restrict__ perm,
    const int* __restrict__ start, const float* __restrict__ bmu,
    const float* __restrict__ blv, const float* __restrict__ eps,
    float* __restrict__ z, double* __restrict__ accp)
{
    __shared__ int sidx[128];
    __shared__ float row[128];
    __shared__ double sred[4];
    int n = blockIdx.x;
    int j = threadIdx.x;
    int lane = j & 31, w = j >> 5;
    int s0 = start[n], s1 = start[n + 1];
    int deg = s1 - s0;
    int cnt = deg < 128 ? deg : 128;
    if (j < cnt) sidx[j] = perm[s0 + j];
    __syncthreads();
    float a0 = 0.f, a1 = 0.f, a2 = 0.f, a3 = 0.f;
    int k = 0;
    for (; k + 4 <= cnt; k += 4) {
        a0 += t[(size_t)sidx[k + 0] * 128 + j];
        a1 += t[(size_t)sidx[k + 1] * 128 + j];
        a2 += t[(size_t)sidx[k + 2] * 128 + j];
        a3 += t[(size_t)sidx[k + 3] * 128 + j];
    }
    for (; k < cnt; k++) a0 += t[(size_t)sidx[k] * 128 + j];
    for (int k2 = 128; k2 < deg; k2++) a0 += t[(size_t)perm[s0 + k2] * 128 + j];
    row[j] = (a0 + a1) + (a2 + a3);
    __syncthreads();
    double local = 0.0;
    if (j < 64) {
        float mu = row[j] + bmu[j];
        float lv = row[j + 64] + blv[j];
        z[(size_t)n * 64 + j] = mu + eps[(size_t)n * 64 + j] * expf(0.5f * lv);
        local = (double)(1.f + lv - mu * mu - expf(lv));
    }
#pragma unroll
    for (int o = 16; o; o >>= 1) local += __shfl_xor_sync(0xffffffffu, local, o);
    if (lane == 0) sred[w] = local;
    __syncthreads();
    if (j == 0) {
        double tt = sred[0] + sred[1] + sred[2] + sred[3];
        atomicAdd(&accp[n & 63], tt);
    }
}

// ---------------- fused decoder gather + selfloop + bias + relu (+bf16 shadow) ----
__global__ __launch_bounds__(256) void gather_dec_kernel(
    const float* __restrict__ msc, const int* __restrict__ perm,
    const int* __restrict__ start, const float* __restrict__ dis,
    const float* __restrict__ bd, float* __restrict__ outp,
    __nv_bfloat16* __restrict__ out16)
{
    __shared__ int sidx[4][64];
    int tid = threadIdx.x;
    int g = tid >> 6, j = tid & 63;
    int n = blockIdx.x * 4 + g;
    int s0 = start[n], s1 = start[n + 1];
    int deg = s1 - s0;
    int cnt = deg < 64 ? deg : 64;
    if (j < cnt) sidx[g][j] = perm[s0 + j];
    __syncthreads();
    float a0 = 0.f, a1 = 0.f, a2 = 0.f, a3 = 0.f;
    int k = 0;
    for (; k + 4 <= cnt; k += 4) {
        a0 += msc[(size_t)sidx[g][k + 0] * 64 + j];
        a1 += msc[(size_t)sidx[g][k + 1] * 64 + j];
        a2 += msc[(size_t)sidx[g][k + 2] * 64 + j];
        a3 += msc[(size_t)sidx[g][k + 3] * 64 + j];
    }
    for (; k < cnt; k++) a0 += msc[(size_t)sidx[g][k] * 64 + j];
    for (int k2 = 64; k2 < deg; k2++) a0 += msc[(size_t)perm[s0 + k2] * 64 + j];
    float v = (a0 + a1) + (a2 + a3) + msc[(size_t)n * 64 + j];
    v = v * dis[n] + bd[j];
    float r = fmaxf(v, 0.f);
    outp[(size_t)n * 64 + j] = r;
    if (out16) out16[(size_t)n * 64 + j] = __float2bfloat16(r);
}

// ---------------- fused edge decoder + BCE loss: 1-sync pipelined tf32 mma --------
// bf16 h + bf16 A12 inputs halve L2 traffic; features built in registers and
// stored directly into double-buffered A-fragment smem; 1 __syncthreads per tile.
__global__ __launch_bounds__(256, 2) void edge_loss_kernel(
    const __nv_bfloat16* __restrict__ h16, const __nv_bfloat16* __restrict__ A12b,
    const float* __restrict__ Wa, const float* __restrict__ ba,
    const float* __restrict__ Wb, const float* __restrict__ bb,
    const float* __restrict__ tau,
    const int* __restrict__ pu, const int* __restrict__ pv,
    const int* __restrict__ nu, const int* __restrict__ nv,
    double* __restrict__ acc)
{
    extern __shared__ float sm[];
    float* sWB    = sm;                 // 8192
    float* sFA    = sWB + 8192;         // 2 x 8448 = 16896
    float* sLogit = sFA + 16896;        // 2 x 64
    int* sU = (int*)(sLogit + 128);     // 2 x 64
    int* sV = sU + 128;                 // 2 x 64
    uint32_t* uWB = (uint32_t*)sWB;
    uint32_t* uFA = (uint32_t*)sFA;

    int tid = threadIdx.x;
    int lane = tid & 31, wid = tid >> 5;
    int mt = wid & 3, nh = wid >> 2;

    const float* W34 = Wa + 128 * 64;
    for (int i = tid; i < 8192; i += 256) {
        int s  = i & 1;
        int ln = (i >> 1) & 31;
        int nt = (i >> 6) & 7;
        int kt = i >> 9;
        int kk = kt * 8 + (ln & 3) + 4 * s;
        int nn = nt * 8 + (ln >> 2);
        uWB[i] = f2tf32(W34[kk * 64 + nn]);
    }

    float tc = fmaxf(tau[0], 1e-4f);
    float invt = 1.0f / tc;
    float bbv = bb[0];
    float2 baR[4], wbR[4];
#pragma unroll
    for (int nt = 0; nt < 4; nt++) {
        int j0 = nh * 32 + nt * 8 + 2 * (lane & 3);
        baR[nt] = *(const float2*)&ba[j0];
        wbR[nt] = *(const float2*)&Wb[j0];
    }
    const float pw = (float)ENEG / (float)EP;
    double dsum = 0.0;

    int eg0 = mt * 16 + (lane >> 2);
    int eg1 = eg0 + 8;

    // feature-store constants: edges e in [8*wid, 8*wid+8), k in {2l,2l+1,64+2l,65+2l}
    int mtbW = wid >> 1;
    int rhiW = wid & 1;
    int k0 = 2 * lane;
    int bD0 = ((mtbW * 16 + (k0 >> 3)) * 4 + rhiW + (((k0 >> 2) & 1) << 1)) * 33 + (k0 & 3);

    const int nTiles = ETOT / 64;
    const int stride = gridDim.x;

    // ---- prologue ----
    if (tid < 64) {
        int ge = blockIdx.x * 64 + tid;
        int u, v;
        if (ge < EP) { u = pu[ge]; v = pv[ge]; }
        else         { u = nu[ge - EP]; v = nv[ge - EP]; }
        sU[tid] = u; sV[tid] = v;
        sLogit[tid] = 0.f; sLogit[64 + tid] = 0.f;
    }
    __syncthreads();
    uint32_t hRu[8], hRv[8];
#pragma unroll
    for (int ee = 0; ee < 8; ee++) {
        int e = wid * 8 + ee;
        int u = sU[e], v = sV[e];
        hRu[ee] = *(const uint32_t*)(h16 + (size_t)u * 64 + k0);
        hRv[ee] = *(const uint32_t*)(h16 + (size_t)v * 64 + k0);
    }

    int buf = 0;
    int lt = -1;
    for (int tile = blockIdx.x; tile < nTiles; tile += stride) {
        int nb = buf ^ 1;
        // A12 (bf16) prefetch for CURRENT tile
        int cu0 = sU[buf * 64 + eg0], cv0 = sV[buf * 64 + eg0];
        int cu1 = sU[buf * 64 + eg1], cv1 = sV[buf * 64 + eg1];
        float2 au0R[4], av0R[4], au1R[4], av1R[4];
#pragma unroll
        for (int nt = 0; nt < 4; nt++) {
            int j0 = nh * 32 + nt * 8 + 2 * (lane & 3);
            au0R[nt] = __bfloat1622float2(*(const __nv_bfloat162*)(A12b + (size_t)cu0 * 128 + j0));
            av0R[nt] = __bfloat1622float2(*(const __nv_bfloat162*)(A12b + (size_t)cv0 * 128 + 64 + j0));
            au1R[nt] = __bfloat1622float2(*(const __nv_bfloat162*)(A12b + (size_t)cu1 * 128 + j0));
            av1R[nt] = __bfloat1622float2(*(const __nv_bfloat162*)(A12b + (size_t)cv1 * 128 + 64 + j0));
        }
        // features from registers -> A-fragment smem (buffer buf)
        {
            uint32_t* uF = uFA + buf * 8448;
#pragma unroll
            for (int ee = 0; ee < 8; ee++) {
                float2 hu = __bfloat1622float2(*(__nv_bfloat162*)&hRu[ee]);
                float2 hv = __bfloat1622float2(*(__nv_bfloat162*)&hRv[ee]);
                int off = ee << 2;
                uF[bD0 + off]        = f2tf32(fabsf(hu.x - hv.x));
                uF[bD0 + 1 + off]    = f2tf32(fabsf(hu.y - hv.y));
                uF[bD0 + 1056 + off] = f2tf32(hu.x * hv.x);
                uF[bD0 + 1057 + off] = f2tf32(hu.y * hv.y);
            }
        }
        // next-tile indices
        if (tid < 64) {
            int ntile = tile + stride;
            int gt = (ntile < nTiles) ? ntile : tile;
            int ge = gt * 64 + tid;
            int u, v;
            if (ge < EP) { u = pu[ge]; v = pv[ge]; }
            else         { u = nu[ge - EP]; v = nv[ge - EP]; }
            sU[nb * 64 + tid] = u; sV[nb * 64 + tid] = v;
        }
        __syncthreads();  // the ONLY barrier per tile
        // deferred loss for PREVIOUS tile
        if (lt >= 0 && tid < 64) {
            float l = (sLogit[nb * 64 + tid] + bbv) * invt;
            int ge = lt * 64 + tid;
            float term;
            if (ge < EP) {
                float ls = fminf(l, 0.f) - log1pf(expf(-fabsf(l)));
                term = pw * ls;
            } else {
                float ls = fminf(-l, 0.f) - log1pf(expf(-fabsf(l)));
                term = ls;
            }
            dsum += (double)term;
            sLogit[nb * 64 + tid] = 0.f;
        }
        // prefetch next tile's h rows (overlaps mma)
#pragma unroll
        for (int ee = 0; ee < 8; ee++) {
            int e = wid * 8 + ee;
            int u = sU[nb * 64 + e], v = sV[nb * 64 + e];
            hRu[ee] = *(const uint32_t*)(h16 + (size_t)u * 64 + k0);
            hRv[ee] = *(const uint32_t*)(h16 + (size_t)v * 64 + k0);
        }
        // mma mainloop on buffer buf
        float a4[4][4];
#pragma unroll
        for (int i = 0; i < 4; i++) { a4[i][0] = a4[i][1] = a4[i][2] = a4[i][3] = 0.f; }
        int fbase = buf * 8448;
#pragma unroll 4
        for (int kt = 0; kt < 16; kt++) {
            int ab = fbase + (mt * 16 + kt) * 132 + lane;
            uint32_t A0 = uFA[ab], A1 = uFA[ab + 33], A2 = uFA[ab + 66], A3 = uFA[ab + 99];
#pragma unroll
            for (int nt = 0; nt < 4; nt++) {
                int bidx = ((kt * 8 + nh * 4 + nt) * 32 + lane) * 2;
                uint32_t B0 = uWB[bidx], B1 = uWB[bidx + 1];
                mma_tf32(a4[nt][0], a4[nt][1], a4[nt][2], a4[nt][3],
                         A0, A1, A2, A3, B0, B1);
            }
        }
        // epilogue -> sLogit[buf]
        {
            float p0 = 0.f, p1 = 0.f;
#pragma unroll
            for (int nt = 0; nt < 4; nt++) {
                float t0 = a4[nt][0] + au0R[nt].x + av0R[nt].x + baR[nt].x;
                float t1 = a4[nt][1] + au0R[nt].y + av0R[nt].y + baR[nt].y;
                float t2 = a4[nt][2] + au1R[nt].x + av1R[nt].x + baR[nt].x;
                float t3 = a4[nt][3] + au1R[nt].y + av1R[nt].y + baR[nt].y;
                p0 += fmaxf(t0, 0.f) * wbR[nt].x + fmaxf(t1, 0.f) * wbR[nt].y;
                p1 += fmaxf(t2, 0.f) * wbR[nt].x + fmaxf(t3, 0.f) * wbR[nt].y;
            }
            p0 += __shfl_xor_sync(0xffffffffu, p0, 1);
            p0 += __shfl_xor_sync(0xffffffffu, p0, 2);
            p1 += __shfl_xor_sync(0xffffffffu, p1, 1);
            p1 += __shfl_xor_sync(0xffffffffu, p1, 2);
            if ((lane & 3) == 0) {
                atomicAdd(&sLogit[buf * 64 + eg0], p0);
                atomicAdd(&sLogit[buf * 64 + eg1], p1);
            }
        }
        lt = tile;
        buf = nb;
    }
    // drain
    __syncthreads();
    if (lt >= 0 && tid < 64) {
        int pb = buf ^ 1;
        float l = (sLogit[pb * 64 + tid] + bbv) * invt;
        int ge = lt * 64 + tid;
        float term;
        if (ge < EP) {
            float ls = fminf(l, 0.f) - log1pf(expf(-fabsf(l)));
            term = pw * ls;
        } else {
            float ls = fminf(-l, 0.f) - log1pf(expf(-fabsf(l)));
            term = ls;
        }
        dsum += (double)term;
    }
#pragma unroll
    for (int o = 16; o; o >>= 1) dsum += __shfl_xor_sync(0xffffffffu, dsum, o);
    __shared__ double sredd[8];
    if (lane == 0) sredd[wid] = dsum;
    __syncthreads();
    if (tid == 0) {
        double t = 0.0;
        for (int i = 0; i < 8; i++) t += sredd[i];
        atomicAdd(acc, t);
    }
}

__global__ void finalize_kernel(const double* __restrict__ acc,
                                const double* __restrict__ accp,
                                float* __restrict__ out, int n)
{
    double kls = 0.0;
    for (int i = 0; i < 64; i++) kls += accp[i];
    double recon = -acc[0] / (double)ETOT;
    double kl = -0.5 * kls / ((double)Nn * 64.0);
    if (n >= 3) {
        out[0] = (float)(recon + kl);
        out[1] = (float)recon;
        out[2] = (float)kl;
    } else {
        out[0] = (float)(recon + kl);
    }
}

// ---------------- launch ----------------
extern "C" void kernel_launch(void* const* d_in, const int* in_sizes, int n_in,
                              void* d_out, int out_size)
{
    const float* x   = (const float*)d_in[0];
    const float* eps = (const float*)d_in[1];
    const int* edge_index = (const int*)d_in[2];
    const int* pos_edge   = (const int*)d_in[3];
    const int* neg_edge   = (const int*)d_in[4];
    const float* W1  = (const float*)d_in[5];
    const float* b1  = (const float*)d_in[6];
    const float* g1  = (const float*)d_in[7];
    const float* bt1 = (const float*)d_in[8];
    const float* Wmu = (const float*)d_in[9];
    const float* bmu = (const float*)d_in[10];
    const float* Wlv = (const float*)d_in[11];
    const float* blv = (const float*)d_in[12];
    const float* Wd1 = (const float*)d_in[13];
    const float* bd1 = (const float*)d_in[14];
    const float* Wd2 = (const float*)d_in[15];
    const float* bd2 = (const float*)d_in[16];
    const float* Wa  = (const float*)d_in[17];
    const float* ba  = (const float*)d_in[18];
    const float* Wb  = (const float*)d_in[19];
    const float* bb  = (const float*)d_in[20];
    const float* tau = (const float*)d_in[21];

    float *p_m, *p_h1, *p_tmulv, *p_z, *p_md, *p_hd, *p_hd2, *p_dis;
    __nv_bfloat16 *p_A12b, *p_h16;
    int *p_degE, *p_degD, *p_startE, *p_startD, *p_curE, *p_curD, *p_permE, *p_permD;
    double *p_acc, *p_accp;
    cudaGetSymbolAddress((void**)&p_m, g_m);
    cudaGetSymbolAddress((void**)&p_h1, g_h1);
    cudaGetSymbolAddress((void**)&p_tmulv, g_tmulv);
    cudaGetSymbolAddress((void**)&p_z, g_z);
    cudaGetSymbolAddress((void**)&p_md, g_md);
    cudaGetSymbolAddress((void**)&p_hd, g_hd);
    cudaGetSymbolAddress((void**)&p_hd2, g_hd2);
    cudaGetSymbolAddress((void**)&p_A12b, g_A12b);
    cudaGetSymbolAddress((void**)&p_h16, g_h16);
    cudaGetSymbolAddress((void**)&p_dis, g_dis);
    cudaGetSymbolAddress((void**)&p_degE, g_degE);
    cudaGetSymbolAddress((void**)&p_degD, g_degD);
    cudaGetSymbolAddress((void**)&p_startE, g_startE);
    cudaGetSymbolAddress((void**)&p_startD, g_startD);
    cudaGetSymbolAddress((void**)&p_curE, g_curE);
    cudaGetSymbolAddress((void**)&p_curD, g_curD);
    cudaGetSymbolAddress((void**)&p_permE, g_permE);
    cudaGetSymbolAddress((void**)&p_permD, g_permD);
    cudaGetSymbolAddress((void**)&p_acc, g_acc);
    cudaGetSymbolAddress((void**)&p_accp, g_accp);

    const int* src = edge_index;
    const int* dst = edge_index + E2;
    const int* pu = pos_edge;
    const int* pv = pos_edge + EP;
    const int* nu = neg_edge;
    const int* nv = neg_edge + ENEG;

    int mby = (Nn + 63) / 64;   // 313

    // ---- fork: CSR build on side stream, encoder GEMM on main stream ----
    cudaStream_t cs;
    cudaStreamCreateWithFlags(&cs, cudaStreamNonBlocking);
    cudaEvent_t ev0, ev1;
    cudaEventCreateWithFlags(&ev0, cudaEventDisableTiming);
    cudaEventCreateWithFlags(&ev1, cudaEventDisableTiming);
    cudaEventRecord(ev0, 0);
    cudaStreamWaitEvent(cs, ev0, 0);

    zero_kernel<<<(Nn + 255) / 256, 256, 0, cs>>>(p_degE, p_degD, p_acc, p_accp);
    count_kernel<<<(E2 + 255) / 256, 256, 0, cs>>>(dst, pv, p_degE, p_degD);
    scan_kernel<<<2, 1024, 0, cs>>>(p_degE, p_startE, p_curE, p_degD, p_startD, p_curD, p_dis);
    fill_kernel<<<(E2 + 255) / 256, 256, 0, cs>>>(src, dst, pu, pv, p_curE, p_curD,
                                                  p_permE, p_permD);
    cudaEventRecord(ev1, cs);

    // encoder layer 1 GEMM (independent of CSR)
    {
        dim3 g(4, mby);
        tgemm_kernel<<<g, 256>>>(x, W1, (const float*)0, p_m, Nn, 256, 256, 256, 0,
                                 (const float*)0, 0);
    }
    cudaStreamWaitEvent(0, ev1, 0);   // join

    gather_ln_kernel<<<Nn, 256>>>(p_m, p_permE, p_startE, b1, g1, bt1, p_h1);

    // ---- mu / logvar (one fused launch; grid.x selects weight) ----
    {
        dim3 g(2, mby);
        tgemm_kernel<<<g, 256>>>(p_h1, Wmu, Wlv, p_tmulv, Nn, 256, 64, 128, 0,
                                 (const float*)0, 0);
    }
    gather_zkl_kernel<<<Nn, 128>>>(p_tmulv, p_permE, p_startE, bmu, blv, eps,
                                   p_z, p_accp);

    // ---- decoder GCN pass 1 ----
    {
        dim3 g(1, mby);
        tgemm_kernel<<<g, 256>>>(p_z, Wd1, (const float*)0, p_md, Nn, 64, 64, 64, 0,
                                 p_dis, 0);
    }
    gather_dec_kernel<<<Nn / 4, 256>>>(p_md, p_permD, p_startD, p_dis, bd1, p_hd,
                                       (__nv_bfloat16*)0);

    // ---- decoder GCN pass 2 (writes fp32 + bf16 shadow) ----
    {
        dim3 g(1, mby);
        tgemm_kernel<<<g, 256>>>(p_hd, Wd2, (const float*)0, p_md, Nn, 64, 64, 64, 0,
                                 p_dis, 0);
    }
    gather_dec_kernel<<<Nn / 4, 256>>>(p_md, p_permD, p_startD, p_dis, bd2, p_hd2,
                                       p_h16);

    // ---- per-node precompute [h@Wa1 | h@Wa2] -> bf16 ----
    {
        dim3 g(2, mby);
        tgemm_kernel<<<g, 256>>>(p_hd2, Wa, Wa + 64 * 64, (float*)p_A12b, Nn, 64, 64, 128, 0,
                                 (const float*)0, 1);
    }

    // ---- fused edge decoder + loss (1-sync pipelined tf32 mma, bf16 inputs) ----
    {
        int smem = (8192 + 16896 + 128) * 4 + 256 * 4;   // 101888 B
        cudaFuncSetAttribute(edge_loss_kernel, cudaFuncAttributeMaxDynamicSharedMemorySize, smem);
        edge_loss_kernel<<<296, 256, smem>>>(p_h16, p_A12b, Wa, ba, Wb, bb, tau,
                                             pu, pv, nu, nv, p_acc);
    }

    finalize_kernel<<<1, 1>>>(p_acc, p_accp, (float*)d_out, out_size);

    (void)in_sizes; (void)n_in;
}